// round 1
// baseline (speedup 1.0000x reference)
#include <cuda_runtime.h>
#include <cuda_bf16.h>
#include <math.h>

// ---------------- problem dims ----------------
#define BB   2
#define TT   2048
#define DD   1024
#define NHH  16
#define HDD  64
#define FFF  4096
#define NLL  2
#define VV   32000
#define MM   (BB*TT)          // 4096 token rows
#define EPSF 1.1920929e-07f

// ---------------- scratch (no allocations allowed) ----------------
__device__ float g_h  [(size_t)MM*DD];
__device__ float g_n  [(size_t)MM*DD];
__device__ float g_qkv[(size_t)MM*3*DD];
__device__ float g_att[(size_t)MM*DD];
__device__ float g_ff [(size_t)MM*FFF];

// ---------------- f32x2 helpers (FFMA2: 2x fp32 rate on sm_103a) ----------------
__device__ __forceinline__ unsigned long long packf2(float x, float y) {
    unsigned long long r;
    asm("mov.b64 %0, {%1, %2};" : "=l"(r) : "r"(__float_as_uint(x)), "r"(__float_as_uint(y)));
    return r;
}
__device__ __forceinline__ void unpackf2(unsigned long long v, float& x, float& y) {
    unsigned int a, b;
    asm("mov.b64 {%0, %1}, %2;" : "=r"(a), "=r"(b) : "l"(v));
    x = __uint_as_float(a); y = __uint_as_float(b);
}
__device__ __forceinline__ void ffma2(unsigned long long& c, unsigned long long a, unsigned long long b) {
    asm("fma.rn.f32x2 %0, %1, %2, %0;" : "+l"(c) : "l"(a), "l"(b));
}

// ---------------- embedding gather ----------------
__global__ __launch_bounds__(256) void embed_kernel(const int* __restrict__ x,
                                                    const float* __restrict__ emb,
                                                    float* __restrict__ h) {
    int row = blockIdx.x;
    int tok = x[row];
    const float4* src = (const float4*)(emb + (size_t)tok * DD);
    float4* dst = (float4*)(h + (size_t)row * DD);
    dst[threadIdx.x] = src[threadIdx.x];
}

// ---------------- RMSNorm: one block per row, D=1024, 256 threads ----------------
__global__ __launch_bounds__(256) void rmsnorm_kernel(const float* __restrict__ x,
                                                      const float* __restrict__ w,
                                                      float* __restrict__ y) {
    int row = blockIdx.x, t = threadIdx.x;
    const float4* xr = (const float4*)(x + (size_t)row * DD);
    float4 v = xr[t];
    float ss = v.x*v.x + v.y*v.y + v.z*v.z + v.w*v.w;
    #pragma unroll
    for (int o = 16; o > 0; o >>= 1) ss += __shfl_xor_sync(0xffffffffu, ss, o);
    __shared__ float wsum[8];
    if ((t & 31) == 0) wsum[t >> 5] = ss;
    __syncthreads();
    float tot = 0.f;
    #pragma unroll
    for (int i = 0; i < 8; i++) tot += wsum[i];
    float rs = rsqrtf(tot * (1.0f / (float)DD) + EPSF);
    float4 wv = ((const float4*)w)[t];
    float4 o4;
    o4.x = v.x * rs * wv.x; o4.y = v.y * rs * wv.y;
    o4.z = v.z * rs * wv.z; o4.w = v.w * rs * wv.w;
    ((float4*)(y + (size_t)row * DD))[t] = o4;
}

// ---------------- fused-epilogue GEMM:  C[M,N] = epi(A[M,K] @ W[N,K]^T + bias) ----------------
// epi: 0 = none, 1 = +aux (residual), 2 = silu, 3 = *aux (gate multiply)
// Tiles: 64(M) x 128(N) x 16(K). 256 threads, 4x4 micro-tile of f32x2 pairs (FFMA2).
#define EPI_NONE 0
#define EPI_RES  1
#define EPI_SILU 2
#define EPI_MUL  3

__global__ __launch_bounds__(256) void gemm_kernel(const float* __restrict__ A,
                                                   const float* __restrict__ W,
                                                   const float* __restrict__ bias,
                                                   const float* aux,
                                                   float* C,
                                                   int M, int N, int K, int epi) {
    __shared__ float As[16][68];   // [k][m]  (pitch 68: float4-aligned, conflict-mitigated)
    __shared__ float Ws[16][132];  // [k][n]
    const int t = threadIdx.x;
    const int bm = blockIdx.y, bn = blockIdx.x;
    const int tx = t & 15, ty = t >> 4;

    const float* Ablk = A + (size_t)bm * 64 * K;
    const float* Wblk = W + (size_t)bn * 128 * K;

    unsigned long long acc[4][4];
    #pragma unroll
    for (int i = 0; i < 4; i++)
        #pragma unroll
        for (int j = 0; j < 4; j++) acc[i][j] = 0ull;

    const int arow = t >> 2, akq = t & 3;

    for (int kt = 0; kt < K; kt += 16) {
        // load A tile: 64 rows x 16 k  (one float4 per thread)
        float4 av = *(const float4*)(Ablk + (size_t)arow * K + kt + akq * 4);
        As[akq*4+0][arow] = av.x; As[akq*4+1][arow] = av.y;
        As[akq*4+2][arow] = av.z; As[akq*4+3][arow] = av.w;
        // load W tile: 128 rows x 16 k  (two float4 per thread)
        #pragma unroll
        for (int r = 0; r < 2; r++) {
            int idx = t + 256 * r;
            int wrow = idx >> 2, wkq = idx & 3;
            float4 wv = *(const float4*)(Wblk + (size_t)wrow * K + kt + wkq * 4);
            Ws[wkq*4+0][wrow] = wv.x; Ws[wkq*4+1][wrow] = wv.y;
            Ws[wkq*4+2][wrow] = wv.z; Ws[wkq*4+3][wrow] = wv.w;
        }
        __syncthreads();
        #pragma unroll
        for (int k = 0; k < 16; k++) {
            float4 a  = *(const float4*)(&As[k][ty * 4]);
            float4 w0 = *(const float4*)(&Ws[k][tx * 8]);
            float4 w1 = *(const float4*)(&Ws[k][tx * 8 + 4]);
            unsigned long long a2[4], wb[4];
            a2[0] = packf2(a.x, a.x); a2[1] = packf2(a.y, a.y);
            a2[2] = packf2(a.z, a.z); a2[3] = packf2(a.w, a.w);
            wb[0] = packf2(w0.x, w0.y); wb[1] = packf2(w0.z, w0.w);
            wb[2] = packf2(w1.x, w1.y); wb[3] = packf2(w1.z, w1.w);
            #pragma unroll
            for (int i = 0; i < 4; i++)
                #pragma unroll
                for (int j = 0; j < 4; j++)
                    ffma2(acc[i][j], a2[i], wb[j]);
        }
        __syncthreads();
    }

    // epilogue
    #pragma unroll
    for (int i = 0; i < 4; i++) {
        size_t m = (size_t)bm * 64 + ty * 4 + i;
        float* crow = C + m * (size_t)N;
        const float* auxrow = (aux != nullptr) ? (aux + m * (size_t)N) : nullptr;
        #pragma unroll
        for (int j = 0; j < 4; j++) {
            int n = bn * 128 + tx * 8 + j * 2;
            float x, y;
            unpackf2(acc[i][j], x, y);
            if (bias) { x += bias[n]; y += bias[n + 1]; }
            if (epi == EPI_RES)      { x += auxrow[n]; y += auxrow[n + 1]; }
            else if (epi == EPI_SILU){ x = x / (1.0f + expf(-x)); y = y / (1.0f + expf(-y)); }
            else if (epi == EPI_MUL) { x *= auxrow[n]; y *= auxrow[n + 1]; }
            crow[n] = x; crow[n + 1] = y;
        }
    }
}

// ---------------- flash attention (fp32, causal), HD=64 ----------------
// grid: (T/64, NH, B), 256 threads. Online softmax, q-tile 64 x kv-tile 64.
#define APITCH 68
#define ATTN_SMEM ((4 * 64 * APITCH + 3 * 64) * (int)sizeof(float))

__global__ __launch_bounds__(256) void attn_kernel(const float* __restrict__ qkv,
                                                   float* __restrict__ o) {
    extern __shared__ float sm[];
    float* Qs = sm;
    float* Ks = Qs + 64 * APITCH;
    float* Vs = Ks + 64 * APITCH;
    float* Ss = Vs + 64 * APITCH;
    float* rowm = Ss + 64 * APITCH;
    float* rowl = rowm + 64;
    float* rowsc = rowl + 64;

    const int t = threadIdx.x;
    const int qt = blockIdx.x, h = blockIdx.y, b = blockIdx.z;
    const int q0 = qt * 64;
    const int tx = t & 15, ty = t >> 4;
    const float NEG = -1e30f;

    // load Q tile [64 x 64]
    for (int i = t; i < 64 * 16; i += 256) {
        int row = i >> 4, c4 = i & 15;
        float4 v = *(const float4*)(qkv + ((size_t)(b * TT + q0 + row)) * (3 * DD) + h * HDD + c4 * 4);
        *(float4*)(&Qs[row * APITCH + c4 * 4]) = v;
    }
    if (t < 64) { rowm[t] = NEG; rowl[t] = 0.f; }

    float o_acc[4][4];
    #pragma unroll
    for (int i = 0; i < 4; i++)
        #pragma unroll
        for (int j = 0; j < 4; j++) o_acc[i][j] = 0.f;

    for (int jt = 0; jt <= qt; jt++) {
        const int k0 = jt * 64;
        // load K, V tiles
        for (int i = t; i < 64 * 16; i += 256) {
            int row = i >> 4, c4 = i & 15;
            size_t base = ((size_t)(b * TT + k0 + row)) * (3 * DD) + h * HDD + c4 * 4;
            *(float4*)(&Ks[row * APITCH + c4 * 4]) = *(const float4*)(qkv + base + DD);
            *(float4*)(&Vs[row * APITCH + c4 * 4]) = *(const float4*)(qkv + base + 2 * DD);
        }
        __syncthreads();

        // S = Q K^T * 1/8  (each thread: 4 q-rows x 4 k-cols)
        float s[4][4];
        #pragma unroll
        for (int i = 0; i < 4; i++)
            #pragma unroll
            for (int j = 0; j < 4; j++) s[i][j] = 0.f;
        #pragma unroll 4
        for (int d4 = 0; d4 < 16; d4++) {
            float4 q4[4], k4[4];
            #pragma unroll
            for (int i = 0; i < 4; i++) q4[i] = *(const float4*)(&Qs[(ty * 4 + i) * APITCH + d4 * 4]);
            #pragma unroll
            for (int j = 0; j < 4; j++) k4[j] = *(const float4*)(&Ks[(tx * 4 + j) * APITCH + d4 * 4]);
            #pragma unroll
            for (int i = 0; i < 4; i++)
                #pragma unroll
                for (int j = 0; j < 4; j++)
                    s[i][j] += q4[i].x * k4[j].x + q4[i].y * k4[j].y
                             + q4[i].z * k4[j].z + q4[i].w * k4[j].w;
        }
        const bool diag = (jt == qt);
        #pragma unroll
        for (int i = 0; i < 4; i++)
            #pragma unroll
            for (int j = 0; j < 4; j++) {
                float v = s[i][j] * 0.125f;
                if (diag && (k0 + tx * 4 + j > q0 + ty * 4 + i)) v = NEG;
                Ss[(ty * 4 + i) * APITCH + (tx * 4 + j)] = v;
            }
        __syncthreads();

        // online softmax: one thread per q-row
        if (t < 64) {
            int r = t;
            float mold = rowm[r];
            float tmax = NEG;
            for (int j = 0; j < 64; j++) tmax = fmaxf(tmax, Ss[r * APITCH + j]);
            float mnew = fmaxf(mold, tmax);
            float corr = __expf(mold - mnew);
            float sum = 0.f;
            for (int j = 0; j < 64; j++) {
                float p = __expf(Ss[r * APITCH + j] - mnew);
                Ss[r * APITCH + j] = p;
                sum += p;
            }
            rowl[r] = rowl[r] * corr + sum;
            rowm[r] = mnew;
            rowsc[r] = corr;
        }
        __syncthreads();

        // O = O*corr + P V  (each thread: 4 q-rows x 4 d-cols)
        #pragma unroll
        for (int i = 0; i < 4; i++) {
            float c = rowsc[ty * 4 + i];
            #pragma unroll
            for (int j = 0; j < 4; j++) o_acc[i][j] *= c;
        }
        for (int k = 0; k < 64; k++) {
            float4 v4 = *(const float4*)(&Vs[k * APITCH + tx * 4]);
            #pragma unroll
            for (int i = 0; i < 4; i++) {
                float p = Ss[(ty * 4 + i) * APITCH + k];
                o_acc[i][0] += p * v4.x; o_acc[i][1] += p * v4.y;
                o_acc[i][2] += p * v4.z; o_acc[i][3] += p * v4.w;
            }
        }
        __syncthreads();
    }

    // write O into [B,T,D] layout (head h occupies cols h*64..)
    #pragma unroll
    for (int i = 0; i < 4; i++) {
        float invl = 1.0f / rowl[ty * 4 + i];
        size_t base = ((size_t)(b * TT + q0 + ty * 4 + i)) * DD + h * HDD + tx * 4;
        #pragma unroll
        for (int j = 0; j < 4; j++) o[base + j] = o_acc[i][j] * invl;
    }
}

// ---------------- driver ----------------
extern "C" void kernel_launch(void* const* d_in, const int* in_sizes, int n_in,
                              void* d_out, int out_size) {
    const int*   x      = (const int*)  d_in[0];
    const float* emb_w  = (const float*)d_in[1];
    const float* n1_w   = (const float*)d_in[2];
    const float* n2_w   = (const float*)d_in[3];
    const float* qkv_w  = (const float*)d_in[4];
    const float* qkv_b  = (const float*)d_in[5];
    const float* o_w    = (const float*)d_in[6];
    const float* o_b    = (const float*)d_in[7];
    const float* gw     = (const float*)d_in[8];
    const float* gb     = (const float*)d_in[9];
    const float* uw     = (const float*)d_in[10];
    const float* ub     = (const float*)d_in[11];
    const float* dnw    = (const float*)d_in[12];
    const float* dnb    = (const float*)d_in[13];
    const float* norm_w = (const float*)d_in[14];
    const float* head_w = (const float*)d_in[15];
    float* out = (float*)d_out;

    float *h_, *n_, *qkv_, *att_, *ff_;
    cudaGetSymbolAddress((void**)&h_,   g_h);
    cudaGetSymbolAddress((void**)&n_,   g_n);
    cudaGetSymbolAddress((void**)&qkv_, g_qkv);
    cudaGetSymbolAddress((void**)&att_, g_att);
    cudaGetSymbolAddress((void**)&ff_,  g_ff);

    cudaFuncSetAttribute(attn_kernel, cudaFuncAttributeMaxDynamicSharedMemorySize, ATTN_SMEM);

    embed_kernel<<<MM, 256>>>(x, emb_w, h_);

    for (int l = 0; l < NLL; l++) {
        rmsnorm_kernel<<<MM, 256>>>(h_, n1_w + (size_t)l * DD, n_);

        gemm_kernel<<<dim3((3 * DD) / 128, MM / 64), 256>>>(
            n_, qkv_w + (size_t)l * 3 * DD * DD, qkv_b + (size_t)l * 3 * DD,
            nullptr, qkv_, MM, 3 * DD, DD, EPI_NONE);

        attn_kernel<<<dim3(TT / 64, NHH, BB), 256, ATTN_SMEM>>>(qkv_, att_);

        gemm_kernel<<<dim3(DD / 128, MM / 64), 256>>>(
            att_, o_w + (size_t)l * DD * DD, o_b + (size_t)l * DD,
            h_, h_, MM, DD, DD, EPI_RES);

        rmsnorm_kernel<<<MM, 256>>>(h_, n2_w + (size_t)l * DD, n_);

        gemm_kernel<<<dim3(FFF / 128, MM / 64), 256>>>(
            n_, gw + (size_t)l * FFF * DD, gb + (size_t)l * FFF,
            nullptr, ff_, MM, FFF, DD, EPI_SILU);

        gemm_kernel<<<dim3(FFF / 128, MM / 64), 256>>>(
            n_, uw + (size_t)l * FFF * DD, ub + (size_t)l * FFF,
            ff_, ff_, MM, FFF, DD, EPI_MUL);

        gemm_kernel<<<dim3(DD / 128, MM / 64), 256>>>(
            ff_, dnw + (size_t)l * DD * FFF, dnb + (size_t)l * DD,
            h_, h_, MM, DD, FFF, EPI_RES);
    }

    rmsnorm_kernel<<<MM, 256>>>(h_, norm_w, n_);

    gemm_kernel<<<dim3(VV / 128, MM / 64), 256>>>(
        n_, head_w, nullptr, nullptr, out, MM, VV, DD, EPI_NONE);
}

// round 3
// speedup vs baseline: 3.2410x; 3.2410x over previous
#include <cuda_runtime.h>
#include <cuda_bf16.h>
#include <math.h>
#include <stdint.h>

// ---------------- problem dims ----------------
#define BB   2
#define TT   2048
#define DD   1024
#define NHH  16
#define HDD  64
#define FFF  4096
#define NLL  2
#define VV   32000
#define MR   (BB*TT)          // 4096 token rows
#define EPSF 1.1920929e-07f

// ---------------- fp32 scratch ----------------
__device__ float g_h  [(size_t)MR*DD];
__device__ float g_qkv[(size_t)MR*3*DD];
__device__ float g_ffs[(size_t)MR*FFF];

// ---------------- bf16 split scratch (hi/lo) ----------------
__device__ __nv_bfloat16 g_wqkv_h[(size_t)NLL*3*DD*DD], g_wqkv_l[(size_t)NLL*3*DD*DD];
__device__ __nv_bfloat16 g_wo_h  [(size_t)NLL*DD*DD],   g_wo_l  [(size_t)NLL*DD*DD];
__device__ __nv_bfloat16 g_wg_h  [(size_t)NLL*FFF*DD],  g_wg_l  [(size_t)NLL*FFF*DD];
__device__ __nv_bfloat16 g_wu_h  [(size_t)NLL*FFF*DD],  g_wu_l  [(size_t)NLL*FFF*DD];
__device__ __nv_bfloat16 g_wdn_h [(size_t)NLL*DD*FFF],  g_wdn_l [(size_t)NLL*DD*FFF];
__device__ __nv_bfloat16 g_whd_h [(size_t)VV*DD],       g_whd_l [(size_t)VV*DD];
__device__ __nv_bfloat16 g_n_h   [(size_t)MR*DD],       g_n_l   [(size_t)MR*DD];
__device__ __nv_bfloat16 g_at_h  [(size_t)MR*DD],       g_at_l  [(size_t)MR*DD];
__device__ __nv_bfloat16 g_ff_h  [(size_t)MR*FFF],      g_ff_l  [(size_t)MR*FFF];

// ================= helpers =================
__device__ __forceinline__ uint32_t smem_u32(const void* p) {
    uint32_t a;
    asm("{ .reg .u64 t; cvta.to.shared.u64 t, %1; cvt.u32.u64 %0, t; }" : "=r"(a) : "l"(p));
    return a;
}

// ================= weight split: x -> hi(bf16) + lo(bf16) =================
__global__ __launch_bounds__(256) void split4_kernel(const float4* __restrict__ src,
                                                     __nv_bfloat16* __restrict__ hi,
                                                     __nv_bfloat16* __restrict__ lo,
                                                     size_t n4) {
    size_t stride = (size_t)gridDim.x * blockDim.x;
    for (size_t i = (size_t)blockIdx.x * blockDim.x + threadIdx.x; i < n4; i += stride) {
        float4 v = src[i];
        __nv_bfloat16 hx = __float2bfloat16(v.x), hy = __float2bfloat16(v.y);
        __nv_bfloat16 hz = __float2bfloat16(v.z), hw = __float2bfloat16(v.w);
        ((ushort4*)hi)[i] = make_ushort4(__bfloat16_as_ushort(hx), __bfloat16_as_ushort(hy),
                                         __bfloat16_as_ushort(hz), __bfloat16_as_ushort(hw));
        __nv_bfloat16 lx = __float2bfloat16(v.x - __bfloat162float(hx));
        __nv_bfloat16 ly = __float2bfloat16(v.y - __bfloat162float(hy));
        __nv_bfloat16 lz = __float2bfloat16(v.z - __bfloat162float(hz));
        __nv_bfloat16 lw = __float2bfloat16(v.w - __bfloat162float(hw));
        ((ushort4*)lo)[i] = make_ushort4(__bfloat16_as_ushort(lx), __bfloat16_as_ushort(ly),
                                         __bfloat16_as_ushort(lz), __bfloat16_as_ushort(lw));
    }
}

// ================= embedding =================
__global__ __launch_bounds__(256) void embed_kernel(const int* __restrict__ x,
                                                    const float* __restrict__ emb,
                                                    float* __restrict__ h) {
    int row = blockIdx.x;
    int tok = x[row];
    ((float4*)(h + (size_t)row * DD))[threadIdx.x] =
        ((const float4*)(emb + (size_t)tok * DD))[threadIdx.x];
}

// ================= RMSNorm -> bf16 hi/lo =================
__global__ __launch_bounds__(256) void rmsnorm_split(const float* __restrict__ x,
                                                     const float* __restrict__ w,
                                                     __nv_bfloat16* __restrict__ hi,
                                                     __nv_bfloat16* __restrict__ lo) {
    int row = blockIdx.x, t = threadIdx.x;
    float4 v = ((const float4*)(x + (size_t)row * DD))[t];
    float ss = v.x*v.x + v.y*v.y + v.z*v.z + v.w*v.w;
    #pragma unroll
    for (int o = 16; o > 0; o >>= 1) ss += __shfl_xor_sync(0xffffffffu, ss, o);
    __shared__ float wsum[8];
    if ((t & 31) == 0) wsum[t >> 5] = ss;
    __syncthreads();
    float tot = 0.f;
    #pragma unroll
    for (int i = 0; i < 8; i++) tot += wsum[i];
    float rs = rsqrtf(tot * (1.0f / (float)DD) + EPSF);
    float4 wv = ((const float4*)w)[t];
    float ox = v.x * rs * wv.x, oy = v.y * rs * wv.y;
    float oz = v.z * rs * wv.z, ow = v.w * rs * wv.w;
    __nv_bfloat16 hx = __float2bfloat16(ox), hy = __float2bfloat16(oy);
    __nv_bfloat16 hz = __float2bfloat16(oz), hw = __float2bfloat16(ow);
    ((ushort4*)(hi + (size_t)row * DD))[t] =
        make_ushort4(__bfloat16_as_ushort(hx), __bfloat16_as_ushort(hy),
                     __bfloat16_as_ushort(hz), __bfloat16_as_ushort(hw));
    __nv_bfloat16 lx = __float2bfloat16(ox - __bfloat162float(hx));
    __nv_bfloat16 ly = __float2bfloat16(oy - __bfloat162float(hy));
    __nv_bfloat16 lz = __float2bfloat16(oz - __bfloat162float(hz));
    __nv_bfloat16 lw = __float2bfloat16(ow - __bfloat162float(hw));
    ((ushort4*)(lo + (size_t)row * DD))[t] =
        make_ushort4(__bfloat16_as_ushort(lx), __bfloat16_as_ushort(ly),
                     __bfloat16_as_ushort(lz), __bfloat16_as_ushort(lw));
}

// ================= HMMA GEMM (mma.sync bf16, register accumulators) =================
// C[M=4096, N] = epi( (Ahi+Alo)[M,K] @ (Whi+Wlo)[N,K]^T + bias )
// 3 accumulation passes: (Ahi,Whi), (Alo,Whi), (Ahi,Wlo).
// CTA tile 128x128, K-chunk 32, cp.async double buffer, 8 warps (2m x 4n),
// warp tile 64x32, mma.m16n8k16. Swizzle: 16B chunk c -> c ^ ((row>>1)&3).
// epi: 0 fp32 out; 1 fp32 out + aux; 2 silu fp32 out; 3 (acc+bias)*aux -> bf16 hi/lo.

__global__ __launch_bounds__(256) void gemm_mma(
    const __nv_bfloat16* __restrict__ ahi, const __nv_bfloat16* __restrict__ alo,
    const __nv_bfloat16* __restrict__ whi, const __nv_bfloat16* __restrict__ wlo,
    const float* __restrict__ bias, const float* __restrict__ aux,
    float* outf, __nv_bfloat16* ohi, __nv_bfloat16* olo,
    int N, int K, int epi)
{
    __shared__ __align__(1024) char smem[32768];   // 2 buffers x (A 8KB + B 8KB)
    const int tid = threadIdx.x;
    const int wid = tid >> 5, lane = tid & 31;
    const int mt = blockIdx.y, nt = blockIdx.x;
    const int warp_m = wid >> 2, warp_n = wid & 3;
    const uint32_t sbase = smem_u32(smem);

    float acc[4][4][4];
    #pragma unroll
    for (int f = 0; f < 4; f++)
        #pragma unroll
        for (int g = 0; g < 4; g++)
            #pragma unroll
            for (int e = 0; e < 4; e++) acc[f][g][e] = 0.f;

    const int nk = K >> 5;
    const int nc = 3 * nk;

    auto prefetch = [&](int c, int b) {
        const int pass = c / nk, kc = c - pass * nk;
        const __nv_bfloat16* asrc = (pass == 1) ? alo : ahi;
        const __nv_bfloat16* wsrc = (pass == 2) ? wlo : whi;
        const size_t koff = (size_t)kc << 5;
        const uint32_t bufo = sbase + ((uint32_t)b << 14);
        #pragma unroll
        for (int rep = 0; rep < 4; ++rep) {
            const int idx = tid + 256 * rep;       // 0..1023
            const int r  = (idx >> 2) & 127;
            const int c4 = idx & 3;
            const bool isA = idx < 512;
            const __nv_bfloat16* g = isA
                ? asrc + ((size_t)(mt * 128 + r)) * K + koff + c4 * 8
                : wsrc + ((size_t)(nt * 128 + r)) * K + koff + c4 * 8;
            const uint32_t dst = bufo + (isA ? 0u : 8192u)
                               + (uint32_t)(r * 64 + ((c4 ^ ((r >> 1) & 3)) << 4));
            asm volatile("cp.async.cg.shared.global [%0], [%1], 16;" :: "r"(dst), "l"(g));
        }
        asm volatile("cp.async.commit_group;" ::: "memory");
    };

    prefetch(0, 0);
    for (int c = 0; c < nc; ++c) {
        if (c + 1 < nc) {
            prefetch(c + 1, (c + 1) & 1);
            asm volatile("cp.async.wait_group 1;" ::: "memory");
        } else {
            asm volatile("cp.async.wait_group 0;" ::: "memory");
        }
        __syncthreads();

        const uint32_t ab = sbase + ((uint32_t)(c & 1) << 14);
        const uint32_t bb = ab + 8192u;
        #pragma unroll
        for (int s = 0; s < 2; ++s) {
            uint32_t a[4][4], bf[4][2];
            #pragma unroll
            for (int f = 0; f < 4; ++f) {
                const int row = warp_m * 64 + f * 16 + (lane & 15);
                const int ch  = s * 2 + (lane >> 4);
                const uint32_t addr = ab + row * 64 + ((ch ^ ((row >> 1) & 3)) << 4);
                asm volatile("ldmatrix.sync.aligned.m8n8.x4.shared.b16 {%0,%1,%2,%3}, [%4];"
                    : "=r"(a[f][0]), "=r"(a[f][1]), "=r"(a[f][2]), "=r"(a[f][3]) : "r"(addr));
            }
            #pragma unroll
            for (int g = 0; g < 4; ++g) {
                const int row = warp_n * 32 + g * 8 + (lane & 7);
                const int ch  = s * 2 + ((lane >> 3) & 1);
                const uint32_t addr = bb + row * 64 + ((ch ^ ((row >> 1) & 3)) << 4);
                asm volatile("ldmatrix.sync.aligned.m8n8.x2.shared.b16 {%0,%1}, [%2];"
                    : "=r"(bf[g][0]), "=r"(bf[g][1]) : "r"(addr));
            }
            #pragma unroll
            for (int f = 0; f < 4; ++f)
                #pragma unroll
                for (int g = 0; g < 4; ++g)
                    asm volatile("mma.sync.aligned.m16n8k16.row.col.f32.bf16.bf16.f32 "
                        "{%0,%1,%2,%3}, {%4,%5,%6,%7}, {%8,%9}, {%0,%1,%2,%3};"
                        : "+f"(acc[f][g][0]), "+f"(acc[f][g][1]),
                          "+f"(acc[f][g][2]), "+f"(acc[f][g][3])
                        : "r"(a[f][0]), "r"(a[f][1]), "r"(a[f][2]), "r"(a[f][3]),
                          "r"(bf[g][0]), "r"(bf[g][1]));
        }
        __syncthreads();
    }

    // ---- epilogue ----
    const int r_in = lane >> 2, c_in = (lane & 3) * 2;
    #pragma unroll
    for (int f = 0; f < 4; ++f) {
        #pragma unroll
        for (int rr = 0; rr < 2; ++rr) {
            const size_t m = (size_t)mt * 128 + warp_m * 64 + f * 16 + rr * 8 + r_in;
            float* frow = outf ? outf + m * (size_t)N : (float*)0;
            const float* arow = aux ? aux + m * (size_t)N : (const float*)0;
            #pragma unroll
            for (int g = 0; g < 4; ++g) {
                const int n = nt * 128 + warp_n * 32 + g * 8 + c_in;
                float x = acc[f][g][rr * 2 + 0];
                float y = acc[f][g][rr * 2 + 1];
                if (bias) { x += bias[n]; y += bias[n + 1]; }
                if (epi == 1) {
                    x += arow[n]; y += arow[n + 1];
                    frow[n] = x; frow[n + 1] = y;
                } else if (epi == 2) {
                    x = x / (1.f + expf(-x)); y = y / (1.f + expf(-y));
                    frow[n] = x; frow[n + 1] = y;
                } else if (epi == 3) {
                    x *= arow[n]; y *= arow[n + 1];
                    __nv_bfloat16 hx = __float2bfloat16(x), hy = __float2bfloat16(y);
                    *(ushort2*)(ohi + m * (size_t)N + n) =
                        make_ushort2(__bfloat16_as_ushort(hx), __bfloat16_as_ushort(hy));
                    __nv_bfloat16 lx = __float2bfloat16(x - __bfloat162float(hx));
                    __nv_bfloat16 ly = __float2bfloat16(y - __bfloat162float(hy));
                    *(ushort2*)(olo + m * (size_t)N + n) =
                        make_ushort2(__bfloat16_as_ushort(lx), __bfloat16_as_ushort(ly));
                } else {
                    frow[n] = x; frow[n + 1] = y;
                }
            }
        }
    }
}

// ================= flash attention (fp32, causal), HD=64, out -> bf16 hi/lo ======
#define APITCH 68
#define ATTN_SMEM ((4 * 64 * APITCH + 3 * 64) * (int)sizeof(float))

__global__ __launch_bounds__(256) void attn_kernel(const float* __restrict__ qkv,
                                                   __nv_bfloat16* __restrict__ ohi,
                                                   __nv_bfloat16* __restrict__ olo) {
    extern __shared__ float sm[];
    float* Qs = sm;
    float* Ks = Qs + 64 * APITCH;
    float* Vs = Ks + 64 * APITCH;
    float* Ss = Vs + 64 * APITCH;
    float* rowm = Ss + 64 * APITCH;
    float* rowl = rowm + 64;
    float* rowsc = rowl + 64;

    const int t = threadIdx.x;
    const int qt = blockIdx.x, h = blockIdx.y, b = blockIdx.z;
    const int q0 = qt * 64;
    const int tx = t & 15, ty = t >> 4;
    const float NEG = -1e30f;

    for (int i = t; i < 64 * 16; i += 256) {
        int row = i >> 4, c4 = i & 15;
        *(float4*)(&Qs[row * APITCH + c4 * 4]) =
            *(const float4*)(qkv + ((size_t)(b * TT + q0 + row)) * (3 * DD) + h * HDD + c4 * 4);
    }
    if (t < 64) { rowm[t] = NEG; rowl[t] = 0.f; }

    float o_acc[4][4];
    #pragma unroll
    for (int i = 0; i < 4; i++)
        #pragma unroll
        for (int j = 0; j < 4; j++) o_acc[i][j] = 0.f;

    for (int jt = 0; jt <= qt; jt++) {
        const int k0 = jt * 64;
        for (int i = t; i < 64 * 16; i += 256) {
            int row = i >> 4, c4 = i & 15;
            size_t base = ((size_t)(b * TT + k0 + row)) * (3 * DD) + h * HDD + c4 * 4;
            *(float4*)(&Ks[row * APITCH + c4 * 4]) = *(const float4*)(qkv + base + DD);
            *(float4*)(&Vs[row * APITCH + c4 * 4]) = *(const float4*)(qkv + base + 2 * DD);
        }
        __syncthreads();

        float s[4][4];
        #pragma unroll
        for (int i = 0; i < 4; i++)
            #pragma unroll
            for (int j = 0; j < 4; j++) s[i][j] = 0.f;
        #pragma unroll 4
        for (int d4 = 0; d4 < 16; d4++) {
            float4 q4[4], k4[4];
            #pragma unroll
            for (int i = 0; i < 4; i++) q4[i] = *(const float4*)(&Qs[(ty * 4 + i) * APITCH + d4 * 4]);
            #pragma unroll
            for (int j = 0; j < 4; j++) k4[j] = *(const float4*)(&Ks[(tx * 4 + j) * APITCH + d4 * 4]);
            #pragma unroll
            for (int i = 0; i < 4; i++)
                #pragma unroll
                for (int j = 0; j < 4; j++)
                    s[i][j] += q4[i].x * k4[j].x + q4[i].y * k4[j].y
                             + q4[i].z * k4[j].z + q4[i].w * k4[j].w;
        }
        const bool diag = (jt == qt);
        #pragma unroll
        for (int i = 0; i < 4; i++)
            #pragma unroll
            for (int j = 0; j < 4; j++) {
                float v = s[i][j] * 0.125f;
                if (diag && (k0 + tx * 4 + j > q0 + ty * 4 + i)) v = NEG;
                Ss[(ty * 4 + i) * APITCH + (tx * 4 + j)] = v;
            }
        __syncthreads();

        if (t < 64) {
            int r = t;
            float mold = rowm[r];
            float tmax = NEG;
            for (int j = 0; j < 64; j++) tmax = fmaxf(tmax, Ss[r * APITCH + j]);
            float mnew = fmaxf(mold, tmax);
            float corr = __expf(mold - mnew);
            float sum = 0.f;
            for (int j = 0; j < 64; j++) {
                float p = __expf(Ss[r * APITCH + j] - mnew);
                Ss[r * APITCH + j] = p;
                sum += p;
            }
            rowl[r] = rowl[r] * corr + sum;
            rowm[r] = mnew;
            rowsc[r] = corr;
        }
        __syncthreads();

        #pragma unroll
        for (int i = 0; i < 4; i++) {
            float c = rowsc[ty * 4 + i];
            #pragma unroll
            for (int j = 0; j < 4; j++) o_acc[i][j] *= c;
        }
        for (int k = 0; k < 64; k++) {
            float4 v4 = *(const float4*)(&Vs[k * APITCH + tx * 4]);
            #pragma unroll
            for (int i = 0; i < 4; i++) {
                float p = Ss[(ty * 4 + i) * APITCH + k];
                o_acc[i][0] += p * v4.x; o_acc[i][1] += p * v4.y;
                o_acc[i][2] += p * v4.z; o_acc[i][3] += p * v4.w;
            }
        }
        __syncthreads();
    }

    #pragma unroll
    for (int i = 0; i < 4; i++) {
        float invl = 1.0f / rowl[ty * 4 + i];
        size_t idx = ((size_t)(b * TT + q0 + ty * 4 + i)) * DD + h * HDD + tx * 4;
        float v0 = o_acc[i][0] * invl, v1 = o_acc[i][1] * invl;
        float v2 = o_acc[i][2] * invl, v3 = o_acc[i][3] * invl;
        __nv_bfloat16 h0 = __float2bfloat16(v0), h1 = __float2bfloat16(v1);
        __nv_bfloat16 h2 = __float2bfloat16(v2), h3 = __float2bfloat16(v3);
        *(ushort4*)(ohi + idx) = make_ushort4(__bfloat16_as_ushort(h0), __bfloat16_as_ushort(h1),
                                              __bfloat16_as_ushort(h2), __bfloat16_as_ushort(h3));
        __nv_bfloat16 l0 = __float2bfloat16(v0 - __bfloat162float(h0));
        __nv_bfloat16 l1 = __float2bfloat16(v1 - __bfloat162float(h1));
        __nv_bfloat16 l2 = __float2bfloat16(v2 - __bfloat162float(h2));
        __nv_bfloat16 l3 = __float2bfloat16(v3 - __bfloat162float(h3));
        *(ushort4*)(olo + idx) = make_ushort4(__bfloat16_as_ushort(l0), __bfloat16_as_ushort(l1),
                                              __bfloat16_as_ushort(l2), __bfloat16_as_ushort(l3));
    }
}

// ================= driver =================
extern "C" void kernel_launch(void* const* d_in, const int* in_sizes, int n_in,
                              void* d_out, int out_size) {
    const int*   x      = (const int*)  d_in[0];
    const float* emb_w  = (const float*)d_in[1];
    const float* n1_w   = (const float*)d_in[2];
    const float* n2_w   = (const float*)d_in[3];
    const float* qkv_w  = (const float*)d_in[4];
    const float* qkv_b  = (const float*)d_in[5];
    const float* o_w    = (const float*)d_in[6];
    const float* o_b    = (const float*)d_in[7];
    const float* gw     = (const float*)d_in[8];
    const float* gb     = (const float*)d_in[9];
    const float* uw     = (const float*)d_in[10];
    const float* ub     = (const float*)d_in[11];
    const float* dnw    = (const float*)d_in[12];
    const float* dnb    = (const float*)d_in[13];
    const float* norm_w = (const float*)d_in[14];
    const float* head_w = (const float*)d_in[15];
    float* out = (float*)d_out;

    float *h_, *qkv_, *ffs_;
    __nv_bfloat16 *wqh, *wql, *woh, *wol, *wgh, *wgl, *wuh, *wul, *wdh, *wdl, *whh, *whl;
    __nv_bfloat16 *nh, *nl, *ath, *atl, *ffh, *ffl;
    cudaGetSymbolAddress((void**)&h_,   g_h);
    cudaGetSymbolAddress((void**)&qkv_, g_qkv);
    cudaGetSymbolAddress((void**)&ffs_, g_ffs);
    cudaGetSymbolAddress((void**)&wqh, g_wqkv_h); cudaGetSymbolAddress((void**)&wql, g_wqkv_l);
    cudaGetSymbolAddress((void**)&woh, g_wo_h);   cudaGetSymbolAddress((void**)&wol, g_wo_l);
    cudaGetSymbolAddress((void**)&wgh, g_wg_h);   cudaGetSymbolAddress((void**)&wgl, g_wg_l);
    cudaGetSymbolAddress((void**)&wuh, g_wu_h);   cudaGetSymbolAddress((void**)&wul, g_wu_l);
    cudaGetSymbolAddress((void**)&wdh, g_wdn_h);  cudaGetSymbolAddress((void**)&wdl, g_wdn_l);
    cudaGetSymbolAddress((void**)&whh, g_whd_h);  cudaGetSymbolAddress((void**)&whl, g_whd_l);
    cudaGetSymbolAddress((void**)&nh,  g_n_h);    cudaGetSymbolAddress((void**)&nl,  g_n_l);
    cudaGetSymbolAddress((void**)&ath, g_at_h);   cudaGetSymbolAddress((void**)&atl, g_at_l);
    cudaGetSymbolAddress((void**)&ffh, g_ff_h);   cudaGetSymbolAddress((void**)&ffl, g_ff_l);

    cudaFuncSetAttribute(attn_kernel, cudaFuncAttributeMaxDynamicSharedMemorySize, ATTN_SMEM);

    // weight splits (inside the graph each replay; ~0.1 ms total)
    split4_kernel<<<2048, 256>>>((const float4*)qkv_w,  wqh, wql, (size_t)NLL*3*DD*DD/4);
    split4_kernel<<<2048, 256>>>((const float4*)o_w,    woh, wol, (size_t)NLL*DD*DD/4);
    split4_kernel<<<2048, 256>>>((const float4*)gw,     wgh, wgl, (size_t)NLL*FFF*DD/4);
    split4_kernel<<<2048, 256>>>((const float4*)uw,     wuh, wul, (size_t)NLL*FFF*DD/4);
    split4_kernel<<<2048, 256>>>((const float4*)dnw,    wdh, wdl, (size_t)NLL*DD*FFF/4);
    split4_kernel<<<2048, 256>>>((const float4*)head_w, whh, whl, (size_t)VV*DD/4);

    embed_kernel<<<MR, 256>>>(x, emb_w, h_);

    for (int l = 0; l < NLL; l++) {
        const size_t oq = (size_t)l * 3 * DD * DD, oo = (size_t)l * DD * DD;
        const size_t of = (size_t)l * FFF * DD;

        rmsnorm_split<<<MR, 256>>>(h_, n1_w + (size_t)l * DD, nh, nl);

        gemm_mma<<<dim3(3 * DD / 128, MR / 128), 256>>>(
            nh, nl, wqh + oq, wql + oq, qkv_b + (size_t)l * 3 * DD,
            nullptr, qkv_, nullptr, nullptr, 3 * DD, DD, 0);

        attn_kernel<<<dim3(TT / 64, NHH, BB), 256, ATTN_SMEM>>>(qkv_, ath, atl);

        gemm_mma<<<dim3(DD / 128, MR / 128), 256>>>(
            ath, atl, woh + oo, wol + oo, o_b + (size_t)l * DD,
            h_, h_, nullptr, nullptr, DD, DD, 1);

        rmsnorm_split<<<MR, 256>>>(h_, n2_w + (size_t)l * DD, nh, nl);

        gemm_mma<<<dim3(FFF / 128, MR / 128), 256>>>(
            nh, nl, wgh + of, wgl + of, gb + (size_t)l * FFF,
            nullptr, ffs_, nullptr, nullptr, FFF, DD, 2);

        gemm_mma<<<dim3(FFF / 128, MR / 128), 256>>>(
            nh, nl, wuh + of, wul + of, ub + (size_t)l * FFF,
            ffs_, nullptr, ffh, ffl, FFF, DD, 3);

        gemm_mma<<<dim3(DD / 128, MR / 128), 256>>>(
            ffh, ffl, wdh + of, wdl + of, dnb + (size_t)l * DD,
            h_, h_, nullptr, nullptr, DD, FFF, 1);
    }

    rmsnorm_split<<<MR, 256>>>(h_, norm_w, nh, nl);

    gemm_mma<<<dim3(VV / 128, MR / 128), 256>>>(
        nh, nl, whh, whl, nullptr,
        nullptr, out, nullptr, nullptr, VV, DD, 0);
}

// round 4
// speedup vs baseline: 3.5543x; 1.0967x over previous
#include <cuda_runtime.h>
#include <cuda_bf16.h>
#include <math.h>
#include <stdint.h>

// ---------------- problem dims ----------------
#define BB   2
#define TT   2048
#define DD   1024
#define NHH  16
#define HDD  64
#define FFF  4096
#define NLL  2
#define VV   32000
#define MR   (BB*TT)          // 4096 token rows
#define EPSF 1.1920929e-07f

// ---------------- fp32 scratch ----------------
__device__ float g_h  [(size_t)MR*DD];
__device__ float g_qkv[(size_t)MR*3*DD];
__device__ float g_ffs[(size_t)MR*FFF];

// ---------------- bf16 split scratch (hi/lo) ----------------
__device__ __nv_bfloat16 g_wqkv_h[(size_t)NLL*3*DD*DD], g_wqkv_l[(size_t)NLL*3*DD*DD];
__device__ __nv_bfloat16 g_wo_h  [(size_t)NLL*DD*DD],   g_wo_l  [(size_t)NLL*DD*DD];
__device__ __nv_bfloat16 g_wg_h  [(size_t)NLL*FFF*DD],  g_wg_l  [(size_t)NLL*FFF*DD];
__device__ __nv_bfloat16 g_wu_h  [(size_t)NLL*FFF*DD],  g_wu_l  [(size_t)NLL*FFF*DD];
__device__ __nv_bfloat16 g_wdn_h [(size_t)NLL*DD*FFF],  g_wdn_l [(size_t)NLL*DD*FFF];
__device__ __nv_bfloat16 g_whd_h [(size_t)VV*DD],       g_whd_l [(size_t)VV*DD];
__device__ __nv_bfloat16 g_n_h   [(size_t)MR*DD],       g_n_l   [(size_t)MR*DD];
__device__ __nv_bfloat16 g_at_h  [(size_t)MR*DD],       g_at_l  [(size_t)MR*DD];
__device__ __nv_bfloat16 g_ff_h  [(size_t)MR*FFF],      g_ff_l  [(size_t)MR*FFF];

// ================= helpers =================
__device__ __forceinline__ uint32_t smem_u32(const void* p) {
    uint32_t a;
    asm("{ .reg .u64 t; cvta.to.shared.u64 t, %1; cvt.u32.u64 %0, t; }" : "=r"(a) : "l"(p));
    return a;
}

// ================= weight split: x -> hi(bf16) + lo(bf16) =================
__global__ __launch_bounds__(256) void split4_kernel(const float4* __restrict__ src,
                                                     __nv_bfloat16* __restrict__ hi,
                                                     __nv_bfloat16* __restrict__ lo,
                                                     size_t n4) {
    size_t stride = (size_t)gridDim.x * blockDim.x;
    for (size_t i = (size_t)blockIdx.x * blockDim.x + threadIdx.x; i < n4; i += stride) {
        float4 v = src[i];
        __nv_bfloat16 hx = __float2bfloat16(v.x), hy = __float2bfloat16(v.y);
        __nv_bfloat16 hz = __float2bfloat16(v.z), hw = __float2bfloat16(v.w);
        ((ushort4*)hi)[i] = make_ushort4(__bfloat16_as_ushort(hx), __bfloat16_as_ushort(hy),
                                         __bfloat16_as_ushort(hz), __bfloat16_as_ushort(hw));
        __nv_bfloat16 lx = __float2bfloat16(v.x - __bfloat162float(hx));
        __nv_bfloat16 ly = __float2bfloat16(v.y - __bfloat162float(hy));
        __nv_bfloat16 lz = __float2bfloat16(v.z - __bfloat162float(hz));
        __nv_bfloat16 lw = __float2bfloat16(v.w - __bfloat162float(hw));
        ((ushort4*)lo)[i] = make_ushort4(__bfloat16_as_ushort(lx), __bfloat16_as_ushort(ly),
                                         __bfloat16_as_ushort(lz), __bfloat16_as_ushort(lw));
    }
}

// ================= embedding =================
__global__ __launch_bounds__(256) void embed_kernel(const int* __restrict__ x,
                                                    const float* __restrict__ emb,
                                                    float* __restrict__ h) {
    int row = blockIdx.x;
    int tok = x[row];
    ((float4*)(h + (size_t)row * DD))[threadIdx.x] =
        ((const float4*)(emb + (size_t)tok * DD))[threadIdx.x];
}

// ================= RMSNorm -> bf16 hi/lo =================
__global__ __launch_bounds__(256) void rmsnorm_split(const float* __restrict__ x,
                                                     const float* __restrict__ w,
                                                     __nv_bfloat16* __restrict__ hi,
                                                     __nv_bfloat16* __restrict__ lo) {
    int row = blockIdx.x, t = threadIdx.x;
    float4 v = ((const float4*)(x + (size_t)row * DD))[t];
    float ss = v.x*v.x + v.y*v.y + v.z*v.z + v.w*v.w;
    #pragma unroll
    for (int o = 16; o > 0; o >>= 1) ss += __shfl_xor_sync(0xffffffffu, ss, o);
    __shared__ float wsum[8];
    if ((t & 31) == 0) wsum[t >> 5] = ss;
    __syncthreads();
    float tot = 0.f;
    #pragma unroll
    for (int i = 0; i < 8; i++) tot += wsum[i];
    float rs = rsqrtf(tot * (1.0f / (float)DD) + EPSF);
    float4 wv = ((const float4*)w)[t];
    float ox = v.x * rs * wv.x, oy = v.y * rs * wv.y;
    float oz = v.z * rs * wv.z, ow = v.w * rs * wv.w;
    __nv_bfloat16 hx = __float2bfloat16(ox), hy = __float2bfloat16(oy);
    __nv_bfloat16 hz = __float2bfloat16(oz), hw = __float2bfloat16(ow);
    ((ushort4*)(hi + (size_t)row * DD))[t] =
        make_ushort4(__bfloat16_as_ushort(hx), __bfloat16_as_ushort(hy),
                     __bfloat16_as_ushort(hz), __bfloat16_as_ushort(hw));
    __nv_bfloat16 lx = __float2bfloat16(ox - __bfloat162float(hx));
    __nv_bfloat16 ly = __float2bfloat16(oy - __bfloat162float(hy));
    __nv_bfloat16 lz = __float2bfloat16(oz - __bfloat162float(hz));
    __nv_bfloat16 lw = __float2bfloat16(ow - __bfloat162float(hw));
    ((ushort4*)(lo + (size_t)row * DD))[t] =
        make_ushort4(__bfloat16_as_ushort(lx), __bfloat16_as_ushort(ly),
                     __bfloat16_as_ushort(lz), __bfloat16_as_ushort(lw));
}

// ================= HMMA GEMM, merged hi/lo operands =================
// C[M=4096, N] = epi( (Ahi+Alo)[M,K] @ (Whi+Wlo)[N,K]^T + bias )
// Per 32-wide k-chunk: load Ahi/Alo/Whi/Wlo tiles once, run all 3 passes
// (hi*hi + lo*hi + hi*lo) against them. CTA tile 128x128, 8 warps (2m x 4n),
// warp tile 64x32, mma.m16n8k16. 3-stage cp.async pipeline (3 x 32KB).
// Grid: (mt fast, nt slow) so a wave shares weight tiles through L2.
// epi: 0 fp32 out; 1 fp32 out + aux; 2 silu fp32 out; 3 (acc+bias)*aux -> bf16 hi/lo.
#define GSMEM (3 * 32768)

__global__ __launch_bounds__(256, 2) void gemm_mma(
    const __nv_bfloat16* __restrict__ ahi, const __nv_bfloat16* __restrict__ alo,
    const __nv_bfloat16* __restrict__ whi, const __nv_bfloat16* __restrict__ wlo,
    const float* __restrict__ bias, const float* __restrict__ aux,
    float* outf, __nv_bfloat16* ohi, __nv_bfloat16* olo,
    int N, int K, int epi)
{
    extern __shared__ __align__(1024) char smem[];
    const int tid = threadIdx.x;
    const int wid = tid >> 5, lane = tid & 31;
    const int mt = blockIdx.x, nt = blockIdx.y;
    const int warp_m = wid >> 2, warp_n = wid & 3;
    const uint32_t sbase = smem_u32(smem);

    float acc[4][4][4];
    #pragma unroll
    for (int f = 0; f < 4; f++)
        #pragma unroll
        for (int g = 0; g < 4; g++)
            #pragma unroll
            for (int e = 0; e < 4; e++) acc[f][g][e] = 0.f;

    const int nc = K >> 5;

    // tiles per 32KB stage: Ahi @0, Alo @8K, Whi @16K, Wlo @24K
    auto prefetch = [&](int kc, int b) {
        const size_t koff = (size_t)kc << 5;
        const uint32_t bufo = sbase + (uint32_t)b * 32768u;
        const __nv_bfloat16* bases[4] = {
            ahi + ((size_t)mt * 128) * K + koff,
            alo + ((size_t)mt * 128) * K + koff,
            whi + ((size_t)nt * 128) * K + koff,
            wlo + ((size_t)nt * 128) * K + koff };
        #pragma unroll
        for (int rep = 0; rep < 8; ++rep) {
            const int idx = tid + 256 * rep;          // 0..2047
            const int tile = idx >> 9;                // 0..3
            const int r  = (idx >> 2) & 127;
            const int c4 = idx & 3;
            const __nv_bfloat16* g = bases[tile] + (size_t)r * K + c4 * 8;
            const uint32_t dst = bufo + (uint32_t)tile * 8192u
                               + (uint32_t)(r * 64 + ((c4 ^ ((r >> 1) & 3)) << 4));
            asm volatile("cp.async.cg.shared.global [%0], [%1], 16;" :: "r"(dst), "l"(g));
        }
        asm volatile("cp.async.commit_group;" ::: "memory");
    };

    prefetch(0, 0);
    if (nc > 1) prefetch(1, 1);
    for (int c = 0; c < nc; ++c) {
        if (c + 2 < nc) {
            prefetch(c + 2, (c + 2) % 3);
            asm volatile("cp.async.wait_group 2;" ::: "memory");
        } else if (c + 1 < nc) {
            asm volatile("cp.async.wait_group 1;" ::: "memory");
        } else {
            asm volatile("cp.async.wait_group 0;" ::: "memory");
        }
        __syncthreads();

        const uint32_t buf = sbase + (uint32_t)(c % 3) * 32768u;
        const uint32_t a_hi_b = buf, a_lo_b = buf + 8192u;
        const uint32_t b_hi_b = buf + 16384u, b_lo_b = buf + 24576u;

        #pragma unroll
        for (int s = 0; s < 2; ++s) {
            const int arow = warp_m * 64 + (lane & 15);
            const int ach  = s * 2 + (lane >> 4);
            const int brow = warp_n * 32 + (lane & 7);
            const int bch  = s * 2 + ((lane >> 3) & 1);

            uint32_t a_hi[4][4], a_lo[4][4], bf[4][2];
            #pragma unroll
            for (int f = 0; f < 4; ++f) {
                const int row = arow + f * 16;
                const uint32_t off = row * 64 + ((ach ^ ((row >> 1) & 3)) << 4);
                asm volatile("ldmatrix.sync.aligned.m8n8.x4.shared.b16 {%0,%1,%2,%3}, [%4];"
                    : "=r"(a_hi[f][0]), "=r"(a_hi[f][1]), "=r"(a_hi[f][2]), "=r"(a_hi[f][3])
                    : "r"(a_hi_b + off));
            }
            #pragma unroll
            for (int g = 0; g < 4; ++g) {
                const int row = brow + g * 8;
                const uint32_t off = row * 64 + ((bch ^ ((row >> 1) & 3)) << 4);
                asm volatile("ldmatrix.sync.aligned.m8n8.x2.shared.b16 {%0,%1}, [%2];"
                    : "=r"(bf[g][0]), "=r"(bf[g][1]) : "r"(b_hi_b + off));
            }
            // pass 1: hi * hi
            #pragma unroll
            for (int f = 0; f < 4; ++f)
                #pragma unroll
                for (int g = 0; g < 4; ++g)
                    asm volatile("mma.sync.aligned.m16n8k16.row.col.f32.bf16.bf16.f32 "
                        "{%0,%1,%2,%3}, {%4,%5,%6,%7}, {%8,%9}, {%0,%1,%2,%3};"
                        : "+f"(acc[f][g][0]), "+f"(acc[f][g][1]),
                          "+f"(acc[f][g][2]), "+f"(acc[f][g][3])
                        : "r"(a_hi[f][0]), "r"(a_hi[f][1]), "r"(a_hi[f][2]), "r"(a_hi[f][3]),
                          "r"(bf[g][0]), "r"(bf[g][1]));
            // pass 2: lo * hi
            #pragma unroll
            for (int f = 0; f < 4; ++f) {
                const int row = arow + f * 16;
                const uint32_t off = row * 64 + ((ach ^ ((row >> 1) & 3)) << 4);
                asm volatile("ldmatrix.sync.aligned.m8n8.x4.shared.b16 {%0,%1,%2,%3}, [%4];"
                    : "=r"(a_lo[f][0]), "=r"(a_lo[f][1]), "=r"(a_lo[f][2]), "=r"(a_lo[f][3])
                    : "r"(a_lo_b + off));
            }
            #pragma unroll
            for (int f = 0; f < 4; ++f)
                #pragma unroll
                for (int g = 0; g < 4; ++g)
                    asm volatile("mma.sync.aligned.m16n8k16.row.col.f32.bf16.bf16.f32 "
                        "{%0,%1,%2,%3}, {%4,%5,%6,%7}, {%8,%9}, {%0,%1,%2,%3};"
                        : "+f"(acc[f][g][0]), "+f"(acc[f][g][1]),
                          "+f"(acc[f][g][2]), "+f"(acc[f][g][3])
                        : "r"(a_lo[f][0]), "r"(a_lo[f][1]), "r"(a_lo[f][2]), "r"(a_lo[f][3]),
                          "r"(bf[g][0]), "r"(bf[g][1]));
            // pass 3: hi * lo  (reload b frags from Wlo)
            #pragma unroll
            for (int g = 0; g < 4; ++g) {
                const int row = brow + g * 8;
                const uint32_t off = row * 64 + ((bch ^ ((row >> 1) & 3)) << 4);
                asm volatile("ldmatrix.sync.aligned.m8n8.x2.shared.b16 {%0,%1}, [%2];"
                    : "=r"(bf[g][0]), "=r"(bf[g][1]) : "r"(b_lo_b + off));
            }
            #pragma unroll
            for (int f = 0; f < 4; ++f)
                #pragma unroll
                for (int g = 0; g < 4; ++g)
                    asm volatile("mma.sync.aligned.m16n8k16.row.col.f32.bf16.bf16.f32 "
                        "{%0,%1,%2,%3}, {%4,%5,%6,%7}, {%8,%9}, {%0,%1,%2,%3};"
                        : "+f"(acc[f][g][0]), "+f"(acc[f][g][1]),
                          "+f"(acc[f][g][2]), "+f"(acc[f][g][3])
                        : "r"(a_hi[f][0]), "r"(a_hi[f][1]), "r"(a_hi[f][2]), "r"(a_hi[f][3]),
                          "r"(bf[g][0]), "r"(bf[g][1]));
        }
        __syncthreads();
    }

    // ---- epilogue ----
    const int r_in = lane >> 2, c_in = (lane & 3) * 2;
    #pragma unroll
    for (int f = 0; f < 4; ++f) {
        #pragma unroll
        for (int rr = 0; rr < 2; ++rr) {
            const size_t m = (size_t)mt * 128 + warp_m * 64 + f * 16 + rr * 8 + r_in;
            float* frow = outf ? outf + m * (size_t)N : (float*)0;
            const float* arow = aux ? aux + m * (size_t)N : (const float*)0;
            #pragma unroll
            for (int g = 0; g < 4; ++g) {
                const int n = nt * 128 + warp_n * 32 + g * 8 + c_in;
                float x = acc[f][g][rr * 2 + 0];
                float y = acc[f][g][rr * 2 + 1];
                if (bias) { x += bias[n]; y += bias[n + 1]; }
                if (epi == 1) {
                    x += arow[n]; y += arow[n + 1];
                    frow[n] = x; frow[n + 1] = y;
                } else if (epi == 2) {
                    x = x / (1.f + expf(-x)); y = y / (1.f + expf(-y));
                    frow[n] = x; frow[n + 1] = y;
                } else if (epi == 3) {
                    x *= arow[n]; y *= arow[n + 1];
                    __nv_bfloat16 hx = __float2bfloat16(x), hy = __float2bfloat16(y);
                    *(ushort2*)(ohi + m * (size_t)N + n) =
                        make_ushort2(__bfloat16_as_ushort(hx), __bfloat16_as_ushort(hy));
                    __nv_bfloat16 lx = __float2bfloat16(x - __bfloat162float(hx));
                    __nv_bfloat16 ly = __float2bfloat16(y - __bfloat162float(hy));
                    *(ushort2*)(olo + m * (size_t)N + n) =
                        make_ushort2(__bfloat16_as_ushort(lx), __bfloat16_as_ushort(ly));
                } else {
                    frow[n] = x; frow[n + 1] = y;
                }
            }
        }
    }
}

// ================= flash attention (fp32, causal), HD=64, out -> bf16 hi/lo ======
#define APITCH 68
#define ATTN_SMEM ((4 * 64 * APITCH + 3 * 64) * (int)sizeof(float))

__global__ __launch_bounds__(256) void attn_kernel(const float* __restrict__ qkv,
                                                   __nv_bfloat16* __restrict__ ohi,
                                                   __nv_bfloat16* __restrict__ olo) {
    extern __shared__ float sm[];
    float* Qs = sm;
    float* Ks = Qs + 64 * APITCH;
    float* Vs = Ks + 64 * APITCH;
    float* Ss = Vs + 64 * APITCH;
    float* rowm = Ss + 64 * APITCH;
    float* rowl = rowm + 64;
    float* rowsc = rowl + 64;

    const int t = threadIdx.x;
    const int qt = blockIdx.x, h = blockIdx.y, b = blockIdx.z;
    const int q0 = qt * 64;
    const int tx = t & 15, ty = t >> 4;
    const float NEG = -1e30f;

    for (int i = t; i < 64 * 16; i += 256) {
        int row = i >> 4, c4 = i & 15;
        *(float4*)(&Qs[row * APITCH + c4 * 4]) =
            *(const float4*)(qkv + ((size_t)(b * TT + q0 + row)) * (3 * DD) + h * HDD + c4 * 4);
    }
    if (t < 64) { rowm[t] = NEG; rowl[t] = 0.f; }

    float o_acc[4][4];
    #pragma unroll
    for (int i = 0; i < 4; i++)
        #pragma unroll
        for (int j = 0; j < 4; j++) o_acc[i][j] = 0.f;

    for (int jt = 0; jt <= qt; jt++) {
        const int k0 = jt * 64;
        for (int i = t; i < 64 * 16; i += 256) {
            int row = i >> 4, c4 = i & 15;
            size_t base = ((size_t)(b * TT + k0 + row)) * (3 * DD) + h * HDD + c4 * 4;
            *(float4*)(&Ks[row * APITCH + c4 * 4]) = *(const float4*)(qkv + base + DD);
            *(float4*)(&Vs[row * APITCH + c4 * 4]) = *(const float4*)(qkv + base + 2 * DD);
        }
        __syncthreads();

        float s[4][4];
        #pragma unroll
        for (int i = 0; i < 4; i++)
            #pragma unroll
            for (int j = 0; j < 4; j++) s[i][j] = 0.f;
        #pragma unroll 4
        for (int d4 = 0; d4 < 16; d4++) {
            float4 q4[4], k4[4];
            #pragma unroll
            for (int i = 0; i < 4; i++) q4[i] = *(const float4*)(&Qs[(ty * 4 + i) * APITCH + d4 * 4]);
            #pragma unroll
            for (int j = 0; j < 4; j++) k4[j] = *(const float4*)(&Ks[(tx * 4 + j) * APITCH + d4 * 4]);
            #pragma unroll
            for (int i = 0; i < 4; i++)
                #pragma unroll
                for (int j = 0; j < 4; j++)
                    s[i][j] += q4[i].x * k4[j].x + q4[i].y * k4[j].y
                             + q4[i].z * k4[j].z + q4[i].w * k4[j].w;
        }
        const bool diag = (jt == qt);
        #pragma unroll
        for (int i = 0; i < 4; i++)
            #pragma unroll
            for (int j = 0; j < 4; j++) {
                float v = s[i][j] * 0.125f;
                if (diag && (k0 + tx * 4 + j > q0 + ty * 4 + i)) v = NEG;
                Ss[(ty * 4 + i) * APITCH + (tx * 4 + j)] = v;
            }
        __syncthreads();

        if (t < 64) {
            int r = t;
            float mold = rowm[r];
            float tmax = NEG;
            for (int j = 0; j < 64; j++) tmax = fmaxf(tmax, Ss[r * APITCH + j]);
            float mnew = fmaxf(mold, tmax);
            float corr = __expf(mold - mnew);
            float sum = 0.f;
            for (int j = 0; j < 64; j++) {
                float p = __expf(Ss[r * APITCH + j] - mnew);
                Ss[r * APITCH + j] = p;
                sum += p;
            }
            rowl[r] = rowl[r] * corr + sum;
            rowm[r] = mnew;
            rowsc[r] = corr;
        }
        __syncthreads();

        #pragma unroll
        for (int i = 0; i < 4; i++) {
            float c = rowsc[ty * 4 + i];
            #pragma unroll
            for (int j = 0; j < 4; j++) o_acc[i][j] *= c;
        }
        for (int k = 0; k < 64; k++) {
            float4 v4 = *(const float4*)(&Vs[k * APITCH + tx * 4]);
            #pragma unroll
            for (int i = 0; i < 4; i++) {
                float p = Ss[(ty * 4 + i) * APITCH + k];
                o_acc[i][0] += p * v4.x; o_acc[i][1] += p * v4.y;
                o_acc[i][2] += p * v4.z; o_acc[i][3] += p * v4.w;
            }
        }
        __syncthreads();
    }

    #pragma unroll
    for (int i = 0; i < 4; i++) {
        float invl = 1.0f / rowl[ty * 4 + i];
        size_t idx = ((size_t)(b * TT + q0 + ty * 4 + i)) * DD + h * HDD + tx * 4;
        float v0 = o_acc[i][0] * invl, v1 = o_acc[i][1] * invl;
        float v2 = o_acc[i][2] * invl, v3 = o_acc[i][3] * invl;
        __nv_bfloat16 h0 = __float2bfloat16(v0), h1 = __float2bfloat16(v1);
        __nv_bfloat16 h2 = __float2bfloat16(v2), h3 = __float2bfloat16(v3);
        *(ushort4*)(ohi + idx) = make_ushort4(__bfloat16_as_ushort(h0), __bfloat16_as_ushort(h1),
                                              __bfloat16_as_ushort(h2), __bfloat16_as_ushort(h3));
        __nv_bfloat16 l0 = __float2bfloat16(v0 - __bfloat162float(h0));
        __nv_bfloat16 l1 = __float2bfloat16(v1 - __bfloat162float(h1));
        __nv_bfloat16 l2 = __float2bfloat16(v2 - __bfloat162float(h2));
        __nv_bfloat16 l3 = __float2bfloat16(v3 - __bfloat162float(h3));
        *(ushort4*)(olo + idx) = make_ushort4(__bfloat16_as_ushort(l0), __bfloat16_as_ushort(l1),
                                              __bfloat16_as_ushort(l2), __bfloat16_as_ushort(l3));
    }
}

// ================= driver =================
extern "C" void kernel_launch(void* const* d_in, const int* in_sizes, int n_in,
                              void* d_out, int out_size) {
    const int*   x      = (const int*)  d_in[0];
    const float* emb_w  = (const float*)d_in[1];
    const float* n1_w   = (const float*)d_in[2];
    const float* n2_w   = (const float*)d_in[3];
    const float* qkv_w  = (const float*)d_in[4];
    const float* qkv_b  = (const float*)d_in[5];
    const float* o_w    = (const float*)d_in[6];
    const float* o_b    = (const float*)d_in[7];
    const float* gw     = (const float*)d_in[8];
    const float* gb     = (const float*)d_in[9];
    const float* uw     = (const float*)d_in[10];
    const float* ub     = (const float*)d_in[11];
    const float* dnw    = (const float*)d_in[12];
    const float* dnb    = (const float*)d_in[13];
    const float* norm_w = (const float*)d_in[14];
    const float* head_w = (const float*)d_in[15];
    float* out = (float*)d_out;

    float *h_, *qkv_, *ffs_;
    __nv_bfloat16 *wqh, *wql, *woh, *wol, *wgh, *wgl, *wuh, *wul, *wdh, *wdl, *whh, *whl;
    __nv_bfloat16 *nh, *nl, *ath, *atl, *ffh, *ffl;
    cudaGetSymbolAddress((void**)&h_,   g_h);
    cudaGetSymbolAddress((void**)&qkv_, g_qkv);
    cudaGetSymbolAddress((void**)&ffs_, g_ffs);
    cudaGetSymbolAddress((void**)&wqh, g_wqkv_h); cudaGetSymbolAddress((void**)&wql, g_wqkv_l);
    cudaGetSymbolAddress((void**)&woh, g_wo_h);   cudaGetSymbolAddress((void**)&wol, g_wo_l);
    cudaGetSymbolAddress((void**)&wgh, g_wg_h);   cudaGetSymbolAddress((void**)&wgl, g_wg_l);
    cudaGetSymbolAddress((void**)&wuh, g_wu_h);   cudaGetSymbolAddress((void**)&wul, g_wu_l);
    cudaGetSymbolAddress((void**)&wdh, g_wdn_h);  cudaGetSymbolAddress((void**)&wdl, g_wdn_l);
    cudaGetSymbolAddress((void**)&whh, g_whd_h);  cudaGetSymbolAddress((void**)&whl, g_whd_l);
    cudaGetSymbolAddress((void**)&nh,  g_n_h);    cudaGetSymbolAddress((void**)&nl,  g_n_l);
    cudaGetSymbolAddress((void**)&ath, g_at_h);   cudaGetSymbolAddress((void**)&atl, g_at_l);
    cudaGetSymbolAddress((void**)&ffh, g_ff_h);   cudaGetSymbolAddress((void**)&ffl, g_ff_l);

    cudaFuncSetAttribute(gemm_mma, cudaFuncAttributeMaxDynamicSharedMemorySize, GSMEM);
    cudaFuncSetAttribute(attn_kernel, cudaFuncAttributeMaxDynamicSharedMemorySize, ATTN_SMEM);

    // weight splits (inside the graph each replay; ~0.07 ms total)
    split4_kernel<<<2048, 256>>>((const float4*)qkv_w,  wqh, wql, (size_t)NLL*3*DD*DD/4);
    split4_kernel<<<2048, 256>>>((const float4*)o_w,    woh, wol, (size_t)NLL*DD*DD/4);
    split4_kernel<<<2048, 256>>>((const float4*)gw,     wgh, wgl, (size_t)NLL*FFF*DD/4);
    split4_kernel<<<2048, 256>>>((const float4*)uw,     wuh, wul, (size_t)NLL*FFF*DD/4);
    split4_kernel<<<2048, 256>>>((const float4*)dnw,    wdh, wdl, (size_t)NLL*DD*FFF/4);
    split4_kernel<<<2048, 256>>>((const float4*)head_w, whh, whl, (size_t)VV*DD/4);

    embed_kernel<<<MR, 256>>>(x, emb_w, h_);

    for (int l = 0; l < NLL; l++) {
        const size_t oq = (size_t)l * 3 * DD * DD, oo = (size_t)l * DD * DD;
        const size_t of = (size_t)l * FFF * DD;

        rmsnorm_split<<<MR, 256>>>(h_, n1_w + (size_t)l * DD, nh, nl);

        gemm_mma<<<dim3(MR / 128, 3 * DD / 128), 256, GSMEM>>>(
            nh, nl, wqh + oq, wql + oq, qkv_b + (size_t)l * 3 * DD,
            nullptr, qkv_, nullptr, nullptr, 3 * DD, DD, 0);

        attn_kernel<<<dim3(TT / 64, NHH, BB), 256, ATTN_SMEM>>>(qkv_, ath, atl);

        gemm_mma<<<dim3(MR / 128, DD / 128), 256, GSMEM>>>(
            ath, atl, woh + oo, wol + oo, o_b + (size_t)l * DD,
            h_, h_, nullptr, nullptr, DD, DD, 1);

        rmsnorm_split<<<MR, 256>>>(h_, n2_w + (size_t)l * DD, nh, nl);

        gemm_mma<<<dim3(MR / 128, FFF / 128), 256, GSMEM>>>(
            nh, nl, wgh + of, wgl + of, gb + (size_t)l * FFF,
            nullptr, ffs_, nullptr, nullptr, FFF, DD, 2);

        gemm_mma<<<dim3(MR / 128, FFF / 128), 256, GSMEM>>>(
            nh, nl, wuh + of, wul + of, ub + (size_t)l * FFF,
            ffs_, nullptr, ffh, ffl, FFF, DD, 3);

        gemm_mma<<<dim3(MR / 128, DD / 128), 256, GSMEM>>>(
            ffh, ffl, wdh + of, wdl + of, dnb + (size_t)l * DD,
            h_, h_, nullptr, nullptr, DD, FFF, 1);
    }

    rmsnorm_split<<<MR, 256>>>(h_, norm_w, nh, nl);

    gemm_mma<<<dim3(MR / 128, VV / 128), 256, GSMEM>>>(
        nh, nl, whh, whl, nullptr,
        nullptr, out, nullptr, nullptr, VV, DD, 0);
}

// round 6
// speedup vs baseline: 3.5685x; 1.0040x over previous
#include <cuda_runtime.h>
#include <cuda_bf16.h>
#include <math.h>
#include <stdint.h>

// ---------------- problem dims ----------------
#define BB   2
#define TT   2048
#define DD   1024
#define NHH  16
#define HDD  64
#define FFF  4096
#define NLL  2
#define VV   32000
#define MR   (BB*TT)          // 4096 token rows
#define EPSF 1.1920929e-07f

// ---------------- fp32 scratch ----------------
__device__ float g_h  [(size_t)MR*DD];
__device__ float g_qkv[(size_t)MR*3*DD];
__device__ float g_ffs[(size_t)MR*FFF];

// ---------------- bf16 split scratch (hi/lo) ----------------
__device__ __nv_bfloat16 g_wqkv_h[(size_t)NLL*3*DD*DD], g_wqkv_l[(size_t)NLL*3*DD*DD];
__device__ __nv_bfloat16 g_wo_h  [(size_t)NLL*DD*DD],   g_wo_l  [(size_t)NLL*DD*DD];
__device__ __nv_bfloat16 g_wg_h  [(size_t)NLL*FFF*DD],  g_wg_l  [(size_t)NLL*FFF*DD];
__device__ __nv_bfloat16 g_wu_h  [(size_t)NLL*FFF*DD],  g_wu_l  [(size_t)NLL*FFF*DD];
__device__ __nv_bfloat16 g_wdn_h [(size_t)NLL*DD*FFF],  g_wdn_l [(size_t)NLL*DD*FFF];
__device__ __nv_bfloat16 g_whd_h [(size_t)VV*DD],       g_whd_l [(size_t)VV*DD];
__device__ __nv_bfloat16 g_n_h   [(size_t)MR*DD],       g_n_l   [(size_t)MR*DD];
__device__ __nv_bfloat16 g_at_h  [(size_t)MR*DD],       g_at_l  [(size_t)MR*DD];
__device__ __nv_bfloat16 g_ff_h  [(size_t)MR*FFF],      g_ff_l  [(size_t)MR*FFF];

// ================= helpers =================
__device__ __forceinline__ uint32_t smem_u32(const void* p) {
    uint32_t a;
    asm("{ .reg .u64 t; cvta.to.shared.u64 t, %1; cvt.u32.u64 %0, t; }" : "=r"(a) : "l"(p));
    return a;
}

// ================= weight split: x -> hi(bf16) + lo(bf16) =================
__global__ __launch_bounds__(256) void split4_kernel(const float4* __restrict__ src,
                                                     __nv_bfloat16* __restrict__ hi,
                                                     __nv_bfloat16* __restrict__ lo,
                                                     size_t n4) {
    size_t stride = (size_t)gridDim.x * blockDim.x;
    for (size_t i = (size_t)blockIdx.x * blockDim.x + threadIdx.x; i < n4; i += stride) {
        float4 v = src[i];
        __nv_bfloat16 hx = __float2bfloat16(v.x), hy = __float2bfloat16(v.y);
        __nv_bfloat16 hz = __float2bfloat16(v.z), hw = __float2bfloat16(v.w);
        ((ushort4*)hi)[i] = make_ushort4(__bfloat16_as_ushort(hx), __bfloat16_as_ushort(hy),
                                         __bfloat16_as_ushort(hz), __bfloat16_as_ushort(hw));
        __nv_bfloat16 lx = __float2bfloat16(v.x - __bfloat162float(hx));
        __nv_bfloat16 ly = __float2bfloat16(v.y - __bfloat162float(hy));
        __nv_bfloat16 lz = __float2bfloat16(v.z - __bfloat162float(hz));
        __nv_bfloat16 lw = __float2bfloat16(v.w - __bfloat162float(hw));
        ((ushort4*)lo)[i] = make_ushort4(__bfloat16_as_ushort(lx), __bfloat16_as_ushort(ly),
                                         __bfloat16_as_ushort(lz), __bfloat16_as_ushort(lw));
    }
}

// ================= embedding =================
__global__ __launch_bounds__(256) void embed_kernel(const int* __restrict__ x,
                                                    const float* __restrict__ emb,
                                                    float* __restrict__ h) {
    int row = blockIdx.x;
    int tok = x[row];
    ((float4*)(h + (size_t)row * DD))[threadIdx.x] =
        ((const float4*)(emb + (size_t)tok * DD))[threadIdx.x];
}

// ================= RMSNorm -> bf16 hi/lo =================
__global__ __launch_bounds__(256) void rmsnorm_split(const float* __restrict__ x,
                                                     const float* __restrict__ w,
                                                     __nv_bfloat16* __restrict__ hi,
                                                     __nv_bfloat16* __restrict__ lo) {
    int row = blockIdx.x, t = threadIdx.x;
    float4 v = ((const float4*)(x + (size_t)row * DD))[t];
    float ss = v.x*v.x + v.y*v.y + v.z*v.z + v.w*v.w;
    #pragma unroll
    for (int o = 16; o > 0; o >>= 1) ss += __shfl_xor_sync(0xffffffffu, ss, o);
    __shared__ float wsum[8];
    if ((t & 31) == 0) wsum[t >> 5] = ss;
    __syncthreads();
    float tot = 0.f;
    #pragma unroll
    for (int i = 0; i < 8; i++) tot += wsum[i];
    float rs = rsqrtf(tot * (1.0f / (float)DD) + EPSF);
    float4 wv = ((const float4*)w)[t];
    float ox = v.x * rs * wv.x, oy = v.y * rs * wv.y;
    float oz = v.z * rs * wv.z, ow = v.w * rs * wv.w;
    __nv_bfloat16 hx = __float2bfloat16(ox), hy = __float2bfloat16(oy);
    __nv_bfloat16 hz = __float2bfloat16(oz), hw = __float2bfloat16(ow);
    ((ushort4*)(hi + (size_t)row * DD))[t] =
        make_ushort4(__bfloat16_as_ushort(hx), __bfloat16_as_ushort(hy),
                     __bfloat16_as_ushort(hz), __bfloat16_as_ushort(hw));
    __nv_bfloat16 lx = __float2bfloat16(ox - __bfloat162float(hx));
    __nv_bfloat16 ly = __float2bfloat16(oy - __bfloat162float(hy));
    __nv_bfloat16 lz = __float2bfloat16(oz - __bfloat162float(hz));
    __nv_bfloat16 lw = __float2bfloat16(ow - __bfloat162float(hw));
    ((ushort4*)(lo + (size_t)row * DD))[t] =
        make_ushort4(__bfloat16_as_ushort(lx), __bfloat16_as_ushort(ly),
                     __bfloat16_as_ushort(lz), __bfloat16_as_ushort(lw));
}

// ================= HMMA GEMM, merged hi/lo operands, low-reg schedule ==========
// C[M=4096, N] = epi( (Ahi+Alo)[M,K] @ (Whi+Wlo)[N,K]^T + bias )
// Per 32-wide k-chunk, per s half-chunk:
//   A<-Ahi, B<-Whi : mma (hi*hi)
//   B<-Wlo         : mma (hi*lo)
//   A<-Alo, B<-Whi : mma (lo*hi)
// Only 24 fragment regs live at once -> no spills at 128-reg cap (2 CTAs/SM).
// CTA tile 128x128, 8 warps (2m x 4n), warp tile 64x32, 3-stage cp.async.
// epi: 0 fp32 out; 1 fp32 out + aux; 2 silu fp32 out; 3 (acc+bias)*aux -> bf16 hi/lo.
#define GSMEM (3 * 32768)

#define MMA16(accfg, A, B0, B1) \
    asm volatile("mma.sync.aligned.m16n8k16.row.col.f32.bf16.bf16.f32 " \
        "{%0,%1,%2,%3}, {%4,%5,%6,%7}, {%8,%9}, {%0,%1,%2,%3};" \
        : "+f"((accfg)[0]), "+f"((accfg)[1]), "+f"((accfg)[2]), "+f"((accfg)[3]) \
        : "r"((A)[0]), "r"((A)[1]), "r"((A)[2]), "r"((A)[3]), "r"(B0), "r"(B1))

__global__ __launch_bounds__(256, 2) void gemm_mma(
    const __nv_bfloat16* __restrict__ ahi, const __nv_bfloat16* __restrict__ alo,
    const __nv_bfloat16* __restrict__ whi, const __nv_bfloat16* __restrict__ wlo,
    const float* __restrict__ bias, const float* __restrict__ aux,
    float* outf, __nv_bfloat16* ohi, __nv_bfloat16* olo,
    int N, int K, int epi)
{
    extern __shared__ __align__(1024) char smem[];
    const int tid = threadIdx.x;
    const int wid = tid >> 5, lane = tid & 31;
    const int mt = blockIdx.x, nt = blockIdx.y;
    const int warp_m = wid >> 2, warp_n = wid & 3;
    const uint32_t sbase = smem_u32(smem);

    float acc[4][4][4];
    #pragma unroll
    for (int f = 0; f < 4; f++)
        #pragma unroll
        for (int g = 0; g < 4; g++)
            #pragma unroll
            for (int e = 0; e < 4; e++) acc[f][g][e] = 0.f;

    const int nc = K >> 5;

    // tiles per 32KB stage: Ahi @0, Alo @8K, Whi @16K, Wlo @24K
    auto prefetch = [&](int kc, int b) {
        const size_t koff = (size_t)kc << 5;
        const uint32_t bufo = sbase + (uint32_t)b * 32768u;
        const __nv_bfloat16* bases[4] = {
            ahi + ((size_t)mt * 128) * K + koff,
            alo + ((size_t)mt * 128) * K + koff,
            whi + ((size_t)nt * 128) * K + koff,
            wlo + ((size_t)nt * 128) * K + koff };
        #pragma unroll
        for (int rep = 0; rep < 8; ++rep) {
            const int idx = tid + 256 * rep;          // 0..2047
            const int tile = idx >> 9;                // 0..3
            const int r  = (idx >> 2) & 127;
            const int c4 = idx & 3;
            const __nv_bfloat16* g = bases[tile] + (size_t)r * K + c4 * 8;
            const uint32_t dst = bufo + (uint32_t)tile * 8192u
                               + (uint32_t)(r * 64 + ((c4 ^ ((r >> 1) & 3)) << 4));
            asm volatile("cp.async.cg.shared.global [%0], [%1], 16;" :: "r"(dst), "l"(g));
        }
        asm volatile("cp.async.commit_group;" ::: "memory");
    };

    prefetch(0, 0);
    if (nc > 1) prefetch(1, 1);
    for (int c = 0; c < nc; ++c) {
        if (c + 2 < nc) {
            prefetch(c + 2, (c + 2) % 3);
            asm volatile("cp.async.wait_group 2;" ::: "memory");
        } else if (c + 1 < nc) {
            asm volatile("cp.async.wait_group 1;" ::: "memory");
        } else {
            asm volatile("cp.async.wait_group 0;" ::: "memory");
        }
        __syncthreads();

        const uint32_t buf = sbase + (uint32_t)(c % 3) * 32768u;
        const uint32_t a_hi_b = buf, a_lo_b = buf + 8192u;
        const uint32_t b_hi_b = buf + 16384u, b_lo_b = buf + 24576u;

        #pragma unroll
        for (int s = 0; s < 2; ++s) {
            const int arow = warp_m * 64 + (lane & 15);
            const int ach  = s * 2 + (lane >> 4);
            const int brow = warp_n * 32 + (lane & 7);
            const int bch  = s * 2 + ((lane >> 3) & 1);
            uint32_t aoff[4], boff[4];
            #pragma unroll
            for (int f = 0; f < 4; ++f) {
                const int row = arow + f * 16;
                aoff[f] = row * 64 + ((ach ^ ((row >> 1) & 3)) << 4);
            }
            #pragma unroll
            for (int g = 0; g < 4; ++g) {
                const int row = brow + g * 8;
                boff[g] = row * 64 + ((bch ^ ((row >> 1) & 3)) << 4);
            }

            uint32_t A[4][4], Bv[4][2];
            // --- A <- Ahi, B <- Whi : hi*hi ---
            #pragma unroll
            for (int f = 0; f < 4; ++f)
                asm volatile("ldmatrix.sync.aligned.m8n8.x4.shared.b16 {%0,%1,%2,%3}, [%4];"
                    : "=r"(A[f][0]), "=r"(A[f][1]), "=r"(A[f][2]), "=r"(A[f][3])
                    : "r"(a_hi_b + aoff[f]));
            #pragma unroll
            for (int g = 0; g < 4; ++g)
                asm volatile("ldmatrix.sync.aligned.m8n8.x2.shared.b16 {%0,%1}, [%2];"
                    : "=r"(Bv[g][0]), "=r"(Bv[g][1]) : "r"(b_hi_b + boff[g]));
            #pragma unroll
            for (int f = 0; f < 4; ++f)
                #pragma unroll
                for (int g = 0; g < 4; ++g)
                    MMA16(acc[f][g], A[f], Bv[g][0], Bv[g][1]);
            // --- B <- Wlo : hi*lo ---
            #pragma unroll
            for (int g = 0; g < 4; ++g)
                asm volatile("ldmatrix.sync.aligned.m8n8.x2.shared.b16 {%0,%1}, [%2];"
                    : "=r"(Bv[g][0]), "=r"(Bv[g][1]) : "r"(b_lo_b + boff[g]));
            #pragma unroll
            for (int f = 0; f < 4; ++f)
                #pragma unroll
                for (int g = 0; g < 4; ++g)
                    MMA16(acc[f][g], A[f], Bv[g][0], Bv[g][1]);
            // --- A <- Alo, B <- Whi : lo*hi ---
            #pragma unroll
            for (int f = 0; f < 4; ++f)
                asm volatile("ldmatrix.sync.aligned.m8n8.x4.shared.b16 {%0,%1,%2,%3}, [%4];"
                    : "=r"(A[f][0]), "=r"(A[f][1]), "=r"(A[f][2]), "=r"(A[f][3])
                    : "r"(a_lo_b + aoff[f]));
            #pragma unroll
            for (int g = 0; g < 4; ++g)
                asm volatile("ldmatrix.sync.aligned.m8n8.x2.shared.b16 {%0,%1}, [%2];"
                    : "=r"(Bv[g][0]), "=r"(Bv[g][1]) : "r"(b_hi_b + boff[g]));
            #pragma unroll
            for (int f = 0; f < 4; ++f)
                #pragma unroll
                for (int g = 0; g < 4; ++g)
                    MMA16(acc[f][g], A[f], Bv[g][0], Bv[g][1]);
        }
        __syncthreads();
    }

    // ---- epilogue ----
    const int r_in = lane >> 2, c_in = (lane & 3) * 2;
    #pragma unroll
    for (int f = 0; f < 4; ++f) {
        #pragma unroll
        for (int rr = 0; rr < 2; ++rr) {
            const size_t m = (size_t)mt * 128 + warp_m * 64 + f * 16 + rr * 8 + r_in;
            float* frow = outf ? outf + m * (size_t)N : (float*)0;
            const float* arow = aux ? aux + m * (size_t)N : (const float*)0;
            #pragma unroll
            for (int g = 0; g < 4; ++g) {
                const int n = nt * 128 + warp_n * 32 + g * 8 + c_in;
                float x = acc[f][g][rr * 2 + 0];
                float y = acc[f][g][rr * 2 + 1];
                if (bias) { x += bias[n]; y += bias[n + 1]; }
                if (epi == 1) {
                    x += arow[n]; y += arow[n + 1];
                    frow[n] = x; frow[n + 1] = y;
                } else if (epi == 2) {
                    x = x / (1.f + expf(-x)); y = y / (1.f + expf(-y));
                    frow[n] = x; frow[n + 1] = y;
                } else if (epi == 3) {
                    x *= arow[n]; y *= arow[n + 1];
                    __nv_bfloat16 hx = __float2bfloat16(x), hy = __float2bfloat16(y);
                    *(ushort2*)(ohi + m * (size_t)N + n) =
                        make_ushort2(__bfloat16_as_ushort(hx), __bfloat16_as_ushort(hy));
                    __nv_bfloat16 lx = __float2bfloat16(x - __bfloat162float(hx));
                    __nv_bfloat16 ly = __float2bfloat16(y - __bfloat162float(hy));
                    *(ushort2*)(olo + m * (size_t)N + n) =
                        make_ushort2(__bfloat16_as_ushort(lx), __bfloat16_as_ushort(ly));
                } else {
                    frow[n] = x; frow[n + 1] = y;
                }
            }
        }
    }
}

// ================= flash attention (fp32, causal), HD=64, out -> bf16 hi/lo ======
#define APITCH 68
#define ATTN_SMEM ((4 * 64 * APITCH + 3 * 64) * (int)sizeof(float))

__global__ __launch_bounds__(256) void attn_kernel(const float* __restrict__ qkv,
                                                   __nv_bfloat16* __restrict__ ohi,
                                                   __nv_bfloat16* __restrict__ olo) {
    extern __shared__ float sm[];
    float* Qs = sm;
    float* Ks = Qs + 64 * APITCH;
    float* Vs = Ks + 64 * APITCH;
    float* Ss = Vs + 64 * APITCH;
    float* rowm = Ss + 64 * APITCH;
    float* rowl = rowm + 64;
    float* rowsc = rowl + 64;

    const int t = threadIdx.x;
    const int qt = blockIdx.x, h = blockIdx.y, b = blockIdx.z;
    const int q0 = qt * 64;
    const int tx = t & 15, ty = t >> 4;
    const float NEG = -1e30f;

    for (int i = t; i < 64 * 16; i += 256) {
        int row = i >> 4, c4 = i & 15;
        *(float4*)(&Qs[row * APITCH + c4 * 4]) =
            *(const float4*)(qkv + ((size_t)(b * TT + q0 + row)) * (3 * DD) + h * HDD + c4 * 4);
    }
    if (t < 64) { rowm[t] = NEG; rowl[t] = 0.f; }

    float o_acc[4][4];
    #pragma unroll
    for (int i = 0; i < 4; i++)
        #pragma unroll
        for (int j = 0; j < 4; j++) o_acc[i][j] = 0.f;

    for (int jt = 0; jt <= qt; jt++) {
        const int k0 = jt * 64;
        for (int i = t; i < 64 * 16; i += 256) {
            int row = i >> 4, c4 = i & 15;
            size_t base = ((size_t)(b * TT + k0 + row)) * (3 * DD) + h * HDD + c4 * 4;
            *(float4*)(&Ks[row * APITCH + c4 * 4]) = *(const float4*)(qkv + base + DD);
            *(float4*)(&Vs[row * APITCH + c4 * 4]) = *(const float4*)(qkv + base + 2 * DD);
        }
        __syncthreads();

        float s[4][4];
        #pragma unroll
        for (int i = 0; i < 4; i++)
            #pragma unroll
            for (int j = 0; j < 4; j++) s[i][j] = 0.f;
        #pragma unroll 4
        for (int d4 = 0; d4 < 16; d4++) {
            float4 q4[4], k4[4];
            #pragma unroll
            for (int i = 0; i < 4; i++) q4[i] = *(const float4*)(&Qs[(ty * 4 + i) * APITCH + d4 * 4]);
            #pragma unroll
            for (int j = 0; j < 4; j++) k4[j] = *(const float4*)(&Ks[(tx * 4 + j) * APITCH + d4 * 4]);
            #pragma unroll
            for (int i = 0; i < 4; i++)
                #pragma unroll
                for (int j = 0; j < 4; j++)
                    s[i][j] += q4[i].x * k4[j].x + q4[i].y * k4[j].y
                             + q4[i].z * k4[j].z + q4[i].w * k4[j].w;
        }
        const bool diag = (jt == qt);
        #pragma unroll
        for (int i = 0; i < 4; i++)
            #pragma unroll
            for (int j = 0; j < 4; j++) {
                float v = s[i][j] * 0.125f;
                if (diag && (k0 + tx * 4 + j > q0 + ty * 4 + i)) v = NEG;
                Ss[(ty * 4 + i) * APITCH + (tx * 4 + j)] = v;
            }
        __syncthreads();

        if (t < 64) {
            int r = t;
            float mold = rowm[r];
            float tmax = NEG;
            for (int j = 0; j < 64; j++) tmax = fmaxf(tmax, Ss[r * APITCH + j]);
            float mnew = fmaxf(mold, tmax);
            float corr = __expf(mold - mnew);
            float sum = 0.f;
            for (int j = 0; j < 64; j++) {
                float p = __expf(Ss[r * APITCH + j] - mnew);
                Ss[r * APITCH + j] = p;
                sum += p;
            }
            rowl[r] = rowl[r] * corr + sum;
            rowm[r] = mnew;
            rowsc[r] = corr;
        }
        __syncthreads();

        #pragma unroll
        for (int i = 0; i < 4; i++) {
            float c = rowsc[ty * 4 + i];
            #pragma unroll
            for (int j = 0; j < 4; j++) o_acc[i][j] *= c;
        }
        for (int k = 0; k < 64; k++) {
            float4 v4 = *(const float4*)(&Vs[k * APITCH + tx * 4]);
            #pragma unroll
            for (int i = 0; i < 4; i++) {
                float p = Ss[(ty * 4 + i) * APITCH + k];
                o_acc[i][0] += p * v4.x; o_acc[i][1] += p * v4.y;
                o_acc[i][2] += p * v4.z; o_acc[i][3] += p * v4.w;
            }
        }
        __syncthreads();
    }

    #pragma unroll
    for (int i = 0; i < 4; i++) {
        float invl = 1.0f / rowl[ty * 4 + i];
        size_t idx = ((size_t)(b * TT + q0 + ty * 4 + i)) * DD + h * HDD + tx * 4;
        float v0 = o_acc[i][0] * invl, v1 = o_acc[i][1] * invl;
        float v2 = o_acc[i][2] * invl, v3 = o_acc[i][3] * invl;
        __nv_bfloat16 h0 = __float2bfloat16(v0), h1 = __float2bfloat16(v1);
        __nv_bfloat16 h2 = __float2bfloat16(v2), h3 = __float2bfloat16(v3);
        *(ushort4*)(ohi + idx) = make_ushort4(__bfloat16_as_ushort(h0), __bfloat16_as_ushort(h1),
                                              __bfloat16_as_ushort(h2), __bfloat16_as_ushort(h3));
        __nv_bfloat16 l0 = __float2bfloat16(v0 - __bfloat162float(h0));
        __nv_bfloat16 l1 = __float2bfloat16(v1 - __bfloat162float(h1));
        __nv_bfloat16 l2 = __float2bfloat16(v2 - __bfloat162float(h2));
        __nv_bfloat16 l3 = __float2bfloat16(v3 - __bfloat162float(h3));
        *(ushort4*)(olo + idx) = make_ushort4(__bfloat16_as_ushort(l0), __bfloat16_as_ushort(l1),
                                              __bfloat16_as_ushort(l2), __bfloat16_as_ushort(l3));
    }
}

// ================= driver =================
extern "C" void kernel_launch(void* const* d_in, const int* in_sizes, int n_in,
                              void* d_out, int out_size) {
    const int*   x      = (const int*)  d_in[0];
    const float* emb_w  = (const float*)d_in[1];
    const float* n1_w   = (const float*)d_in[2];
    const float* n2_w   = (const float*)d_in[3];
    const float* qkv_w  = (const float*)d_in[4];
    const float* qkv_b  = (const float*)d_in[5];
    const float* o_w    = (const float*)d_in[6];
    const float* o_b    = (const float*)d_in[7];
    const float* gw     = (const float*)d_in[8];
    const float* gb     = (const float*)d_in[9];
    const float* uw     = (const float*)d_in[10];
    const float* ub     = (const float*)d_in[11];
    const float* dnw    = (const float*)d_in[12];
    const float* dnb    = (const float*)d_in[13];
    const float* norm_w = (const float*)d_in[14];
    const float* head_w = (const float*)d_in[15];
    float* out = (float*)d_out;

    float *h_, *qkv_, *ffs_;
    __nv_bfloat16 *wqh, *wql, *woh, *wol, *wgh, *wgl, *wuh, *wul, *wdh, *wdl, *whh, *whl;
    __nv_bfloat16 *nh, *nl, *ath, *atl, *ffh, *ffl;
    cudaGetSymbolAddress((void**)&h_,   g_h);
    cudaGetSymbolAddress((void**)&qkv_, g_qkv);
    cudaGetSymbolAddress((void**)&ffs_, g_ffs);
    cudaGetSymbolAddress((void**)&wqh, g_wqkv_h); cudaGetSymbolAddress((void**)&wql, g_wqkv_l);
    cudaGetSymbolAddress((void**)&woh, g_wo_h);   cudaGetSymbolAddress((void**)&wol, g_wo_l);
    cudaGetSymbolAddress((void**)&wgh, g_wg_h);   cudaGetSymbolAddress((void**)&wgl, g_wg_l);
    cudaGetSymbolAddress((void**)&wuh, g_wu_h);   cudaGetSymbolAddress((void**)&wul, g_wu_l);
    cudaGetSymbolAddress((void**)&wdh, g_wdn_h);  cudaGetSymbolAddress((void**)&wdl, g_wdn_l);
    cudaGetSymbolAddress((void**)&whh, g_whd_h);  cudaGetSymbolAddress((void**)&whl, g_whd_l);
    cudaGetSymbolAddress((void**)&nh,  g_n_h);    cudaGetSymbolAddress((void**)&nl,  g_n_l);
    cudaGetSymbolAddress((void**)&ath, g_at_h);   cudaGetSymbolAddress((void**)&atl, g_at_l);
    cudaGetSymbolAddress((void**)&ffh, g_ff_h);   cudaGetSymbolAddress((void**)&ffl, g_ff_l);

    cudaFuncSetAttribute(gemm_mma, cudaFuncAttributeMaxDynamicSharedMemorySize, GSMEM);
    cudaFuncSetAttribute(attn_kernel, cudaFuncAttributeMaxDynamicSharedMemorySize, ATTN_SMEM);

    // weight splits (inside the graph each replay; ~0.07 ms total)
    split4_kernel<<<2048, 256>>>((const float4*)qkv_w,  wqh, wql, (size_t)NLL*3*DD*DD/4);
    split4_kernel<<<2048, 256>>>((const float4*)o_w,    woh, wol, (size_t)NLL*DD*DD/4);
    split4_kernel<<<2048, 256>>>((const float4*)gw,     wgh, wgl, (size_t)NLL*FFF*DD/4);
    split4_kernel<<<2048, 256>>>((const float4*)uw,     wuh, wul, (size_t)NLL*FFF*DD/4);
    split4_kernel<<<2048, 256>>>((const float4*)dnw,    wdh, wdl, (size_t)NLL*DD*FFF/4);
    split4_kernel<<<2048, 256>>>((const float4*)head_w, whh, whl, (size_t)VV*DD/4);

    embed_kernel<<<MR, 256>>>(x, emb_w, h_);

    for (int l = 0; l < NLL; l++) {
        const size_t oq = (size_t)l * 3 * DD * DD, oo = (size_t)l * DD * DD;
        const size_t of = (size_t)l * FFF * DD;

        rmsnorm_split<<<MR, 256>>>(h_, n1_w + (size_t)l * DD, nh, nl);

        gemm_mma<<<dim3(MR / 128, 3 * DD / 128), 256, GSMEM>>>(
            nh, nl, wqh + oq, wql + oq, qkv_b + (size_t)l * 3 * DD,
            nullptr, qkv_, nullptr, nullptr, 3 * DD, DD, 0);

        attn_kernel<<<dim3(TT / 64, NHH, BB), 256, ATTN_SMEM>>>(qkv_, ath, atl);

        gemm_mma<<<dim3(MR / 128, DD / 128), 256, GSMEM>>>(
            ath, atl, woh + oo, wol + oo, o_b + (size_t)l * DD,
            h_, h_, nullptr, nullptr, DD, DD, 1);

        rmsnorm_split<<<MR, 256>>>(h_, n2_w + (size_t)l * DD, nh, nl);

        gemm_mma<<<dim3(MR / 128, FFF / 128), 256, GSMEM>>>(
            nh, nl, wgh + of, wgl + of, gb + (size_t)l * FFF,
            nullptr, ffs_, nullptr, nullptr, FFF, DD, 2);

        gemm_mma<<<dim3(MR / 128, FFF / 128), 256, GSMEM>>>(
            nh, nl, wuh + of, wul + of, ub + (size_t)l * FFF,
            ffs_, nullptr, ffh, ffl, FFF, DD, 3);

        gemm_mma<<<dim3(MR / 128, DD / 128), 256, GSMEM>>>(
            ffh, ffl, wdh + of, wdl + of, dnb + (size_t)l * DD,
            h_, h_, nullptr, nullptr, DD, FFF, 1);
    }

    rmsnorm_split<<<MR, 256>>>(h_, norm_w, nh, nl);

    gemm_mma<<<dim3(MR / 128, VV / 128), 256, GSMEM>>>(
        nh, nl, whh, whl, nullptr,
        nullptr, out, nullptr, nullptr, VV, DD, 0);
}

// round 7
// speedup vs baseline: 4.2883x; 1.2017x over previous
#include <cuda_runtime.h>
#include <cuda_fp16.h>
#include <math.h>
#include <stdint.h>

// ---------------- problem dims ----------------
#define BB   2
#define TT   2048
#define DD   1024
#define NHH  16
#define HDD  64
#define FFF  4096
#define NLL  2
#define VV   32000
#define MR   (BB*TT)          // 4096 token rows
#define EPSF 1.1920929e-07f

// ---------------- fp32 scratch ----------------
__device__ float g_h  [(size_t)MR*DD];
__device__ float g_qkv[(size_t)MR*3*DD];
__device__ float g_ffs[(size_t)MR*FFF];

// ---------------- fp16 scratch ----------------
// weights: single fp16 copy. activations: hi/lo split (A-side 2-pass).
__device__ __half g_wqkv[(size_t)NLL*3*DD*DD];
__device__ __half g_wo  [(size_t)NLL*DD*DD];
__device__ __half g_wg  [(size_t)NLL*FFF*DD];
__device__ __half g_wu  [(size_t)NLL*FFF*DD];
__device__ __half g_wdn [(size_t)NLL*DD*FFF];
__device__ __half g_whd [(size_t)VV*DD];
__device__ __half g_n_h [(size_t)MR*DD],  g_n_l [(size_t)MR*DD];
__device__ __half g_at_h[(size_t)MR*DD],  g_at_l[(size_t)MR*DD];
__device__ __half g_ff_h[(size_t)MR*FFF], g_ff_l[(size_t)MR*FFF];

// ================= helpers =================
__device__ __forceinline__ uint32_t smem_u32(const void* p) {
    uint32_t a;
    asm("{ .reg .u64 t; cvta.to.shared.u64 t, %1; cvt.u32.u64 %0, t; }" : "=r"(a) : "l"(p));
    return a;
}

// ================= weight convert: float -> fp16 =================
__global__ __launch_bounds__(256) void convert4_kernel(const float4* __restrict__ src,
                                                       __half* __restrict__ dst,
                                                       size_t n4) {
    size_t stride = (size_t)gridDim.x * blockDim.x;
    for (size_t i = (size_t)blockIdx.x * blockDim.x + threadIdx.x; i < n4; i += stride) {
        float4 v = src[i];
        __half hx = __float2half_rn(v.x), hy = __float2half_rn(v.y);
        __half hz = __float2half_rn(v.z), hw = __float2half_rn(v.w);
        ((ushort4*)dst)[i] = make_ushort4(__half_as_ushort(hx), __half_as_ushort(hy),
                                          __half_as_ushort(hz), __half_as_ushort(hw));
    }
}

// ================= embedding =================
__global__ __launch_bounds__(256) void embed_kernel(const int* __restrict__ x,
                                                    const float* __restrict__ emb,
                                                    float* __restrict__ h) {
    int row = blockIdx.x;
    int tok = x[row];
    ((float4*)(h + (size_t)row * DD))[threadIdx.x] =
        ((const float4*)(emb + (size_t)tok * DD))[threadIdx.x];
}

// ================= RMSNorm -> fp16 hi/lo =================
__global__ __launch_bounds__(256) void rmsnorm_split(const float* __restrict__ x,
                                                     const float* __restrict__ w,
                                                     __half* __restrict__ hi,
                                                     __half* __restrict__ lo) {
    int row = blockIdx.x, t = threadIdx.x;
    float4 v = ((const float4*)(x + (size_t)row * DD))[t];
    float ss = v.x*v.x + v.y*v.y + v.z*v.z + v.w*v.w;
    #pragma unroll
    for (int o = 16; o > 0; o >>= 1) ss += __shfl_xor_sync(0xffffffffu, ss, o);
    __shared__ float wsum[8];
    if ((t & 31) == 0) wsum[t >> 5] = ss;
    __syncthreads();
    float tot = 0.f;
    #pragma unroll
    for (int i = 0; i < 8; i++) tot += wsum[i];
    float rs = rsqrtf(tot * (1.0f / (float)DD) + EPSF);
    float4 wv = ((const float4*)w)[t];
    float o0 = v.x * rs * wv.x, o1 = v.y * rs * wv.y;
    float o2 = v.z * rs * wv.z, o3 = v.w * rs * wv.w;
    __half h0 = __float2half_rn(o0), h1 = __float2half_rn(o1);
    __half h2 = __float2half_rn(o2), h3 = __float2half_rn(o3);
    ((ushort4*)(hi + (size_t)row * DD))[t] =
        make_ushort4(__half_as_ushort(h0), __half_as_ushort(h1),
                     __half_as_ushort(h2), __half_as_ushort(h3));
    __half l0 = __float2half_rn(o0 - __half2float(h0));
    __half l1 = __float2half_rn(o1 - __half2float(h1));
    __half l2 = __float2half_rn(o2 - __half2float(h2));
    __half l3 = __float2half_rn(o3 - __half2float(h3));
    ((ushort4*)(lo + (size_t)row * DD))[t] =
        make_ushort4(__half_as_ushort(l0), __half_as_ushort(l1),
                     __half_as_ushort(l2), __half_as_ushort(l3));
}

// ================= HMMA GEMM, fp16 2-pass (A hi/lo split, W single) =============
// C[M=4096, N] = epi( (Ahi+Alo)[M,K] @ W[N,K]^T + bias )
// Per 32-wide k-chunk, per s half-chunk: B<-W once; A<-Ahi: 16 mma; A<-Alo: 16 mma.
// CTA tile 128x128, 8 warps (2m x 4n), warp tile 64x32, 3-stage cp.async (24KB/stage).
// epi: 0 fp32 out; 1 fp32 out + aux; 2 silu fp32 out; 3 (acc+bias)*aux -> fp16 hi/lo.
#define GSMEM (3 * 24576)

#define MMA16(accfg, A, B0, B1) \
    asm volatile("mma.sync.aligned.m16n8k16.row.col.f32.f16.f16.f32 " \
        "{%0,%1,%2,%3}, {%4,%5,%6,%7}, {%8,%9}, {%0,%1,%2,%3};" \
        : "+f"((accfg)[0]), "+f"((accfg)[1]), "+f"((accfg)[2]), "+f"((accfg)[3]) \
        : "r"((A)[0]), "r"((A)[1]), "r"((A)[2]), "r"((A)[3]), "r"(B0), "r"(B1))

__global__ __launch_bounds__(256, 2) void gemm_mma(
    const __half* __restrict__ ahi, const __half* __restrict__ alo,
    const __half* __restrict__ w,
    const float* __restrict__ bias, const float* __restrict__ aux,
    float* outf, __half* ohi, __half* olo,
    int N, int K, int epi)
{
    extern __shared__ __align__(1024) char smem[];
    const int tid = threadIdx.x;
    const int wid = tid >> 5, lane = tid & 31;
    const int mt = blockIdx.x, nt = blockIdx.y;
    const int warp_m = wid >> 2, warp_n = wid & 3;
    const uint32_t sbase = smem_u32(smem);

    float acc[4][4][4];
    #pragma unroll
    for (int f = 0; f < 4; f++)
        #pragma unroll
        for (int g = 0; g < 4; g++)
            #pragma unroll
            for (int e = 0; e < 4; e++) acc[f][g][e] = 0.f;

    const int nc = K >> 5;

    // tiles per 24KB stage: Ahi @0, Alo @8K, W @16K
    auto prefetch = [&](int kc, int b) {
        const size_t koff = (size_t)kc << 5;
        const uint32_t bufo = sbase + (uint32_t)b * 24576u;
        const __half* bases[3] = {
            ahi + ((size_t)mt * 128) * K + koff,
            alo + ((size_t)mt * 128) * K + koff,
            w   + ((size_t)nt * 128) * K + koff };
        #pragma unroll
        for (int rep = 0; rep < 6; ++rep) {
            const int idx = tid + 256 * rep;          // 0..1535
            const int tile = idx >> 9;                // 0..2
            const int r  = (idx >> 2) & 127;
            const int c4 = idx & 3;
            const __half* g = bases[tile] + (size_t)r * K + c4 * 8;
            const uint32_t dst = bufo + (uint32_t)tile * 8192u
                               + (uint32_t)(r * 64 + ((c4 ^ ((r >> 1) & 3)) << 4));
            asm volatile("cp.async.cg.shared.global [%0], [%1], 16;" :: "r"(dst), "l"(g));
        }
        asm volatile("cp.async.commit_group;" ::: "memory");
    };

    prefetch(0, 0);
    if (nc > 1) prefetch(1, 1);
    for (int c = 0; c < nc; ++c) {
        if (c + 2 < nc) {
            prefetch(c + 2, (c + 2) % 3);
            asm volatile("cp.async.wait_group 2;" ::: "memory");
        } else if (c + 1 < nc) {
            asm volatile("cp.async.wait_group 1;" ::: "memory");
        } else {
            asm volatile("cp.async.wait_group 0;" ::: "memory");
        }
        __syncthreads();

        const uint32_t buf = sbase + (uint32_t)(c % 3) * 24576u;
        const uint32_t a_hi_b = buf, a_lo_b = buf + 8192u, b_b = buf + 16384u;

        #pragma unroll
        for (int s = 0; s < 2; ++s) {
            const int arow = warp_m * 64 + (lane & 15);
            const int ach  = s * 2 + (lane >> 4);
            const int brow = warp_n * 32 + (lane & 7);
            const int bch  = s * 2 + ((lane >> 3) & 1);
            uint32_t aoff[4], boff[4];
            #pragma unroll
            for (int f = 0; f < 4; ++f) {
                const int row = arow + f * 16;
                aoff[f] = row * 64 + ((ach ^ ((row >> 1) & 3)) << 4);
            }
            #pragma unroll
            for (int g = 0; g < 4; ++g) {
                const int row = brow + g * 8;
                boff[g] = row * 64 + ((bch ^ ((row >> 1) & 3)) << 4);
            }

            uint32_t A[4][4], Bv[4][2];
            // B <- W (loaded once per s, reused by both passes)
            #pragma unroll
            for (int g = 0; g < 4; ++g)
                asm volatile("ldmatrix.sync.aligned.m8n8.x2.shared.b16 {%0,%1}, [%2];"
                    : "=r"(Bv[g][0]), "=r"(Bv[g][1]) : "r"(b_b + boff[g]));
            // pass 1: A <- Ahi
            #pragma unroll
            for (int f = 0; f < 4; ++f)
                asm volatile("ldmatrix.sync.aligned.m8n8.x4.shared.b16 {%0,%1,%2,%3}, [%4];"
                    : "=r"(A[f][0]), "=r"(A[f][1]), "=r"(A[f][2]), "=r"(A[f][3])
                    : "r"(a_hi_b + aoff[f]));
            #pragma unroll
            for (int f = 0; f < 4; ++f)
                #pragma unroll
                for (int g = 0; g < 4; ++g)
                    MMA16(acc[f][g], A[f], Bv[g][0], Bv[g][1]);
            // pass 2: A <- Alo
            #pragma unroll
            for (int f = 0; f < 4; ++f)
                asm volatile("ldmatrix.sync.aligned.m8n8.x4.shared.b16 {%0,%1,%2,%3}, [%4];"
                    : "=r"(A[f][0]), "=r"(A[f][1]), "=r"(A[f][2]), "=r"(A[f][3])
                    : "r"(a_lo_b + aoff[f]));
            #pragma unroll
            for (int f = 0; f < 4; ++f)
                #pragma unroll
                for (int g = 0; g < 4; ++g)
                    MMA16(acc[f][g], A[f], Bv[g][0], Bv[g][1]);
        }
        __syncthreads();
    }

    // ---- epilogue ----
    const int r_in = lane >> 2, c_in = (lane & 3) * 2;
    #pragma unroll
    for (int f = 0; f < 4; ++f) {
        #pragma unroll
        for (int rr = 0; rr < 2; ++rr) {
            const size_t m = (size_t)mt * 128 + warp_m * 64 + f * 16 + rr * 8 + r_in;
            float* frow = outf ? outf + m * (size_t)N : (float*)0;
            const float* arow = aux ? aux + m * (size_t)N : (const float*)0;
            #pragma unroll
            for (int g = 0; g < 4; ++g) {
                const int n = nt * 128 + warp_n * 32 + g * 8 + c_in;
                float x = acc[f][g][rr * 2 + 0];
                float y = acc[f][g][rr * 2 + 1];
                if (bias) { x += bias[n]; y += bias[n + 1]; }
                if (epi == 1) {
                    x += arow[n]; y += arow[n + 1];
                    frow[n] = x; frow[n + 1] = y;
                } else if (epi == 2) {
                    x = x / (1.f + expf(-x)); y = y / (1.f + expf(-y));
                    frow[n] = x; frow[n + 1] = y;
                } else if (epi == 3) {
                    x *= arow[n]; y *= arow[n + 1];
                    __half hx = __float2half_rn(x), hy = __float2half_rn(y);
                    *(ushort2*)(ohi + m * (size_t)N + n) =
                        make_ushort2(__half_as_ushort(hx), __half_as_ushort(hy));
                    __half lx = __float2half_rn(x - __half2float(hx));
                    __half ly = __float2half_rn(y - __half2float(hy));
                    *(ushort2*)(olo + m * (size_t)N + n) =
                        make_ushort2(__half_as_ushort(lx), __half_as_ushort(ly));
                } else {
                    frow[n] = x; frow[n + 1] = y;
                }
            }
        }
    }
}

// ================= flash attention (fp32, causal), HD=64, out -> fp16 hi/lo ======
#define APITCH 68
#define ATTN_SMEM ((4 * 64 * APITCH + 3 * 64) * (int)sizeof(float))

__global__ __launch_bounds__(256) void attn_kernel(const float* __restrict__ qkv,
                                                   __half* __restrict__ ohi,
                                                   __half* __restrict__ olo) {
    extern __shared__ float sm[];
    float* Qs = sm;
    float* Ks = Qs + 64 * APITCH;
    float* Vs = Ks + 64 * APITCH;
    float* Ss = Vs + 64 * APITCH;
    float* rowm = Ss + 64 * APITCH;
    float* rowl = rowm + 64;
    float* rowsc = rowl + 64;

    const int t = threadIdx.x;
    const int qt = blockIdx.x, h = blockIdx.y, b = blockIdx.z;
    const int q0 = qt * 64;
    const int tx = t & 15, ty = t >> 4;
    const float NEG = -1e30f;

    for (int i = t; i < 64 * 16; i += 256) {
        int row = i >> 4, c4 = i & 15;
        *(float4*)(&Qs[row * APITCH + c4 * 4]) =
            *(const float4*)(qkv + ((size_t)(b * TT + q0 + row)) * (3 * DD) + h * HDD + c4 * 4);
    }
    if (t < 64) { rowm[t] = NEG; rowl[t] = 0.f; }

    float o_acc[4][4];
    #pragma unroll
    for (int i = 0; i < 4; i++)
        #pragma unroll
        for (int j = 0; j < 4; j++) o_acc[i][j] = 0.f;

    for (int jt = 0; jt <= qt; jt++) {
        const int k0 = jt * 64;
        for (int i = t; i < 64 * 16; i += 256) {
            int row = i >> 4, c4 = i & 15;
            size_t base = ((size_t)(b * TT + k0 + row)) * (3 * DD) + h * HDD + c4 * 4;
            *(float4*)(&Ks[row * APITCH + c4 * 4]) = *(const float4*)(qkv + base + DD);
            *(float4*)(&Vs[row * APITCH + c4 * 4]) = *(const float4*)(qkv + base + 2 * DD);
        }
        __syncthreads();

        float s[4][4];
        #pragma unroll
        for (int i = 0; i < 4; i++)
            #pragma unroll
            for (int j = 0; j < 4; j++) s[i][j] = 0.f;
        #pragma unroll 4
        for (int d4 = 0; d4 < 16; d4++) {
            float4 q4[4], k4[4];
            #pragma unroll
            for (int i = 0; i < 4; i++) q4[i] = *(const float4*)(&Qs[(ty * 4 + i) * APITCH + d4 * 4]);
            #pragma unroll
            for (int j = 0; j < 4; j++) k4[j] = *(const float4*)(&Ks[(tx * 4 + j) * APITCH + d4 * 4]);
            #pragma unroll
            for (int i = 0; i < 4; i++)
                #pragma unroll
                for (int j = 0; j < 4; j++)
                    s[i][j] += q4[i].x * k4[j].x + q4[i].y * k4[j].y
                             + q4[i].z * k4[j].z + q4[i].w * k4[j].w;
        }
        const bool diag = (jt == qt);
        #pragma unroll
        for (int i = 0; i < 4; i++)
            #pragma unroll
            for (int j = 0; j < 4; j++) {
                float v = s[i][j] * 0.125f;
                if (diag && (k0 + tx * 4 + j > q0 + ty * 4 + i)) v = NEG;
                Ss[(ty * 4 + i) * APITCH + (tx * 4 + j)] = v;
            }
        __syncthreads();

        if (t < 64) {
            int r = t;
            float mold = rowm[r];
            float tmax = NEG;
            for (int j = 0; j < 64; j++) tmax = fmaxf(tmax, Ss[r * APITCH + j]);
            float mnew = fmaxf(mold, tmax);
            float corr = __expf(mold - mnew);
            float sum = 0.f;
            for (int j = 0; j < 64; j++) {
                float p = __expf(Ss[r * APITCH + j] - mnew);
                Ss[r * APITCH + j] = p;
                sum += p;
            }
            rowl[r] = rowl[r] * corr + sum;
            rowm[r] = mnew;
            rowsc[r] = corr;
        }
        __syncthreads();

        #pragma unroll
        for (int i = 0; i < 4; i++) {
            float c = rowsc[ty * 4 + i];
            #pragma unroll
            for (int j = 0; j < 4; j++) o_acc[i][j] *= c;
        }
        for (int k = 0; k < 64; k++) {
            float4 v4 = *(const float4*)(&Vs[k * APITCH + tx * 4]);
            #pragma unroll
            for (int i = 0; i < 4; i++) {
                float p = Ss[(ty * 4 + i) * APITCH + k];
                o_acc[i][0] += p * v4.x; o_acc[i][1] += p * v4.y;
                o_acc[i][2] += p * v4.z; o_acc[i][3] += p * v4.w;
            }
        }
        __syncthreads();
    }

    #pragma unroll
    for (int i = 0; i < 4; i++) {
        float invl = 1.0f / rowl[ty * 4 + i];
        size_t idx = ((size_t)(b * TT + q0 + ty * 4 + i)) * DD + h * HDD + tx * 4;
        float v0 = o_acc[i][0] * invl, v1 = o_acc[i][1] * invl;
        float v2 = o_acc[i][2] * invl, v3 = o_acc[i][3] * invl;
        __half h0 = __float2half_rn(v0), h1 = __float2half_rn(v1);
        __half h2 = __float2half_rn(v2), h3 = __float2half_rn(v3);
        *(ushort4*)(ohi + idx) = make_ushort4(__half_as_ushort(h0), __half_as_ushort(h1),
                                              __half_as_ushort(h2), __half_as_ushort(h3));
        __half l0 = __float2half_rn(v0 - __half2float(h0));
        __half l1 = __float2half_rn(v1 - __half2float(h1));
        __half l2 = __float2half_rn(v2 - __half2float(h2));
        __half l3 = __float2half_rn(v3 - __half2float(h3));
        *(ushort4*)(olo + idx) = make_ushort4(__half_as_ushort(l0), __half_as_ushort(l1),
                                              __half_as_ushort(l2), __half_as_ushort(l3));
    }
}

// ================= driver =================
extern "C" void kernel_launch(void* const* d_in, const int* in_sizes, int n_in,
                              void* d_out, int out_size) {
    const int*   x      = (const int*)  d_in[0];
    const float* emb_w  = (const float*)d_in[1];
    const float* n1_w   = (const float*)d_in[2];
    const float* n2_w   = (const float*)d_in[3];
    const float* qkv_w  = (const float*)d_in[4];
    const float* qkv_b  = (const float*)d_in[5];
    const float* o_w    = (const float*)d_in[6];
    const float* o_b    = (const float*)d_in[7];
    const float* gw     = (const float*)d_in[8];
    const float* gb     = (const float*)d_in[9];
    const float* uw     = (const float*)d_in[10];
    const float* ub     = (const float*)d_in[11];
    const float* dnw    = (const float*)d_in[12];
    const float* dnb    = (const float*)d_in[13];
    const float* norm_w = (const float*)d_in[14];
    const float* head_w = (const float*)d_in[15];
    float* out = (float*)d_out;

    float *h_, *qkv_, *ffs_;
    __half *wq, *wo, *wg, *wu, *wd, *wh;
    __half *nh, *nl, *ath, *atl, *ffh, *ffl;
    cudaGetSymbolAddress((void**)&h_,   g_h);
    cudaGetSymbolAddress((void**)&qkv_, g_qkv);
    cudaGetSymbolAddress((void**)&ffs_, g_ffs);
    cudaGetSymbolAddress((void**)&wq, g_wqkv);
    cudaGetSymbolAddress((void**)&wo, g_wo);
    cudaGetSymbolAddress((void**)&wg, g_wg);
    cudaGetSymbolAddress((void**)&wu, g_wu);
    cudaGetSymbolAddress((void**)&wd, g_wdn);
    cudaGetSymbolAddress((void**)&wh, g_whd);
    cudaGetSymbolAddress((void**)&nh,  g_n_h);  cudaGetSymbolAddress((void**)&nl,  g_n_l);
    cudaGetSymbolAddress((void**)&ath, g_at_h); cudaGetSymbolAddress((void**)&atl, g_at_l);
    cudaGetSymbolAddress((void**)&ffh, g_ff_h); cudaGetSymbolAddress((void**)&ffl, g_ff_l);

    cudaFuncSetAttribute(gemm_mma, cudaFuncAttributeMaxDynamicSharedMemorySize, GSMEM);
    cudaFuncSetAttribute(attn_kernel, cudaFuncAttributeMaxDynamicSharedMemorySize, ATTN_SMEM);

    // Launch order arranged so ncu (-s 5 -c 1) captures gemm_mma (launch index 5).
    embed_kernel<<<MR, 256>>>(x, emb_w, h_);                                         // 0
    convert4_kernel<<<2048, 256>>>((const float4*)qkv_w,  wq, (size_t)NLL*3*DD*DD/4); // 1
    rmsnorm_split<<<MR, 256>>>(h_, n1_w, nh, nl);                                    // 2
    convert4_kernel<<<2048, 256>>>((const float4*)gw,     wg, (size_t)NLL*FFF*DD/4);  // 3
    convert4_kernel<<<2048, 256>>>((const float4*)uw,     wu, (size_t)NLL*FFF*DD/4);  // 4

    for (int l = 0; l < NLL; l++) {
        const size_t oq = (size_t)l * 3 * DD * DD, oo = (size_t)l * DD * DD;
        const size_t of = (size_t)l * FFF * DD;

        if (l > 0) rmsnorm_split<<<MR, 256>>>(h_, n1_w + (size_t)l * DD, nh, nl);

        gemm_mma<<<dim3(MR / 128, 3 * DD / 128), 256, GSMEM>>>(                      // 5 on l=0
            nh, nl, wq + oq, qkv_b + (size_t)l * 3 * DD,
            nullptr, qkv_, nullptr, nullptr, 3 * DD, DD, 0);

        attn_kernel<<<dim3(TT / 64, NHH, BB), 256, ATTN_SMEM>>>(qkv_, ath, atl);

        if (l == 0) convert4_kernel<<<2048, 256>>>((const float4*)o_w, wo, (size_t)NLL*DD*DD/4);

        gemm_mma<<<dim3(MR / 128, DD / 128), 256, GSMEM>>>(
            ath, atl, wo + oo, o_b + (size_t)l * DD,
            h_, h_, nullptr, nullptr, DD, DD, 1);

        rmsnorm_split<<<MR, 256>>>(h_, n2_w + (size_t)l * DD, nh, nl);

        gemm_mma<<<dim3(MR / 128, FFF / 128), 256, GSMEM>>>(
            nh, nl, wg + of, gb + (size_t)l * FFF,
            nullptr, ffs_, nullptr, nullptr, FFF, DD, 2);

        gemm_mma<<<dim3(MR / 128, FFF / 128), 256, GSMEM>>>(
            nh, nl, wu + of, ub + (size_t)l * FFF,
            ffs_, nullptr, ffh, ffl, FFF, DD, 3);

        if (l == 0) convert4_kernel<<<2048, 256>>>((const float4*)dnw, wd, (size_t)NLL*DD*FFF/4);

        gemm_mma<<<dim3(MR / 128, DD / 128), 256, GSMEM>>>(
            ffh, ffl, wd + of, dnb + (size_t)l * DD,
            h_, h_, nullptr, nullptr, DD, FFF, 1);

        if (l == 0) convert4_kernel<<<2048, 256>>>((const float4*)head_w, wh, (size_t)VV*DD/4);
    }

    rmsnorm_split<<<MR, 256>>>(h_, norm_w, nh, nl);

    gemm_mma<<<dim3(MR / 128, VV / 128), 256, GSMEM>>>(
        nh, nl, wh, nullptr,
        nullptr, out, nullptr, nullptr, VV, DD, 0);
}

// round 8
// speedup vs baseline: 6.1180x; 1.4267x over previous
#include <cuda_runtime.h>
#include <cuda_fp16.h>
#include <math.h>
#include <stdint.h>

// ---------------- problem dims ----------------
#define BB   2
#define TT   2048
#define DD   1024
#define NHH  16
#define HDD  64
#define FFF  4096
#define NLL  2
#define VV   32000
#define MR   (BB*TT)          // 4096 token rows
#define EPSF 1.1920929e-07f

// ---------------- fp32 scratch ----------------
__device__ float g_h  [(size_t)MR*DD];
__device__ float g_qkv[(size_t)MR*3*DD];
__device__ float g_ffs[(size_t)MR*FFF];

// ---------------- fp16 scratch ----------------
__device__ __half g_wqkv[(size_t)NLL*3*DD*DD];
__device__ __half g_wo  [(size_t)NLL*DD*DD];
__device__ __half g_wg  [(size_t)NLL*FFF*DD];
__device__ __half g_wu  [(size_t)NLL*FFF*DD];
__device__ __half g_wdn [(size_t)NLL*DD*FFF];
__device__ __half g_whd [(size_t)VV*DD];
__device__ __half g_n_h [(size_t)MR*DD],  g_n_l [(size_t)MR*DD];
__device__ __half g_at_h[(size_t)MR*DD],  g_at_l[(size_t)MR*DD];
__device__ __half g_ff_h[(size_t)MR*FFF], g_ff_l[(size_t)MR*FFF];

// ================= helpers =================
__device__ __forceinline__ uint32_t smem_u32(const void* p) {
    uint32_t a;
    asm("{ .reg .u64 t; cvta.to.shared.u64 t, %1; cvt.u32.u64 %0, t; }" : "=r"(a) : "l"(p));
    return a;
}
__device__ __forceinline__ uint32_t packh2(float lo, float hi) {
    uint32_t r;
    asm("cvt.rn.f16x2.f32 %0, %1, %2;" : "=r"(r) : "f"(hi), "f"(lo));
    return r;
}

#define MMA16(accfg, A, B0, B1) \
    asm volatile("mma.sync.aligned.m16n8k16.row.col.f32.f16.f16.f32 " \
        "{%0,%1,%2,%3}, {%4,%5,%6,%7}, {%8,%9}, {%0,%1,%2,%3};" \
        : "+f"((accfg)[0]), "+f"((accfg)[1]), "+f"((accfg)[2]), "+f"((accfg)[3]) \
        : "r"((A)[0]), "r"((A)[1]), "r"((A)[2]), "r"((A)[3]), "r"(B0), "r"(B1))

// ================= weight convert: float -> fp16 =================
__global__ __launch_bounds__(256) void convert4_kernel(const float4* __restrict__ src,
                                                       __half* __restrict__ dst,
                                                       size_t n4) {
    size_t stride = (size_t)gridDim.x * blockDim.x;
    for (size_t i = (size_t)blockIdx.x * blockDim.x + threadIdx.x; i < n4; i += stride) {
        float4 v = src[i];
        __half hx = __float2half_rn(v.x), hy = __float2half_rn(v.y);
        __half hz = __float2half_rn(v.z), hw = __float2half_rn(v.w);
        ((ushort4*)dst)[i] = make_ushort4(__half_as_ushort(hx), __half_as_ushort(hy),
                                          __half_as_ushort(hz), __half_as_ushort(hw));
    }
}

// ================= embedding =================
__global__ __launch_bounds__(256) void embed_kernel(const int* __restrict__ x,
                                                    const float* __restrict__ emb,
                                                    float* __restrict__ h) {
    int row = blockIdx.x;
    int tok = x[row];
    ((float4*)(h + (size_t)row * DD))[threadIdx.x] =
        ((const float4*)(emb + (size_t)tok * DD))[threadIdx.x];
}

// ================= RMSNorm -> fp16 hi/lo =================
__global__ __launch_bounds__(256) void rmsnorm_split(const float* __restrict__ x,
                                                     const float* __restrict__ w,
                                                     __half* __restrict__ hi,
                                                     __half* __restrict__ lo) {
    int row = blockIdx.x, t = threadIdx.x;
    float4 v = ((const float4*)(x + (size_t)row * DD))[t];
    float ss = v.x*v.x + v.y*v.y + v.z*v.z + v.w*v.w;
    #pragma unroll
    for (int o = 16; o > 0; o >>= 1) ss += __shfl_xor_sync(0xffffffffu, ss, o);
    __shared__ float wsum[8];
    if ((t & 31) == 0) wsum[t >> 5] = ss;
    __syncthreads();
    float tot = 0.f;
    #pragma unroll
    for (int i = 0; i < 8; i++) tot += wsum[i];
    float rs = rsqrtf(tot * (1.0f / (float)DD) + EPSF);
    float4 wv = ((const float4*)w)[t];
    float o0 = v.x * rs * wv.x, o1 = v.y * rs * wv.y;
    float o2 = v.z * rs * wv.z, o3 = v.w * rs * wv.w;
    __half h0 = __float2half_rn(o0), h1 = __float2half_rn(o1);
    __half h2 = __float2half_rn(o2), h3 = __float2half_rn(o3);
    ((ushort4*)(hi + (size_t)row * DD))[t] =
        make_ushort4(__half_as_ushort(h0), __half_as_ushort(h1),
                     __half_as_ushort(h2), __half_as_ushort(h3));
    __half l0 = __float2half_rn(o0 - __half2float(h0));
    __half l1 = __float2half_rn(o1 - __half2float(h1));
    __half l2 = __float2half_rn(o2 - __half2float(h2));
    __half l3 = __float2half_rn(o3 - __half2float(h3));
    ((ushort4*)(lo + (size_t)row * DD))[t] =
        make_ushort4(__half_as_ushort(l0), __half_as_ushort(l1),
                     __half_as_ushort(l2), __half_as_ushort(l3));
}

// ================= HMMA GEMM, fp16 2-pass (A hi/lo split, W single) =============
#define GSMEM (3 * 24576)

__global__ __launch_bounds__(256, 2) void gemm_mma(
    const __half* __restrict__ ahi, const __half* __restrict__ alo,
    const __half* __restrict__ w,
    const float* __restrict__ bias, const float* __restrict__ aux,
    float* outf, __half* ohi, __half* olo,
    int N, int K, int epi)
{
    extern __shared__ __align__(1024) char smem[];
    const int tid = threadIdx.x;
    const int wid = tid >> 5, lane = tid & 31;
    const int mt = blockIdx.x, nt = blockIdx.y;
    const int warp_m = wid >> 2, warp_n = wid & 3;
    const uint32_t sbase = smem_u32(smem);

    float acc[4][4][4];
    #pragma unroll
    for (int f = 0; f < 4; f++)
        #pragma unroll
        for (int g = 0; g < 4; g++)
            #pragma unroll
            for (int e = 0; e < 4; e++) acc[f][g][e] = 0.f;

    const int nc = K >> 5;

    auto prefetch = [&](int kc, int b) {
        const size_t koff = (size_t)kc << 5;
        const uint32_t bufo = sbase + (uint32_t)b * 24576u;
        const __half* bases[3] = {
            ahi + ((size_t)mt * 128) * K + koff,
            alo + ((size_t)mt * 128) * K + koff,
            w   + ((size_t)nt * 128) * K + koff };
        #pragma unroll
        for (int rep = 0; rep < 6; ++rep) {
            const int idx = tid + 256 * rep;
            const int tile = idx >> 9;
            const int r  = (idx >> 2) & 127;
            const int c4 = idx & 3;
            const __half* g = bases[tile] + (size_t)r * K + c4 * 8;
            const uint32_t dst = bufo + (uint32_t)tile * 8192u
                               + (uint32_t)(r * 64 + ((c4 ^ ((r >> 1) & 3)) << 4));
            asm volatile("cp.async.cg.shared.global [%0], [%1], 16;" :: "r"(dst), "l"(g));
        }
        asm volatile("cp.async.commit_group;" ::: "memory");
    };

    prefetch(0, 0);
    if (nc > 1) prefetch(1, 1);
    for (int c = 0; c < nc; ++c) {
        if (c + 2 < nc) {
            prefetch(c + 2, (c + 2) % 3);
            asm volatile("cp.async.wait_group 2;" ::: "memory");
        } else if (c + 1 < nc) {
            asm volatile("cp.async.wait_group 1;" ::: "memory");
        } else {
            asm volatile("cp.async.wait_group 0;" ::: "memory");
        }
        __syncthreads();

        const uint32_t buf = sbase + (uint32_t)(c % 3) * 24576u;
        const uint32_t a_hi_b = buf, a_lo_b = buf + 8192u, b_b = buf + 16384u;

        #pragma unroll
        for (int s = 0; s < 2; ++s) {
            const int arow = warp_m * 64 + (lane & 15);
            const int ach  = s * 2 + (lane >> 4);
            const int brow = warp_n * 32 + (lane & 7);
            const int bch  = s * 2 + ((lane >> 3) & 1);
            uint32_t aoff[4], boff[4];
            #pragma unroll
            for (int f = 0; f < 4; ++f) {
                const int row = arow + f * 16;
                aoff[f] = row * 64 + ((ach ^ ((row >> 1) & 3)) << 4);
            }
            #pragma unroll
            for (int g = 0; g < 4; ++g) {
                const int row = brow + g * 8;
                boff[g] = row * 64 + ((bch ^ ((row >> 1) & 3)) << 4);
            }

            uint32_t A[4][4], Bv[4][2];
            #pragma unroll
            for (int g = 0; g < 4; ++g)
                asm volatile("ldmatrix.sync.aligned.m8n8.x2.shared.b16 {%0,%1}, [%2];"
                    : "=r"(Bv[g][0]), "=r"(Bv[g][1]) : "r"(b_b + boff[g]));
            #pragma unroll
            for (int f = 0; f < 4; ++f)
                asm volatile("ldmatrix.sync.aligned.m8n8.x4.shared.b16 {%0,%1,%2,%3}, [%4];"
                    : "=r"(A[f][0]), "=r"(A[f][1]), "=r"(A[f][2]), "=r"(A[f][3])
                    : "r"(a_hi_b + aoff[f]));
            #pragma unroll
            for (int f = 0; f < 4; ++f)
                #pragma unroll
                for (int g = 0; g < 4; ++g)
                    MMA16(acc[f][g], A[f], Bv[g][0], Bv[g][1]);
            #pragma unroll
            for (int f = 0; f < 4; ++f)
                asm volatile("ldmatrix.sync.aligned.m8n8.x4.shared.b16 {%0,%1,%2,%3}, [%4];"
                    : "=r"(A[f][0]), "=r"(A[f][1]), "=r"(A[f][2]), "=r"(A[f][3])
                    : "r"(a_lo_b + aoff[f]));
            #pragma unroll
            for (int f = 0; f < 4; ++f)
                #pragma unroll
                for (int g = 0; g < 4; ++g)
                    MMA16(acc[f][g], A[f], Bv[g][0], Bv[g][1]);
        }
        __syncthreads();
    }

    // ---- epilogue ----
    const int r_in = lane >> 2, c_in = (lane & 3) * 2;
    #pragma unroll
    for (int f = 0; f < 4; ++f) {
        #pragma unroll
        for (int rr = 0; rr < 2; ++rr) {
            const size_t m = (size_t)mt * 128 + warp_m * 64 + f * 16 + rr * 8 + r_in;
            float* frow = outf ? outf + m * (size_t)N : (float*)0;
            const float* arow = aux ? aux + m * (size_t)N : (const float*)0;
            #pragma unroll
            for (int g = 0; g < 4; ++g) {
                const int n = nt * 128 + warp_n * 32 + g * 8 + c_in;
                float x = acc[f][g][rr * 2 + 0];
                float y = acc[f][g][rr * 2 + 1];
                if (bias) { x += bias[n]; y += bias[n + 1]; }
                if (epi == 1) {
                    x += arow[n]; y += arow[n + 1];
                    frow[n] = x; frow[n + 1] = y;
                } else if (epi == 2) {
                    x = x / (1.f + expf(-x)); y = y / (1.f + expf(-y));
                    frow[n] = x; frow[n + 1] = y;
                } else if (epi == 3) {
                    x *= arow[n]; y *= arow[n + 1];
                    __half hx = __float2half_rn(x), hy = __float2half_rn(y);
                    *(ushort2*)(ohi + m * (size_t)N + n) =
                        make_ushort2(__half_as_ushort(hx), __half_as_ushort(hy));
                    __half lx = __float2half_rn(x - __half2float(hx));
                    __half ly = __float2half_rn(y - __half2float(hy));
                    *(ushort2*)(olo + m * (size_t)N + n) =
                        make_ushort2(__half_as_ushort(lx), __half_as_ushort(ly));
                } else {
                    frow[n] = x; frow[n + 1] = y;
                }
            }
        }
    }
}

// ================= HMMA flash attention (causal), HD=64 =================
// 128 threads (4 warps). q-tile 64, kv-tile 64. Warp w owns q rows [16w,16w+16).
// Q split hi/lo (2-pass S), K single fp16, P fp16, V split hi/lo (2-pass PV).
// smem fp16 tiles [64 x 64], 128B rows, chunk swizzle c8 ^ (r&7).
__global__ __launch_bounds__(128) void attn_mma(const float* __restrict__ qkv,
                                                __half* __restrict__ ohi,
                                                __half* __restrict__ olo) {
    __shared__ __align__(128) __half sQh[64*64], sQl[64*64], sK[64*64],
                                     sVh[64*64], sVl[64*64];
    const int tid = threadIdx.x, lane = tid & 31, w = tid >> 5;
    const int qt = blockIdx.x, h = blockIdx.y, b = blockIdx.z;
    const int q0 = qt * 64;
    const uint32_t bQh = smem_u32(sQh), bQl = smem_u32(sQl), bK = smem_u32(sK);
    const uint32_t bVh = smem_u32(sVh), bVl = smem_u32(sVl);

    // load Q tile -> hi/lo fp16, swizzled (512 chunks, 4 per thread)
    #pragma unroll
    for (int i = 0; i < 4; i++) {
        const int idx = tid + 128 * i;
        const int r = idx >> 3, c8 = idx & 7;
        const float* src = qkv + ((size_t)(b * TT + q0 + r)) * (3 * DD) + h * HDD + c8 * 8;
        const uint32_t off = (uint32_t)(r * 128 + ((c8 ^ (r & 7)) << 4));
        __half hh[8], ll[8];
        #pragma unroll
        for (int e = 0; e < 8; e++) {
            float v = src[e];
            hh[e] = __float2half_rn(v);
            ll[e] = __float2half_rn(v - __half2float(hh[e]));
        }
        *(uint4*)((char*)sQh + off) = *(uint4*)hh;
        *(uint4*)((char*)sQl + off) = *(uint4*)ll;
    }

    float m_a = -1e30f, m_b = -1e30f, l_a = 0.f, l_b = 0.f;
    float o[8][4];
    #pragma unroll
    for (int n = 0; n < 8; n++)
        #pragma unroll
        for (int e = 0; e < 4; e++) o[n][e] = 0.f;

    for (int jt = 0; jt <= qt; jt++) {
        const int k0 = jt * 64;
        // load K (single) and V (hi/lo)
        #pragma unroll
        for (int i = 0; i < 4; i++) {
            const int idx = tid + 128 * i;
            const int r = idx >> 3, c8 = idx & 7;
            const size_t base = ((size_t)(b * TT + k0 + r)) * (3 * DD) + h * HDD + c8 * 8;
            const uint32_t off = (uint32_t)(r * 128 + ((c8 ^ (r & 7)) << 4));
            __half kk[8], vh[8], vl[8];
            #pragma unroll
            for (int e = 0; e < 8; e++) {
                kk[e] = __float2half_rn(qkv[base + DD + e]);
                float v = qkv[base + 2 * DD + e];
                vh[e] = __float2half_rn(v);
                vl[e] = __float2half_rn(v - __half2float(vh[e]));
            }
            *(uint4*)((char*)sK  + off) = *(uint4*)kk;
            *(uint4*)((char*)sVh + off) = *(uint4*)vh;
            *(uint4*)((char*)sVl + off) = *(uint4*)vl;
        }
        __syncthreads();

        // ---- S = Q K^T (2-pass on Q) ----
        float s[8][4];
        #pragma unroll
        for (int n = 0; n < 8; n++)
            #pragma unroll
            for (int e = 0; e < 4; e++) s[n][e] = 0.f;

        #pragma unroll
        for (int t = 0; t < 4; t++) {
            const int ar = w * 16 + (lane & 15);
            const uint32_t aoff = (uint32_t)(ar * 128 + (((t * 2 + (lane >> 4)) ^ (ar & 7)) << 4));
            uint32_t Ah[4], Al[4];
            asm volatile("ldmatrix.sync.aligned.m8n8.x4.shared.b16 {%0,%1,%2,%3}, [%4];"
                : "=r"(Ah[0]), "=r"(Ah[1]), "=r"(Ah[2]), "=r"(Ah[3]) : "r"(bQh + aoff));
            asm volatile("ldmatrix.sync.aligned.m8n8.x4.shared.b16 {%0,%1,%2,%3}, [%4];"
                : "=r"(Al[0]), "=r"(Al[1]), "=r"(Al[2]), "=r"(Al[3]) : "r"(bQl + aoff));
            #pragma unroll
            for (int n = 0; n < 8; n++) {
                const int br = n * 8 + (lane & 7);
                const uint32_t boff = (uint32_t)(br * 128 +
                    (((t * 2 + ((lane >> 3) & 1)) ^ (br & 7)) << 4));
                uint32_t B0, B1;
                asm volatile("ldmatrix.sync.aligned.m8n8.x2.shared.b16 {%0,%1}, [%2];"
                    : "=r"(B0), "=r"(B1) : "r"(bK + boff));
                MMA16(s[n], Ah, B0, B1);
                MMA16(s[n], Al, B0, B1);
            }
        }

        // scale + causal mask
        #pragma unroll
        for (int n = 0; n < 8; n++)
            #pragma unroll
            for (int e = 0; e < 4; e++) s[n][e] *= 0.125f;
        if (jt == qt) {
            const int rla = w * 16 + (lane >> 2), rlb = rla + 8;
            #pragma unroll
            for (int n = 0; n < 8; n++) {
                const int c0 = n * 8 + (lane & 3) * 2;
                if (c0     > rla) s[n][0] = -1e30f;
                if (c0 + 1 > rla) s[n][1] = -1e30f;
                if (c0     > rlb) s[n][2] = -1e30f;
                if (c0 + 1 > rlb) s[n][3] = -1e30f;
            }
        }

        // online softmax (per-thread rows a, b; quad lanes share a row)
        float mx_a = -1e30f, mx_b = -1e30f;
        #pragma unroll
        for (int n = 0; n < 8; n++) {
            mx_a = fmaxf(mx_a, fmaxf(s[n][0], s[n][1]));
            mx_b = fmaxf(mx_b, fmaxf(s[n][2], s[n][3]));
        }
        mx_a = fmaxf(mx_a, __shfl_xor_sync(0xffffffffu, mx_a, 1));
        mx_a = fmaxf(mx_a, __shfl_xor_sync(0xffffffffu, mx_a, 2));
        mx_b = fmaxf(mx_b, __shfl_xor_sync(0xffffffffu, mx_b, 1));
        mx_b = fmaxf(mx_b, __shfl_xor_sync(0xffffffffu, mx_b, 2));
        const float mn_a = fmaxf(m_a, mx_a), mn_b = fmaxf(m_b, mx_b);
        const float corr_a = __expf(m_a - mn_a), corr_b = __expf(m_b - mn_b);
        m_a = mn_a; m_b = mn_b;
        float sum_a = 0.f, sum_b = 0.f;
        #pragma unroll
        for (int n = 0; n < 8; n++) {
            s[n][0] = __expf(s[n][0] - mn_a); s[n][1] = __expf(s[n][1] - mn_a);
            s[n][2] = __expf(s[n][2] - mn_b); s[n][3] = __expf(s[n][3] - mn_b);
            sum_a += s[n][0] + s[n][1];
            sum_b += s[n][2] + s[n][3];
        }
        sum_a += __shfl_xor_sync(0xffffffffu, sum_a, 1);
        sum_a += __shfl_xor_sync(0xffffffffu, sum_a, 2);
        sum_b += __shfl_xor_sync(0xffffffffu, sum_b, 1);
        sum_b += __shfl_xor_sync(0xffffffffu, sum_b, 2);
        l_a = l_a * corr_a + sum_a;
        l_b = l_b * corr_b + sum_b;
        #pragma unroll
        for (int n = 0; n < 8; n++) {
            o[n][0] *= corr_a; o[n][1] *= corr_a;
            o[n][2] *= corr_b; o[n][3] *= corr_b;
        }

        // pack P -> fp16 A fragments
        uint32_t P[4][4];
        #pragma unroll
        for (int t = 0; t < 4; t++) {
            P[t][0] = packh2(s[2*t  ][0], s[2*t  ][1]);
            P[t][1] = packh2(s[2*t  ][2], s[2*t  ][3]);
            P[t][2] = packh2(s[2*t+1][0], s[2*t+1][1]);
            P[t][3] = packh2(s[2*t+1][2], s[2*t+1][3]);
        }

        // ---- O += P V (2-pass on V) ----
        #pragma unroll
        for (int t = 0; t < 4; t++) {
            #pragma unroll
            for (int dp = 0; dp < 4; dp++) {
                const int vr = t * 16 + ((lane >> 3) & 1) * 8 + (lane & 7);
                const uint32_t voff = (uint32_t)(vr * 128 +
                    (((dp * 2 + (lane >> 4)) ^ (vr & 7)) << 4));
                uint32_t r0, r1, r2, r3;
                asm volatile("ldmatrix.sync.aligned.m8n8.x4.trans.shared.b16 {%0,%1,%2,%3}, [%4];"
                    : "=r"(r0), "=r"(r1), "=r"(r2), "=r"(r3) : "r"(bVh + voff));
                MMA16(o[2*dp], P[t], r0, r1);
                MMA16(o[2*dp+1], P[t], r2, r3);
                asm volatile("ldmatrix.sync.aligned.m8n8.x4.trans.shared.b16 {%0,%1,%2,%3}, [%4];"
                    : "=r"(r0), "=r"(r1), "=r"(r2), "=r"(r3) : "r"(bVl + voff));
                MMA16(o[2*dp], P[t], r0, r1);
                MMA16(o[2*dp+1], P[t], r2, r3);
            }
        }
        __syncthreads();
    }

    // write O -> hi/lo fp16, layout [token][h*64 + d]
    const float il_a = 1.0f / l_a, il_b = 1.0f / l_b;
    const size_t ra = (size_t)(b * TT + q0 + w * 16 + (lane >> 2));
    const size_t rb = ra + 8;
    #pragma unroll
    for (int n = 0; n < 8; n++) {
        const int col = h * HDD + n * 8 + (lane & 3) * 2;
        float v0 = o[n][0] * il_a, v1 = o[n][1] * il_a;
        __half h0 = __float2half_rn(v0), h1 = __float2half_rn(v1);
        *(ushort2*)(ohi + ra * DD + col) =
            make_ushort2(__half_as_ushort(h0), __half_as_ushort(h1));
        __half e0 = __float2half_rn(v0 - __half2float(h0));
        __half e1 = __float2half_rn(v1 - __half2float(h1));
        *(ushort2*)(olo + ra * DD + col) =
            make_ushort2(__half_as_ushort(e0), __half_as_ushort(e1));
        float v2 = o[n][2] * il_b, v3 = o[n][3] * il_b;
        __half h2 = __float2half_rn(v2), h3 = __float2half_rn(v3);
        *(ushort2*)(ohi + rb * DD + col) =
            make_ushort2(__half_as_ushort(h2), __half_as_ushort(h3));
        __half e2 = __float2half_rn(v2 - __half2float(h2));
        __half e3 = __float2half_rn(v3 - __half2float(h3));
        *(ushort2*)(olo + rb * DD + col) =
            make_ushort2(__half_as_ushort(e2), __half_as_ushort(e3));
    }
}

// ================= driver =================
extern "C" void kernel_launch(void* const* d_in, const int* in_sizes, int n_in,
                              void* d_out, int out_size) {
    const int*   x      = (const int*)  d_in[0];
    const float* emb_w  = (const float*)d_in[1];
    const float* n1_w   = (const float*)d_in[2];
    const float* n2_w   = (const float*)d_in[3];
    const float* qkv_w  = (const float*)d_in[4];
    const float* qkv_b  = (const float*)d_in[5];
    const float* o_w    = (const float*)d_in[6];
    const float* o_b    = (const float*)d_in[7];
    const float* gw     = (const float*)d_in[8];
    const float* gb     = (const float*)d_in[9];
    const float* uw     = (const float*)d_in[10];
    const float* ub     = (const float*)d_in[11];
    const float* dnw    = (const float*)d_in[12];
    const float* dnb    = (const float*)d_in[13];
    const float* norm_w = (const float*)d_in[14];
    const float* head_w = (const float*)d_in[15];
    float* out = (float*)d_out;

    float *h_, *qkv_, *ffs_;
    __half *wq, *wo, *wg, *wu, *wd, *wh;
    __half *nh, *nl, *ath, *atl, *ffh, *ffl;
    cudaGetSymbolAddress((void**)&h_,   g_h);
    cudaGetSymbolAddress((void**)&qkv_, g_qkv);
    cudaGetSymbolAddress((void**)&ffs_, g_ffs);
    cudaGetSymbolAddress((void**)&wq, g_wqkv);
    cudaGetSymbolAddress((void**)&wo, g_wo);
    cudaGetSymbolAddress((void**)&wg, g_wg);
    cudaGetSymbolAddress((void**)&wu, g_wu);
    cudaGetSymbolAddress((void**)&wd, g_wdn);
    cudaGetSymbolAddress((void**)&wh, g_whd);
    cudaGetSymbolAddress((void**)&nh,  g_n_h);  cudaGetSymbolAddress((void**)&nl,  g_n_l);
    cudaGetSymbolAddress((void**)&ath, g_at_h); cudaGetSymbolAddress((void**)&atl, g_at_l);
    cudaGetSymbolAddress((void**)&ffh, g_ff_h); cudaGetSymbolAddress((void**)&ffl, g_ff_l);

    cudaFuncSetAttribute(gemm_mma, cudaFuncAttributeMaxDynamicSharedMemorySize, GSMEM);

    // launch order: gemm at index 3, attn at index 4 (ncu -s 5 -c 1 lands on one of them)
    convert4_kernel<<<2048, 256>>>((const float4*)qkv_w, wq, (size_t)NLL*3*DD*DD/4); // 0
    embed_kernel<<<MR, 256>>>(x, emb_w, h_);                                         // 1

    for (int l = 0; l < NLL; l++) {
        const size_t oq = (size_t)l * 3 * DD * DD, oo = (size_t)l * DD * DD;
        const size_t of = (size_t)l * FFF * DD;

        rmsnorm_split<<<MR, 256>>>(h_, n1_w + (size_t)l * DD, nh, nl);               // 2

        gemm_mma<<<dim3(MR / 128, 3 * DD / 128), 256, GSMEM>>>(                      // 3
            nh, nl, wq + oq, qkv_b + (size_t)l * 3 * DD,
            nullptr, qkv_, nullptr, nullptr, 3 * DD, DD, 0);

        attn_mma<<<dim3(TT / 64, NHH, BB), 128>>>(qkv_, ath, atl);                   // 4

        if (l == 0) convert4_kernel<<<2048, 256>>>((const float4*)o_w, wo, (size_t)NLL*DD*DD/4);

        gemm_mma<<<dim3(MR / 128, DD / 128), 256, GSMEM>>>(
            ath, atl, wo + oo, o_b + (size_t)l * DD,
            h_, h_, nullptr, nullptr, DD, DD, 1);

        rmsnorm_split<<<MR, 256>>>(h_, n2_w + (size_t)l * DD, nh, nl);

        if (l == 0) {
            convert4_kernel<<<2048, 256>>>((const float4*)gw, wg, (size_t)NLL*FFF*DD/4);
            convert4_kernel<<<2048, 256>>>((const float4*)uw, wu, (size_t)NLL*FFF*DD/4);
        }

        gemm_mma<<<dim3(MR / 128, FFF / 128), 256, GSMEM>>>(
            nh, nl, wg + of, gb + (size_t)l * FFF,
            nullptr, ffs_, nullptr, nullptr, FFF, DD, 2);

        gemm_mma<<<dim3(MR / 128, FFF / 128), 256, GSMEM>>>(
            nh, nl, wu + of, ub + (size_t)l * FFF,
            ffs_, nullptr, ffh, ffl, FFF, DD, 3);

        if (l == 0) convert4_kernel<<<2048, 256>>>((const float4*)dnw, wd, (size_t)NLL*DD*FFF/4);

        gemm_mma<<<dim3(MR / 128, DD / 128), 256, GSMEM>>>(
            ffh, ffl, wd + of, dnb + (size_t)l * DD,
            h_, h_, nullptr, nullptr, DD, FFF, 1);

        if (l == 0) convert4_kernel<<<2048, 256>>>((const float4*)head_w, wh, (size_t)VV*DD/4);
    }

    rmsnorm_split<<<MR, 256>>>(h_, norm_w, nh, nl);

    gemm_mma<<<dim3(MR / 128, VV / 128), 256, GSMEM>>>(
        nh, nl, wh, nullptr,
        nullptr, out, nullptr, nullptr, VV, DD, 0);
}

// round 9
// speedup vs baseline: 7.0897x; 1.1588x over previous
#include <cuda_runtime.h>
#include <cuda_fp16.h>
#include <math.h>
#include <stdint.h>

// ---------------- problem dims ----------------
#define BB   2
#define TT   2048
#define DD   1024
#define NHH  16
#define HDD  64
#define FFF  4096
#define NLL  2
#define VV   32000
#define MR   (BB*TT)          // 4096 token rows
#define EPSF 1.1920929e-07f

// ---------------- fp32 scratch ----------------
__device__ float g_h  [(size_t)MR*DD];
__device__ float g_qkv[(size_t)MR*3*DD];
__device__ float g_ffs[(size_t)MR*FFF];

// ---------------- fp16 scratch ----------------
__device__ __half g_wqkv[(size_t)NLL*3*DD*DD];
__device__ __half g_wo  [(size_t)NLL*DD*DD];
__device__ __half g_wg  [(size_t)NLL*FFF*DD];
__device__ __half g_wu  [(size_t)NLL*FFF*DD];
__device__ __half g_wdn [(size_t)NLL*DD*FFF];
__device__ __half g_whd [(size_t)VV*DD];
__device__ __half g_n_h [(size_t)MR*DD],  g_n_l [(size_t)MR*DD];
__device__ __half g_at_h[(size_t)MR*DD],  g_at_l[(size_t)MR*DD];
__device__ __half g_ff_h[(size_t)MR*FFF], g_ff_l[(size_t)MR*FFF];

// ================= helpers =================
__device__ __forceinline__ uint32_t smem_u32(const void* p) {
    uint32_t a;
    asm("{ .reg .u64 t; cvta.to.shared.u64 t, %1; cvt.u32.u64 %0, t; }" : "=r"(a) : "l"(p));
    return a;
}
__device__ __forceinline__ uint32_t packh2(float lo, float hi) {
    uint32_t r;
    asm("cvt.rn.f16x2.f32 %0, %1, %2;" : "=r"(r) : "f"(hi), "f"(lo));
    return r;
}

#define MMA16(accfg, A, B0, B1) \
    asm volatile("mma.sync.aligned.m16n8k16.row.col.f32.f16.f16.f32 " \
        "{%0,%1,%2,%3}, {%4,%5,%6,%7}, {%8,%9}, {%0,%1,%2,%3};" \
        : "+f"((accfg)[0]), "+f"((accfg)[1]), "+f"((accfg)[2]), "+f"((accfg)[3]) \
        : "r"((A)[0]), "r"((A)[1]), "r"((A)[2]), "r"((A)[3]), "r"(B0), "r"(B1))

// ================= weight convert: float -> fp16 =================
__global__ __launch_bounds__(256) void convert4_kernel(const float4* __restrict__ src,
                                                       __half* __restrict__ dst,
                                                       size_t n4) {
    size_t stride = (size_t)gridDim.x * blockDim.x;
    for (size_t i = (size_t)blockIdx.x * blockDim.x + threadIdx.x; i < n4; i += stride) {
        float4 v = src[i];
        __half hx = __float2half_rn(v.x), hy = __float2half_rn(v.y);
        __half hz = __float2half_rn(v.z), hw = __float2half_rn(v.w);
        ((ushort4*)dst)[i] = make_ushort4(__half_as_ushort(hx), __half_as_ushort(hy),
                                          __half_as_ushort(hz), __half_as_ushort(hw));
    }
}

// ================= embedding =================
__global__ __launch_bounds__(256) void embed_kernel(const int* __restrict__ x,
                                                    const float* __restrict__ emb,
                                                    float* __restrict__ h) {
    int row = blockIdx.x;
    int tok = x[row];
    ((float4*)(h + (size_t)row * DD))[threadIdx.x] =
        ((const float4*)(emb + (size_t)tok * DD))[threadIdx.x];
}

// ================= RMSNorm -> fp16 hi/lo =================
__global__ __launch_bounds__(256) void rmsnorm_split(const float* __restrict__ x,
                                                     const float* __restrict__ w,
                                                     __half* __restrict__ hi,
                                                     __half* __restrict__ lo) {
    int row = blockIdx.x, t = threadIdx.x;
    float4 v = ((const float4*)(x + (size_t)row * DD))[t];
    float ss = v.x*v.x + v.y*v.y + v.z*v.z + v.w*v.w;
    #pragma unroll
    for (int o = 16; o > 0; o >>= 1) ss += __shfl_xor_sync(0xffffffffu, ss, o);
    __shared__ float wsum[8];
    if ((t & 31) == 0) wsum[t >> 5] = ss;
    __syncthreads();
    float tot = 0.f;
    #pragma unroll
    for (int i = 0; i < 8; i++) tot += wsum[i];
    float rs = rsqrtf(tot * (1.0f / (float)DD) + EPSF);
    float4 wv = ((const float4*)w)[t];
    float o0 = v.x * rs * wv.x, o1 = v.y * rs * wv.y;
    float o2 = v.z * rs * wv.z, o3 = v.w * rs * wv.w;
    __half h0 = __float2half_rn(o0), h1 = __float2half_rn(o1);
    __half h2 = __float2half_rn(o2), h3 = __float2half_rn(o3);
    ((ushort4*)(hi + (size_t)row * DD))[t] =
        make_ushort4(__half_as_ushort(h0), __half_as_ushort(h1),
                     __half_as_ushort(h2), __half_as_ushort(h3));
    __half l0 = __float2half_rn(o0 - __half2float(h0));
    __half l1 = __float2half_rn(o1 - __half2float(h1));
    __half l2 = __float2half_rn(o2 - __half2float(h2));
    __half l3 = __float2half_rn(o3 - __half2float(h3));
    ((ushort4*)(lo + (size_t)row * DD))[t] =
        make_ushort4(__half_as_ushort(l0), __half_as_ushort(l1),
                     __half_as_ushort(l2), __half_as_ushort(l3));
}

// ================= HMMA GEMM, fp16 (A hi/lo split, W single) =====================
// passes=2: full hi+lo A. passes=1: hi only (used for the LM head, where A-rounding
// error does not propagate).
#define GSMEM (3 * 24576)

__global__ __launch_bounds__(256, 2) void gemm_mma(
    const __half* __restrict__ ahi, const __half* __restrict__ alo,
    const __half* __restrict__ w,
    const float* __restrict__ bias, const float* __restrict__ aux,
    float* outf, __half* ohi, __half* olo,
    int N, int K, int epi, int passes)
{
    extern __shared__ __align__(1024) char smem[];
    const int tid = threadIdx.x;
    const int wid = tid >> 5, lane = tid & 31;
    const int mt = blockIdx.x, nt = blockIdx.y;
    const int warp_m = wid >> 2, warp_n = wid & 3;
    const uint32_t sbase = smem_u32(smem);

    float acc[4][4][4];
    #pragma unroll
    for (int f = 0; f < 4; f++)
        #pragma unroll
        for (int g = 0; g < 4; g++)
            #pragma unroll
            for (int e = 0; e < 4; e++) acc[f][g][e] = 0.f;

    const int nc = K >> 5;

    auto prefetch = [&](int kc, int b) {
        const size_t koff = (size_t)kc << 5;
        const uint32_t bufo = sbase + (uint32_t)b * 24576u;
        const __half* bases[3] = {
            ahi + ((size_t)mt * 128) * K + koff,
            alo + ((size_t)mt * 128) * K + koff,
            w   + ((size_t)nt * 128) * K + koff };
        #pragma unroll
        for (int rep = 0; rep < 6; ++rep) {
            const int idx = tid + 256 * rep;
            const int tile = idx >> 9;
            const int r  = (idx >> 2) & 127;
            const int c4 = idx & 3;
            const __half* g = bases[tile] + (size_t)r * K + c4 * 8;
            const uint32_t dst = bufo + (uint32_t)tile * 8192u
                               + (uint32_t)(r * 64 + ((c4 ^ ((r >> 1) & 3)) << 4));
            asm volatile("cp.async.cg.shared.global [%0], [%1], 16;" :: "r"(dst), "l"(g));
        }
        asm volatile("cp.async.commit_group;" ::: "memory");
    };

    prefetch(0, 0);
    if (nc > 1) prefetch(1, 1);
    for (int c = 0; c < nc; ++c) {
        if (c + 2 < nc) {
            prefetch(c + 2, (c + 2) % 3);
            asm volatile("cp.async.wait_group 2;" ::: "memory");
        } else if (c + 1 < nc) {
            asm volatile("cp.async.wait_group 1;" ::: "memory");
        } else {
            asm volatile("cp.async.wait_group 0;" ::: "memory");
        }
        __syncthreads();

        const uint32_t buf = sbase + (uint32_t)(c % 3) * 24576u;
        const uint32_t a_hi_b = buf, a_lo_b = buf + 8192u, b_b = buf + 16384u;

        #pragma unroll
        for (int s = 0; s < 2; ++s) {
            const int arow = warp_m * 64 + (lane & 15);
            const int ach  = s * 2 + (lane >> 4);
            const int brow = warp_n * 32 + (lane & 7);
            const int bch  = s * 2 + ((lane >> 3) & 1);
            uint32_t aoff[4], boff[4];
            #pragma unroll
            for (int f = 0; f < 4; ++f) {
                const int row = arow + f * 16;
                aoff[f] = row * 64 + ((ach ^ ((row >> 1) & 3)) << 4);
            }
            #pragma unroll
            for (int g = 0; g < 4; ++g) {
                const int row = brow + g * 8;
                boff[g] = row * 64 + ((bch ^ ((row >> 1) & 3)) << 4);
            }

            uint32_t A[4][4], Bv[4][2];
            #pragma unroll
            for (int g = 0; g < 4; ++g)
                asm volatile("ldmatrix.sync.aligned.m8n8.x2.shared.b16 {%0,%1}, [%2];"
                    : "=r"(Bv[g][0]), "=r"(Bv[g][1]) : "r"(b_b + boff[g]));
            #pragma unroll
            for (int f = 0; f < 4; ++f)
                asm volatile("ldmatrix.sync.aligned.m8n8.x4.shared.b16 {%0,%1,%2,%3}, [%4];"
                    : "=r"(A[f][0]), "=r"(A[f][1]), "=r"(A[f][2]), "=r"(A[f][3])
                    : "r"(a_hi_b + aoff[f]));
            #pragma unroll
            for (int f = 0; f < 4; ++f)
                #pragma unroll
                for (int g = 0; g < 4; ++g)
                    MMA16(acc[f][g], A[f], Bv[g][0], Bv[g][1]);
            if (passes == 2) {
                #pragma unroll
                for (int f = 0; f < 4; ++f)
                    asm volatile("ldmatrix.sync.aligned.m8n8.x4.shared.b16 {%0,%1,%2,%3}, [%4];"
                        : "=r"(A[f][0]), "=r"(A[f][1]), "=r"(A[f][2]), "=r"(A[f][3])
                        : "r"(a_lo_b + aoff[f]));
                #pragma unroll
                for (int f = 0; f < 4; ++f)
                    #pragma unroll
                    for (int g = 0; g < 4; ++g)
                        MMA16(acc[f][g], A[f], Bv[g][0], Bv[g][1]);
            }
        }
        __syncthreads();
    }

    // ---- epilogue ----
    const int r_in = lane >> 2, c_in = (lane & 3) * 2;
    #pragma unroll
    for (int f = 0; f < 4; ++f) {
        #pragma unroll
        for (int rr = 0; rr < 2; ++rr) {
            const size_t m = (size_t)mt * 128 + warp_m * 64 + f * 16 + rr * 8 + r_in;
            float* frow = outf ? outf + m * (size_t)N : (float*)0;
            const float* arow = aux ? aux + m * (size_t)N : (const float*)0;
            #pragma unroll
            for (int g = 0; g < 4; ++g) {
                const int n = nt * 128 + warp_n * 32 + g * 8 + c_in;
                float x = acc[f][g][rr * 2 + 0];
                float y = acc[f][g][rr * 2 + 1];
                if (bias) { x += bias[n]; y += bias[n + 1]; }
                if (epi == 1) {
                    x += arow[n]; y += arow[n + 1];
                    frow[n] = x; frow[n + 1] = y;
                } else if (epi == 2) {
                    x = x / (1.f + expf(-x)); y = y / (1.f + expf(-y));
                    frow[n] = x; frow[n + 1] = y;
                } else if (epi == 3) {
                    x *= arow[n]; y *= arow[n + 1];
                    __half hx = __float2half_rn(x), hy = __float2half_rn(y);
                    *(ushort2*)(ohi + m * (size_t)N + n) =
                        make_ushort2(__half_as_ushort(hx), __half_as_ushort(hy));
                    __half lx = __float2half_rn(x - __half2float(hx));
                    __half ly = __float2half_rn(y - __half2float(hy));
                    *(ushort2*)(olo + m * (size_t)N + n) =
                        make_ushort2(__half_as_ushort(lx), __half_as_ushort(ly));
                } else {
                    frow[n] = x; frow[n + 1] = y;
                }
            }
        }
    }
}

// ================= HMMA flash attention (causal), HD=64 =================
__global__ __launch_bounds__(128) void attn_mma(const float* __restrict__ qkv,
                                                __half* __restrict__ ohi,
                                                __half* __restrict__ olo) {
    __shared__ __align__(128) __half sQh[64*64], sQl[64*64], sK[64*64],
                                     sVh[64*64], sVl[64*64];
    const int tid = threadIdx.x, lane = tid & 31, w = tid >> 5;
    const int qt = blockIdx.x, h = blockIdx.y, b = blockIdx.z;
    const int q0 = qt * 64;
    const uint32_t bQh = smem_u32(sQh), bQl = smem_u32(sQl), bK = smem_u32(sK);
    const uint32_t bVh = smem_u32(sVh), bVl = smem_u32(sVl);

    #pragma unroll
    for (int i = 0; i < 4; i++) {
        const int idx = tid + 128 * i;
        const int r = idx >> 3, c8 = idx & 7;
        const float* src = qkv + ((size_t)(b * TT + q0 + r)) * (3 * DD) + h * HDD + c8 * 8;
        const uint32_t off = (uint32_t)(r * 128 + ((c8 ^ (r & 7)) << 4));
        __half hh[8], ll[8];
        #pragma unroll
        for (int e = 0; e < 8; e++) {
            float v = src[e];
            hh[e] = __float2half_rn(v);
            ll[e] = __float2half_rn(v - __half2float(hh[e]));
        }
        *(uint4*)((char*)sQh + off) = *(uint4*)hh;
        *(uint4*)((char*)sQl + off) = *(uint4*)ll;
    }

    float m_a = -1e30f, m_b = -1e30f, l_a = 0.f, l_b = 0.f;
    float o[8][4];
    #pragma unroll
    for (int n = 0; n < 8; n++)
        #pragma unroll
        for (int e = 0; e < 4; e++) o[n][e] = 0.f;

    for (int jt = 0; jt <= qt; jt++) {
        const int k0 = jt * 64;
        #pragma unroll
        for (int i = 0; i < 4; i++) {
            const int idx = tid + 128 * i;
            const int r = idx >> 3, c8 = idx & 7;
            const size_t base = ((size_t)(b * TT + k0 + r)) * (3 * DD) + h * HDD + c8 * 8;
            const uint32_t off = (uint32_t)(r * 128 + ((c8 ^ (r & 7)) << 4));
            __half kk[8], vh[8], vl[8];
            #pragma unroll
            for (int e = 0; e < 8; e++) {
                kk[e] = __float2half_rn(qkv[base + DD + e]);
                float v = qkv[base + 2 * DD + e];
                vh[e] = __float2half_rn(v);
                vl[e] = __float2half_rn(v - __half2float(vh[e]));
            }
            *(uint4*)((char*)sK  + off) = *(uint4*)kk;
            *(uint4*)((char*)sVh + off) = *(uint4*)vh;
            *(uint4*)((char*)sVl + off) = *(uint4*)vl;
        }
        __syncthreads();

        float s[8][4];
        #pragma unroll
        for (int n = 0; n < 8; n++)
            #pragma unroll
            for (int e = 0; e < 4; e++) s[n][e] = 0.f;

        #pragma unroll
        for (int t = 0; t < 4; t++) {
            const int ar = w * 16 + (lane & 15);
            const uint32_t aoff = (uint32_t)(ar * 128 + (((t * 2 + (lane >> 4)) ^ (ar & 7)) << 4));
            uint32_t Ah[4], Al[4];
            asm volatile("ldmatrix.sync.aligned.m8n8.x4.shared.b16 {%0,%1,%2,%3}, [%4];"
                : "=r"(Ah[0]), "=r"(Ah[1]), "=r"(Ah[2]), "=r"(Ah[3]) : "r"(bQh + aoff));
            asm volatile("ldmatrix.sync.aligned.m8n8.x4.shared.b16 {%0,%1,%2,%3}, [%4];"
                : "=r"(Al[0]), "=r"(Al[1]), "=r"(Al[2]), "=r"(Al[3]) : "r"(bQl + aoff));
            #pragma unroll
            for (int n = 0; n < 8; n++) {
                const int br = n * 8 + (lane & 7);
                const uint32_t boff = (uint32_t)(br * 128 +
                    (((t * 2 + ((lane >> 3) & 1)) ^ (br & 7)) << 4));
                uint32_t B0, B1;
                asm volatile("ldmatrix.sync.aligned.m8n8.x2.shared.b16 {%0,%1}, [%2];"
                    : "=r"(B0), "=r"(B1) : "r"(bK + boff));
                MMA16(s[n], Ah, B0, B1);
                MMA16(s[n], Al, B0, B1);
            }
        }

        #pragma unroll
        for (int n = 0; n < 8; n++)
            #pragma unroll
            for (int e = 0; e < 4; e++) s[n][e] *= 0.125f;
        if (jt == qt) {
            const int rla = w * 16 + (lane >> 2), rlb = rla + 8;
            #pragma unroll
            for (int n = 0; n < 8; n++) {
                const int c0 = n * 8 + (lane & 3) * 2;
                if (c0     > rla) s[n][0] = -1e30f;
                if (c0 + 1 > rla) s[n][1] = -1e30f;
                if (c0     > rlb) s[n][2] = -1e30f;
                if (c0 + 1 > rlb) s[n][3] = -1e30f;
            }
        }

        float mx_a = -1e30f, mx_b = -1e30f;
        #pragma unroll
        for (int n = 0; n < 8; n++) {
            mx_a = fmaxf(mx_a, fmaxf(s[n][0], s[n][1]));
            mx_b = fmaxf(mx_b, fmaxf(s[n][2], s[n][3]));
        }
        mx_a = fmaxf(mx_a, __shfl_xor_sync(0xffffffffu, mx_a, 1));
        mx_a = fmaxf(mx_a, __shfl_xor_sync(0xffffffffu, mx_a, 2));
        mx_b = fmaxf(mx_b, __shfl_xor_sync(0xffffffffu, mx_b, 1));
        mx_b = fmaxf(mx_b, __shfl_xor_sync(0xffffffffu, mx_b, 2));
        const float mn_a = fmaxf(m_a, mx_a), mn_b = fmaxf(m_b, mx_b);
        const float corr_a = __expf(m_a - mn_a), corr_b = __expf(m_b - mn_b);
        m_a = mn_a; m_b = mn_b;
        float sum_a = 0.f, sum_b = 0.f;
        #pragma unroll
        for (int n = 0; n < 8; n++) {
            s[n][0] = __expf(s[n][0] - mn_a); s[n][1] = __expf(s[n][1] - mn_a);
            s[n][2] = __expf(s[n][2] - mn_b); s[n][3] = __expf(s[n][3] - mn_b);
            sum_a += s[n][0] + s[n][1];
            sum_b += s[n][2] + s[n][3];
        }
        sum_a += __shfl_xor_sync(0xffffffffu, sum_a, 1);
        sum_a += __shfl_xor_sync(0xffffffffu, sum_a, 2);
        sum_b += __shfl_xor_sync(0xffffffffu, sum_b, 1);
        sum_b += __shfl_xor_sync(0xffffffffu, sum_b, 2);
        l_a = l_a * corr_a + sum_a;
        l_b = l_b * corr_b + sum_b;
        #pragma unroll
        for (int n = 0; n < 8; n++) {
            o[n][0] *= corr_a; o[n][1] *= corr_a;
            o[n][2] *= corr_b; o[n][3] *= corr_b;
        }

        uint32_t P[4][4];
        #pragma unroll
        for (int t = 0; t < 4; t++) {
            P[t][0] = packh2(s[2*t  ][0], s[2*t  ][1]);
            P[t][1] = packh2(s[2*t  ][2], s[2*t  ][3]);
            P[t][2] = packh2(s[2*t+1][0], s[2*t+1][1]);
            P[t][3] = packh2(s[2*t+1][2], s[2*t+1][3]);
        }

        #pragma unroll
        for (int t = 0; t < 4; t++) {
            #pragma unroll
            for (int dp = 0; dp < 4; dp++) {
                const int vr = t * 16 + ((lane >> 3) & 1) * 8 + (lane & 7);
                const uint32_t voff = (uint32_t)(vr * 128 +
                    (((dp * 2 + (lane >> 4)) ^ (vr & 7)) << 4));
                uint32_t r0, r1, r2, r3;
                asm volatile("ldmatrix.sync.aligned.m8n8.x4.trans.shared.b16 {%0,%1,%2,%3}, [%4];"
                    : "=r"(r0), "=r"(r1), "=r"(r2), "=r"(r3) : "r"(bVh + voff));
                MMA16(o[2*dp], P[t], r0, r1);
                MMA16(o[2*dp+1], P[t], r2, r3);
                asm volatile("ldmatrix.sync.aligned.m8n8.x4.trans.shared.b16 {%0,%1,%2,%3}, [%4];"
                    : "=r"(r0), "=r"(r1), "=r"(r2), "=r"(r3) : "r"(bVl + voff));
                MMA16(o[2*dp], P[t], r0, r1);
                MMA16(o[2*dp+1], P[t], r2, r3);
            }
        }
        __syncthreads();
    }

    const float il_a = 1.0f / l_a, il_b = 1.0f / l_b;
    const size_t ra = (size_t)(b * TT + q0 + w * 16 + (lane >> 2));
    const size_t rb = ra + 8;
    #pragma unroll
    for (int n = 0; n < 8; n++) {
        const int col = h * HDD + n * 8 + (lane & 3) * 2;
        float v0 = o[n][0] * il_a, v1 = o[n][1] * il_a;
        __half h0 = __float2half_rn(v0), h1 = __float2half_rn(v1);
        *(ushort2*)(ohi + ra * DD + col) =
            make_ushort2(__half_as_ushort(h0), __half_as_ushort(h1));
        __half e0 = __float2half_rn(v0 - __half2float(h0));
        __half e1 = __float2half_rn(v1 - __half2float(h1));
        *(ushort2*)(olo + ra * DD + col) =
            make_ushort2(__half_as_ushort(e0), __half_as_ushort(e1));
        float v2 = o[n][2] * il_b, v3 = o[n][3] * il_b;
        __half h2 = __float2half_rn(v2), h3 = __float2half_rn(v3);
        *(ushort2*)(ohi + rb * DD + col) =
            make_ushort2(__half_as_ushort(h2), __half_as_ushort(h3));
        __half e2 = __float2half_rn(v2 - __half2float(h2));
        __half e3 = __float2half_rn(v3 - __half2float(h3));
        *(ushort2*)(olo + rb * DD + col) =
            make_ushort2(__half_as_ushort(e2), __half_as_ushort(e3));
    }
}

// ================= driver =================
extern "C" void kernel_launch(void* const* d_in, const int* in_sizes, int n_in,
                              void* d_out, int out_size) {
    const int*   x      = (const int*)  d_in[0];
    const float* emb_w  = (const float*)d_in[1];
    const float* n1_w   = (const float*)d_in[2];
    const float* n2_w   = (const float*)d_in[3];
    const float* qkv_w  = (const float*)d_in[4];
    const float* qkv_b  = (const float*)d_in[5];
    const float* o_w    = (const float*)d_in[6];
    const float* o_b    = (const float*)d_in[7];
    const float* gw     = (const float*)d_in[8];
    const float* gb     = (const float*)d_in[9];
    const float* uw     = (const float*)d_in[10];
    const float* ub     = (const float*)d_in[11];
    const float* dnw    = (const float*)d_in[12];
    const float* dnb    = (const float*)d_in[13];
    const float* norm_w = (const float*)d_in[14];
    const float* head_w = (const float*)d_in[15];
    float* out = (float*)d_out;

    float *h_, *qkv_, *ffs_;
    __half *wq, *wo, *wg, *wu, *wd, *wh;
    __half *nh, *nl, *ath, *atl, *ffh, *ffl;
    cudaGetSymbolAddress((void**)&h_,   g_h);
    cudaGetSymbolAddress((void**)&qkv_, g_qkv);
    cudaGetSymbolAddress((void**)&ffs_, g_ffs);
    cudaGetSymbolAddress((void**)&wq, g_wqkv);
    cudaGetSymbolAddress((void**)&wo, g_wo);
    cudaGetSymbolAddress((void**)&wg, g_wg);
    cudaGetSymbolAddress((void**)&wu, g_wu);
    cudaGetSymbolAddress((void**)&wd, g_wdn);
    cudaGetSymbolAddress((void**)&wh, g_whd);
    cudaGetSymbolAddress((void**)&nh,  g_n_h);  cudaGetSymbolAddress((void**)&nl,  g_n_l);
    cudaGetSymbolAddress((void**)&ath, g_at_h); cudaGetSymbolAddress((void**)&atl, g_at_l);
    cudaGetSymbolAddress((void**)&ffh, g_ff_h); cudaGetSymbolAddress((void**)&ffl, g_ff_l);

    cudaFuncSetAttribute(gemm_mma, cudaFuncAttributeMaxDynamicSharedMemorySize, GSMEM);

    convert4_kernel<<<2048, 256>>>((const float4*)qkv_w, wq, (size_t)NLL*3*DD*DD/4); // 0
    embed_kernel<<<MR, 256>>>(x, emb_w, h_);                                         // 1

    for (int l = 0; l < NLL; l++) {
        const size_t oq = (size_t)l * 3 * DD * DD, oo = (size_t)l * DD * DD;
        const size_t of = (size_t)l * FFF * DD;

        rmsnorm_split<<<MR, 256>>>(h_, n1_w + (size_t)l * DD, nh, nl);               // 2

        gemm_mma<<<dim3(MR / 128, 3 * DD / 128), 256, GSMEM>>>(                      // 3
            nh, nl, wq + oq, qkv_b + (size_t)l * 3 * DD,
            nullptr, qkv_, nullptr, nullptr, 3 * DD, DD, 0, 2);

        attn_mma<<<dim3(TT / 64, NHH, BB), 128>>>(qkv_, ath, atl);                   // 4

        if (l == 0) convert4_kernel<<<2048, 256>>>((const float4*)o_w, wo, (size_t)NLL*DD*DD/4);

        gemm_mma<<<dim3(MR / 128, DD / 128), 256, GSMEM>>>(
            ath, atl, wo + oo, o_b + (size_t)l * DD,
            h_, h_, nullptr, nullptr, DD, DD, 1, 2);

        rmsnorm_split<<<MR, 256>>>(h_, n2_w + (size_t)l * DD, nh, nl);

        if (l == 0) {
            convert4_kernel<<<2048, 256>>>((const float4*)gw, wg, (size_t)NLL*FFF*DD/4);
            convert4_kernel<<<2048, 256>>>((const float4*)uw, wu, (size_t)NLL*FFF*DD/4);
        }

        gemm_mma<<<dim3(MR / 128, FFF / 128), 256, GSMEM>>>(
            nh, nl, wg + of, gb + (size_t)l * FFF,
            nullptr, ffs_, nullptr, nullptr, FFF, DD, 2, 2);

        gemm_mma<<<dim3(MR / 128, FFF / 128), 256, GSMEM>>>(
            nh, nl, wu + of, ub + (size_t)l * FFF,
            ffs_, nullptr, ffh, ffl, FFF, DD, 3, 2);

        if (l == 0) convert4_kernel<<<2048, 256>>>((const float4*)dnw, wd, (size_t)NLL*DD*FFF/4);

        gemm_mma<<<dim3(MR / 128, DD / 128), 256, GSMEM>>>(
            ffh, ffl, wd + of, dnb + (size_t)l * DD,
            h_, h_, nullptr, nullptr, DD, FFF, 1, 2);

        if (l == 0) convert4_kernel<<<2048, 256>>>((const float4*)head_w, wh, (size_t)VV*DD/4);
    }

    rmsnorm_split<<<MR, 256>>>(h_, norm_w, nh, nl);

    // LM head: single-pass A (final-layer output; A-rounding error does not propagate)
    gemm_mma<<<dim3(MR / 128, VV / 128), 256, GSMEM>>>(
        nh, nl, wh, nullptr,
        nullptr, out, nullptr, nullptr, VV, DD, 0, 1);
}

// round 11
// speedup vs baseline: 7.6260x; 1.0756x over previous
#include <cuda_runtime.h>
#include <cuda_fp16.h>
#include <math.h>
#include <stdint.h>

// ---------------- problem dims ----------------
#define BB   2
#define TT   2048
#define DD   1024
#define NHH  16
#define HDD  64
#define FFF  4096
#define NLL  2
#define VV   32000
#define MR   (BB*TT)          // 4096 token rows
#define EPSF 1.1920929e-07f

// ---------------- fp32 scratch ----------------
__device__ float g_h  [(size_t)MR*DD];
__device__ float g_qkv[(size_t)MR*3*DD];
__device__ float g_ffs[(size_t)MR*FFF];

// ---------------- fp16 scratch ----------------
__device__ __half g_wqkv[(size_t)NLL*3*DD*DD];
__device__ __half g_wo  [(size_t)NLL*DD*DD];
__device__ __half g_wg  [(size_t)NLL*FFF*DD];
__device__ __half g_wu  [(size_t)NLL*FFF*DD];
__device__ __half g_wdn [(size_t)NLL*DD*FFF];
__device__ __half g_whd [(size_t)VV*DD];
__device__ __half g_n_h [(size_t)MR*DD],  g_n_l [(size_t)MR*DD];
__device__ __half g_at_h[(size_t)MR*DD],  g_at_l[(size_t)MR*DD];
__device__ __half g_ff_h[(size_t)MR*FFF], g_ff_l[(size_t)MR*FFF];

// ================= helpers =================
__device__ __forceinline__ uint32_t smem_u32(const void* p) {
    uint32_t a;
    asm("{ .reg .u64 t; cvta.to.shared.u64 t, %1; cvt.u32.u64 %0, t; }" : "=r"(a) : "l"(p));
    return a;
}
__device__ __forceinline__ uint32_t packh2(float lo, float hi) {
    uint32_t r;
    asm("cvt.rn.f16x2.f32 %0, %1, %2;" : "=r"(r) : "f"(hi), "f"(lo));
    return r;
}

#define MMA16(accfg, A, B0, B1) \
    asm volatile("mma.sync.aligned.m16n8k16.row.col.f32.f16.f16.f32 " \
        "{%0,%1,%2,%3}, {%4,%5,%6,%7}, {%8,%9}, {%0,%1,%2,%3};" \
        : "+f"((accfg)[0]), "+f"((accfg)[1]), "+f"((accfg)[2]), "+f"((accfg)[3]) \
        : "r"((A)[0]), "r"((A)[1]), "r"((A)[2]), "r"((A)[3]), "r"(B0), "r"(B1))

// ================= weight convert: float -> fp16 =================
__global__ __launch_bounds__(256) void convert4_kernel(const float4* __restrict__ src,
                                                       __half* __restrict__ dst,
                                                       size_t n4) {
    size_t stride = (size_t)gridDim.x * blockDim.x;
    for (size_t i = (size_t)blockIdx.x * blockDim.x + threadIdx.x; i < n4; i += stride) {
        float4 v = src[i];
        __half hx = __float2half_rn(v.x), hy = __float2half_rn(v.y);
        __half hz = __float2half_rn(v.z), hw = __float2half_rn(v.w);
        ((ushort4*)dst)[i] = make_ushort4(__half_as_ushort(hx), __half_as_ushort(hy),
                                          __half_as_ushort(hz), __half_as_ushort(hw));
    }
}

// ================= embedding =================
__global__ __launch_bounds__(256) void embed_kernel(const int* __restrict__ x,
                                                    const float* __restrict__ emb,
                                                    float* __restrict__ h) {
    int row = blockIdx.x;
    int tok = x[row];
    ((float4*)(h + (size_t)row * DD))[threadIdx.x] =
        ((const float4*)(emb + (size_t)tok * DD))[threadIdx.x];
}

// ================= RMSNorm -> fp16 hi/lo =================
__global__ __launch_bounds__(256) void rmsnorm_split(const float* __restrict__ x,
                                                     const float* __restrict__ w,
                                                     __half* __restrict__ hi,
                                                     __half* __restrict__ lo) {
    int row = blockIdx.x, t = threadIdx.x;
    float4 v = ((const float4*)(x + (size_t)row * DD))[t];
    float ss = v.x*v.x + v.y*v.y + v.z*v.z + v.w*v.w;
    #pragma unroll
    for (int o = 16; o > 0; o >>= 1) ss += __shfl_xor_sync(0xffffffffu, ss, o);
    __shared__ float wsum[8];
    if ((t & 31) == 0) wsum[t >> 5] = ss;
    __syncthreads();
    float tot = 0.f;
    #pragma unroll
    for (int i = 0; i < 8; i++) tot += wsum[i];
    float rs = rsqrtf(tot * (1.0f / (float)DD) + EPSF);
    float4 wv = ((const float4*)w)[t];
    float o0 = v.x * rs * wv.x, o1 = v.y * rs * wv.y;
    float o2 = v.z * rs * wv.z, o3 = v.w * rs * wv.w;
    __half h0 = __float2half_rn(o0), h1 = __float2half_rn(o1);
    __half h2 = __float2half_rn(o2), h3 = __float2half_rn(o3);
    ((ushort4*)(hi + (size_t)row * DD))[t] =
        make_ushort4(__half_as_ushort(h0), __half_as_ushort(h1),
                     __half_as_ushort(h2), __half_as_ushort(h3));
    __half l0 = __float2half_rn(o0 - __half2float(h0));
    __half l1 = __float2half_rn(o1 - __half2float(h1));
    __half l2 = __float2half_rn(o2 - __half2float(h2));
    __half l3 = __float2half_rn(o3 - __half2float(h3));
    ((ushort4*)(lo + (size_t)row * DD))[t] =
        make_ushort4(__half_as_ushort(l0), __half_as_ushort(l1),
                     __half_as_ushort(l2), __half_as_ushort(l3));
}

// ================= HMMA GEMM, fp16 (A hi/lo split, W single), k64 chunks =========
// passes=2: full hi+lo A. passes=1: hi only (LM head).
// K-chunk 64, 2-stage double buffer (48KB/stage), CTA tile 128x128, 8 warps.
// Swizzle: full-128B rows, 16B chunk c8 -> c8 ^ (r & 7).
#define GSTAGE 49152
#define GSMEM (2 * GSTAGE)

__global__ __launch_bounds__(256, 2) void gemm_mma(
    const __half* __restrict__ ahi, const __half* __restrict__ alo,
    const __half* __restrict__ w,
    const float* __restrict__ bias, const float* __restrict__ aux,
    float* outf, __half* ohi, __half* olo,
    int N, int K, int epi, int passes)
{
    extern __shared__ __align__(1024) char smem[];
    const int tid = threadIdx.x;
    const int wid = tid >> 5, lane = tid & 31;
    const int mt = blockIdx.x, nt = blockIdx.y;
    const int warp_m = wid >> 2, warp_n = wid & 3;
    const uint32_t sbase = smem_u32(smem);

    float acc[4][4][4];
    #pragma unroll
    for (int f = 0; f < 4; f++)
        #pragma unroll
        for (int g = 0; g < 4; g++)
            #pragma unroll
            for (int e = 0; e < 4; e++) acc[f][g][e] = 0.f;

    const int nc = K >> 6;   // 64-wide k-chunks

    // stage layout: Ahi @0, Alo @16K, W @32K ; 128 rows x 128 bytes each
    auto prefetch = [&](int kc, int b) {
        const size_t koff = (size_t)kc << 6;
        const uint32_t bufo = sbase + (uint32_t)b * (uint32_t)GSTAGE;
        const __half* bases[3] = {
            ahi + ((size_t)mt * 128) * K + koff,
            alo + ((size_t)mt * 128) * K + koff,
            w   + ((size_t)nt * 128) * K + koff };
        #pragma unroll
        for (int rep = 0; rep < 12; ++rep) {
            const int idx = tid + 256 * rep;          // 0..3071
            const int tile = idx >> 10;               // 0..2
            const int t  = idx & 1023;
            const int r  = t >> 3, c8 = t & 7;
            const __half* g = bases[tile] + (size_t)r * K + c8 * 8;
            const uint32_t dst = bufo + (uint32_t)tile * 16384u
                               + (uint32_t)(r * 128 + ((c8 ^ (r & 7)) << 4));
            asm volatile("cp.async.cg.shared.global [%0], [%1], 16;" :: "r"(dst), "l"(g));
        }
        asm volatile("cp.async.commit_group;" ::: "memory");
    };

    prefetch(0, 0);
    for (int c = 0; c < nc; ++c) {
        if (c + 1 < nc) {
            prefetch(c + 1, (c + 1) & 1);
            asm volatile("cp.async.wait_group 1;" ::: "memory");
        } else {
            asm volatile("cp.async.wait_group 0;" ::: "memory");
        }
        __syncthreads();

        const uint32_t buf = sbase + (uint32_t)(c & 1) * (uint32_t)GSTAGE;
        const uint32_t a_hi_b = buf, a_lo_b = buf + 16384u, b_b = buf + 32768u;

        #pragma unroll
        for (int s = 0; s < 4; ++s) {
            const int arow = warp_m * 64 + (lane & 15);
            const int ach  = s * 2 + (lane >> 4);
            const int brow = warp_n * 32 + (lane & 7);
            const int bch  = s * 2 + ((lane >> 3) & 1);
            uint32_t aoff[4], boff[4];
            #pragma unroll
            for (int f = 0; f < 4; ++f) {
                const int row = arow + f * 16;
                aoff[f] = row * 128 + ((ach ^ (row & 7)) << 4);
            }
            #pragma unroll
            for (int g = 0; g < 4; ++g) {
                const int row = brow + g * 8;
                boff[g] = row * 128 + ((bch ^ (row & 7)) << 4);
            }

            uint32_t A[4][4], Bv[4][2];
            #pragma unroll
            for (int g = 0; g < 4; ++g)
                asm volatile("ldmatrix.sync.aligned.m8n8.x2.shared.b16 {%0,%1}, [%2];"
                    : "=r"(Bv[g][0]), "=r"(Bv[g][1]) : "r"(b_b + boff[g]));
            #pragma unroll
            for (int f = 0; f < 4; ++f)
                asm volatile("ldmatrix.sync.aligned.m8n8.x4.shared.b16 {%0,%1,%2,%3}, [%4];"
                    : "=r"(A[f][0]), "=r"(A[f][1]), "=r"(A[f][2]), "=r"(A[f][3])
                    : "r"(a_hi_b + aoff[f]));
            #pragma unroll
            for (int f = 0; f < 4; ++f)
                #pragma unroll
                for (int g = 0; g < 4; ++g)
                    MMA16(acc[f][g], A[f], Bv[g][0], Bv[g][1]);
            if (passes == 2) {
                #pragma unroll
                for (int f = 0; f < 4; ++f)
                    asm volatile("ldmatrix.sync.aligned.m8n8.x4.shared.b16 {%0,%1,%2,%3}, [%4];"
                        : "=r"(A[f][0]), "=r"(A[f][1]), "=r"(A[f][2]), "=r"(A[f][3])
                        : "r"(a_lo_b + aoff[f]));
                #pragma unroll
                for (int f = 0; f < 4; ++f)
                    #pragma unroll
                    for (int g = 0; g < 4; ++g)
                        MMA16(acc[f][g], A[f], Bv[g][0], Bv[g][1]);
            }
        }
        __syncthreads();
    }

    // ---- epilogue ----
    const int r_in = lane >> 2, c_in = (lane & 3) * 2;
    #pragma unroll
    for (int f = 0; f < 4; ++f) {
        #pragma unroll
        for (int rr = 0; rr < 2; ++rr) {
            const size_t m = (size_t)mt * 128 + warp_m * 64 + f * 16 + rr * 8 + r_in;
            float* frow = outf ? outf + m * (size_t)N : (float*)0;
            const float* arow = aux ? aux + m * (size_t)N : (const float*)0;
            #pragma unroll
            for (int g = 0; g < 4; ++g) {
                const int n = nt * 128 + warp_n * 32 + g * 8 + c_in;
                float x = acc[f][g][rr * 2 + 0];
                float y = acc[f][g][rr * 2 + 1];
                if (bias) { x += bias[n]; y += bias[n + 1]; }
                if (epi == 1) {
                    x += arow[n]; y += arow[n + 1];
                    frow[n] = x; frow[n + 1] = y;
                } else if (epi == 2) {
                    x = x / (1.f + expf(-x)); y = y / (1.f + expf(-y));
                    frow[n] = x; frow[n + 1] = y;
                } else if (epi == 3) {
                    x *= arow[n]; y *= arow[n + 1];
                    __half hx = __float2half_rn(x), hy = __float2half_rn(y);
                    *(ushort2*)(ohi + m * (size_t)N + n) =
                        make_ushort2(__half_as_ushort(hx), __half_as_ushort(hy));
                    __half lx = __float2half_rn(x - __half2float(hx));
                    __half ly = __float2half_rn(y - __half2float(hy));
                    *(ushort2*)(olo + m * (size_t)N + n) =
                        make_ushort2(__half_as_ushort(lx), __half_as_ushort(ly));
                } else {
                    frow[n] = x; frow[n + 1] = y;
                }
            }
        }
    }
}

// ================= HMMA flash attention (causal), HD=64 =================
__global__ __launch_bounds__(128) void attn_mma(const float* __restrict__ qkv,
                                                __half* __restrict__ ohi,
                                                __half* __restrict__ olo) {
    __shared__ __align__(128) __half sQh[64*64], sQl[64*64], sK[64*64],
                                     sVh[64*64], sVl[64*64];
    const int tid = threadIdx.x, lane = tid & 31, w = tid >> 5;
    const int qt = blockIdx.x, h = blockIdx.y, b = blockIdx.z;
    const int q0 = qt * 64;
    const uint32_t bQh = smem_u32(sQh), bQl = smem_u32(sQl), bK = smem_u32(sK);
    const uint32_t bVh = smem_u32(sVh), bVl = smem_u32(sVl);

    #pragma unroll
    for (int i = 0; i < 4; i++) {
        const int idx = tid + 128 * i;
        const int r = idx >> 3, c8 = idx & 7;
        const float* src = qkv + ((size_t)(b * TT + q0 + r)) * (3 * DD) + h * HDD + c8 * 8;
        const uint32_t off = (uint32_t)(r * 128 + ((c8 ^ (r & 7)) << 4));
        __half hh[8], ll[8];
        #pragma unroll
        for (int e = 0; e < 8; e++) {
            float v = src[e];
            hh[e] = __float2half_rn(v);
            ll[e] = __float2half_rn(v - __half2float(hh[e]));
        }
        *(uint4*)((char*)sQh + off) = *(uint4*)hh;
        *(uint4*)((char*)sQl + off) = *(uint4*)ll;
    }

    float m_a = -1e30f, m_b = -1e30f, l_a = 0.f, l_b = 0.f;
    float o[8][4];
    #pragma unroll
    for (int n = 0; n < 8; n++)
        #pragma unroll
        for (int e = 0; e < 4; e++) o[n][e] = 0.f;

    for (int jt = 0; jt <= qt; jt++) {
        const int k0 = jt * 64;
        #pragma unroll
        for (int i = 0; i < 4; i++) {
            const int idx = tid + 128 * i;
            const int r = idx >> 3, c8 = idx & 7;
            const size_t base = ((size_t)(b * TT + k0 + r)) * (3 * DD) + h * HDD + c8 * 8;
            const uint32_t off = (uint32_t)(r * 128 + ((c8 ^ (r & 7)) << 4));
            __half kk[8], vh[8], vl[8];
            #pragma unroll
            for (int e = 0; e < 8; e++) {
                kk[e] = __float2half_rn(qkv[base + DD + e]);
                float v = qkv[base + 2 * DD + e];
                vh[e] = __float2half_rn(v);
                vl[e] = __float2half_rn(v - __half2float(vh[e]));
            }
            *(uint4*)((char*)sK  + off) = *(uint4*)kk;
            *(uint4*)((char*)sVh + off) = *(uint4*)vh;
            *(uint4*)((char*)sVl + off) = *(uint4*)vl;
        }
        __syncthreads();

        float s[8][4];
        #pragma unroll
        for (int n = 0; n < 8; n++)
            #pragma unroll
            for (int e = 0; e < 4; e++) s[n][e] = 0.f;

        #pragma unroll
        for (int t = 0; t < 4; t++) {
            const int ar = w * 16 + (lane & 15);
            const uint32_t aoff = (uint32_t)(ar * 128 + (((t * 2 + (lane >> 4)) ^ (ar & 7)) << 4));
            uint32_t Ah[4], Al[4];
            asm volatile("ldmatrix.sync.aligned.m8n8.x4.shared.b16 {%0,%1,%2,%3}, [%4];"
                : "=r"(Ah[0]), "=r"(Ah[1]), "=r"(Ah[2]), "=r"(Ah[3]) : "r"(bQh + aoff));
            asm volatile("ldmatrix.sync.aligned.m8n8.x4.shared.b16 {%0,%1,%2,%3}, [%4];"
                : "=r"(Al[0]), "=r"(Al[1]), "=r"(Al[2]), "=r"(Al[3]) : "r"(bQl + aoff));
            #pragma unroll
            for (int n = 0; n < 8; n++) {
                const int br = n * 8 + (lane & 7);
                const uint32_t boff = (uint32_t)(br * 128 +
                    (((t * 2 + ((lane >> 3) & 1)) ^ (br & 7)) << 4));
                uint32_t B0, B1;
                asm volatile("ldmatrix.sync.aligned.m8n8.x2.shared.b16 {%0,%1}, [%2];"
                    : "=r"(B0), "=r"(B1) : "r"(bK + boff));
                MMA16(s[n], Ah, B0, B1);
                MMA16(s[n], Al, B0, B1);
            }
        }

        #pragma unroll
        for (int n = 0; n < 8; n++)
            #pragma unroll
            for (int e = 0; e < 4; e++) s[n][e] *= 0.125f;
        if (jt == qt) {
            const int rla = w * 16 + (lane >> 2), rlb = rla + 8;
            #pragma unroll
            for (int n = 0; n < 8; n++) {
                const int c0 = n * 8 + (lane & 3) * 2;
                if (c0     > rla) s[n][0] = -1e30f;
                if (c0 + 1 > rla) s[n][1] = -1e30f;
                if (c0     > rlb) s[n][2] = -1e30f;
                if (c0 + 1 > rlb) s[n][3] = -1e30f;
            }
        }

        float mx_a = -1e30f, mx_b = -1e30f;
        #pragma unroll
        for (int n = 0; n < 8; n++) {
            mx_a = fmaxf(mx_a, fmaxf(s[n][0], s[n][1]));
            mx_b = fmaxf(mx_b, fmaxf(s[n][2], s[n][3]));
        }
        mx_a = fmaxf(mx_a, __shfl_xor_sync(0xffffffffu, mx_a, 1));
        mx_a = fmaxf(mx_a, __shfl_xor_sync(0xffffffffu, mx_a, 2));
        mx_b = fmaxf(mx_b, __shfl_xor_sync(0xffffffffu, mx_b, 1));
        mx_b = fmaxf(mx_b, __shfl_xor_sync(0xffffffffu, mx_b, 2));
        const float mn_a = fmaxf(m_a, mx_a), mn_b = fmaxf(m_b, mx_b);
        const float corr_a = __expf(m_a - mn_a), corr_b = __expf(m_b - mn_b);
        m_a = mn_a; m_b = mn_b;
        float sum_a = 0.f, sum_b = 0.f;
        #pragma unroll
        for (int n = 0; n < 8; n++) {
            s[n][0] = __expf(s[n][0] - mn_a); s[n][1] = __expf(s[n][1] - mn_a);
            s[n][2] = __expf(s[n][2] - mn_b); s[n][3] = __expf(s[n][3] - mn_b);
            sum_a += s[n][0] + s[n][1];
            sum_b += s[n][2] + s[n][3];
        }
        sum_a += __shfl_xor_sync(0xffffffffu, sum_a, 1);
        sum_a += __shfl_xor_sync(0xffffffffu, sum_a, 2);
        sum_b += __shfl_xor_sync(0xffffffffu, sum_b, 1);
        sum_b += __shfl_xor_sync(0xffffffffu, sum_b, 2);
        l_a = l_a * corr_a + sum_a;
        l_b = l_b * corr_b + sum_b;
        #pragma unroll
        for (int n = 0; n < 8; n++) {
            o[n][0] *= corr_a; o[n][1] *= corr_a;
            o[n][2] *= corr_b; o[n][3] *= corr_b;
        }

        uint32_t P[4][4];
        #pragma unroll
        for (int t = 0; t < 4; t++) {
            P[t][0] = packh2(s[2*t  ][0], s[2*t  ][1]);
            P[t][1] = packh2(s[2*t  ][2], s[2*t  ][3]);
            P[t][2] = packh2(s[2*t+1][0], s[2*t+1][1]);
            P[t][3] = packh2(s[2*t+1][2], s[2*t+1][3]);
        }

        #pragma unroll
        for (int t = 0; t < 4; t++) {
            #pragma unroll
            for (int dp = 0; dp < 4; dp++) {
                const int vr = t * 16 + ((lane >> 3) & 1) * 8 + (lane & 7);
                const uint32_t voff = (uint32_t)(vr * 128 +
                    (((dp * 2 + (lane >> 4)) ^ (vr & 7)) << 4));
                uint32_t r0, r1, r2, r3;
                asm volatile("ldmatrix.sync.aligned.m8n8.x4.trans.shared.b16 {%0,%1,%2,%3}, [%4];"
                    : "=r"(r0), "=r"(r1), "=r"(r2), "=r"(r3) : "r"(bVh + voff));
                MMA16(o[2*dp], P[t], r0, r1);
                MMA16(o[2*dp+1], P[t], r2, r3);
                asm volatile("ldmatrix.sync.aligned.m8n8.x4.trans.shared.b16 {%0,%1,%2,%3}, [%4];"
                    : "=r"(r0), "=r"(r1), "=r"(r2), "=r"(r3) : "r"(bVl + voff));
                MMA16(o[2*dp], P[t], r0, r1);
                MMA16(o[2*dp+1], P[t], r2, r3);
            }
        }
        __syncthreads();
    }

    const float il_a = 1.0f / l_a, il_b = 1.0f / l_b;
    const size_t ra = (size_t)(b * TT + q0 + w * 16 + (lane >> 2));
    const size_t rb = ra + 8;
    #pragma unroll
    for (int n = 0; n < 8; n++) {
        const int col = h * HDD + n * 8 + (lane & 3) * 2;
        float v0 = o[n][0] * il_a, v1 = o[n][1] * il_a;
        __half h0 = __float2half_rn(v0), h1 = __float2half_rn(v1);
        *(ushort2*)(ohi + ra * DD + col) =
            make_ushort2(__half_as_ushort(h0), __half_as_ushort(h1));
        __half e0 = __float2half_rn(v0 - __half2float(h0));
        __half e1 = __float2half_rn(v1 - __half2float(h1));
        *(ushort2*)(olo + ra * DD + col) =
            make_ushort2(__half_as_ushort(e0), __half_as_ushort(e1));
        float v2 = o[n][2] * il_b, v3 = o[n][3] * il_b;
        __half h2 = __float2half_rn(v2), h3 = __float2half_rn(v3);
        *(ushort2*)(ohi + rb * DD + col) =
            make_ushort2(__half_as_ushort(h2), __half_as_ushort(h3));
        __half e2 = __float2half_rn(v2 - __half2float(h2));
        __half e3 = __float2half_rn(v3 - __half2float(h3));
        *(ushort2*)(olo + rb * DD + col) =
            make_ushort2(__half_as_ushort(e2), __half_as_ushort(e3));
    }
}

// ================= driver =================
extern "C" void kernel_launch(void* const* d_in, const int* in_sizes, int n_in,
                              void* d_out, int out_size) {
    const int*   x      = (const int*)  d_in[0];
    const float* emb_w  = (const float*)d_in[1];
    const float* n1_w   = (const float*)d_in[2];
    const float* n2_w   = (const float*)d_in[3];
    const float* qkv_w  = (const float*)d_in[4];
    const float* qkv_b  = (const float*)d_in[5];
    const float* o_w    = (const float*)d_in[6];
    const float* o_b    = (const float*)d_in[7];
    const float* gw     = (const float*)d_in[8];
    const float* gb     = (const float*)d_in[9];
    const float* uw     = (const float*)d_in[10];
    const float* ub     = (const float*)d_in[11];
    const float* dnw    = (const float*)d_in[12];
    const float* dnb    = (const float*)d_in[13];
    const float* norm_w = (const float*)d_in[14];
    const float* head_w = (const float*)d_in[15];
    float* out = (float*)d_out;

    float *h_, *qkv_, *ffs_;
    __half *wq, *wo, *wg, *wu, *wd, *wh;
    __half *nh, *nl, *ath, *atl, *ffh, *ffl;
    cudaGetSymbolAddress((void**)&h_,   g_h);
    cudaGetSymbolAddress((void**)&qkv_, g_qkv);
    cudaGetSymbolAddress((void**)&ffs_, g_ffs);
    cudaGetSymbolAddress((void**)&wq, g_wqkv);
    cudaGetSymbolAddress((void**)&wo, g_wo);
    cudaGetSymbolAddress((void**)&wg, g_wg);
    cudaGetSymbolAddress((void**)&wu, g_wu);
    cudaGetSymbolAddress((void**)&wd, g_wdn);
    cudaGetSymbolAddress((void**)&wh, g_whd);
    cudaGetSymbolAddress((void**)&nh,  g_n_h);  cudaGetSymbolAddress((void**)&nl,  g_n_l);
    cudaGetSymbolAddress((void**)&ath, g_at_h); cudaGetSymbolAddress((void**)&atl, g_at_l);
    cudaGetSymbolAddress((void**)&ffh, g_ff_h); cudaGetSymbolAddress((void**)&ffl, g_ff_l);

    cudaFuncSetAttribute(gemm_mma, cudaFuncAttributeMaxDynamicSharedMemorySize, GSMEM);

    convert4_kernel<<<2048, 256>>>((const float4*)qkv_w, wq, (size_t)NLL*3*DD*DD/4); // 0
    embed_kernel<<<MR, 256>>>(x, emb_w, h_);                                         // 1

    for (int l = 0; l < NLL; l++) {
        const size_t oq = (size_t)l * 3 * DD * DD, oo = (size_t)l * DD * DD;
        const size_t of = (size_t)l * FFF * DD;

        rmsnorm_split<<<MR, 256>>>(h_, n1_w + (size_t)l * DD, nh, nl);               // 2

        gemm_mma<<<dim3(MR / 128, 3 * DD / 128), 256, GSMEM>>>(                      // 3
            nh, nl, wq + oq, qkv_b + (size_t)l * 3 * DD,
            nullptr, qkv_, nullptr, nullptr, 3 * DD, DD, 0, 2);

        attn_mma<<<dim3(TT / 64, NHH, BB), 128>>>(qkv_, ath, atl);                   // 4

        if (l == 0) convert4_kernel<<<2048, 256>>>((const float4*)o_w, wo, (size_t)NLL*DD*DD/4);

        gemm_mma<<<dim3(MR / 128, DD / 128), 256, GSMEM>>>(
            ath, atl, wo + oo, o_b + (size_t)l * DD,
            h_, h_, nullptr, nullptr, DD, DD, 1, 2);

        rmsnorm_split<<<MR, 256>>>(h_, n2_w + (size_t)l * DD, nh, nl);

        if (l == 0) {
            convert4_kernel<<<2048, 256>>>((const float4*)gw, wg, (size_t)NLL*FFF*DD/4);
            convert4_kernel<<<2048, 256>>>((const float4*)uw, wu, (size_t)NLL*FFF*DD/4);
        }

        gemm_mma<<<dim3(MR / 128, FFF / 128), 256, GSMEM>>>(
            nh, nl, wg + of, gb + (size_t)l * FFF,
            nullptr, ffs_, nullptr, nullptr, FFF, DD, 2, 2);

        gemm_mma<<<dim3(MR / 128, FFF / 128), 256, GSMEM>>>(
            nh, nl, wu + of, ub + (size_t)l * FFF,
            ffs_, nullptr, ffh, ffl, FFF, DD, 3, 2);

        if (l == 0) convert4_kernel<<<2048, 256>>>((const float4*)dnw, wd, (size_t)NLL*DD*FFF/4);

        gemm_mma<<<dim3(MR / 128, DD / 128), 256, GSMEM>>>(
            ffh, ffl, wd + of, dnb + (size_t)l * DD,
            h_, h_, nullptr, nullptr, DD, FFF, 1, 2);

        if (l == 0) convert4_kernel<<<2048, 256>>>((const float4*)head_w, wh, (size_t)VV*DD/4);
    }

    rmsnorm_split<<<MR, 256>>>(h_, norm_w, nh, nl);

    // LM head: single-pass A (final-layer output; A-rounding error does not propagate)
    gemm_mma<<<dim3(MR / 128, VV / 128), 256, GSMEM>>>(
        nh, nl, wh, nullptr,
        nullptr, out, nullptr, nullptr, VV, DD, 0, 1);
}